// round 10
// baseline (speedup 1.0000x reference)
#include <cuda_runtime.h>
#include <cstdint>

#define LDIM 256
#define CDIM 128
#define NH 4
#define HDIM 32
#define NROWS (LDIM*LDIM)        // 65536
#define QKVN 384
#define SQRT32 5.656854249492380f
#define APAD 140
#define BPAD 136

// ---------------- scratch ----------------
__device__ float g_qkv  [(size_t)NROWS * QKVN];
__device__ float g_gate [(size_t)NROWS * CDIM];
__device__ float g_biasT[(size_t)NH * NROWS];
__device__ float g_attn [(size_t)NROWS * CDIM];

// ---------------- helpers ----------------
__device__ __forceinline__ unsigned f2tf(float f) {
    unsigned r;
    asm("cvt.rna.tf32.f32 %0, %1;" : "=r"(r) : "f"(f));
    return r;
}
__device__ __forceinline__ float f2tff(float f) { return __uint_as_float(f2tf(f)); }
__device__ __forceinline__ unsigned fu(float f) { return __float_as_uint(f); }

__device__ __forceinline__ void mma_tf32(float c[4], const unsigned a[4], const unsigned b[2]) {
    asm volatile(
        "mma.sync.aligned.m16n8k8.row.col.f32.tf32.tf32.f32 "
        "{%0,%1,%2,%3},{%4,%5,%6,%7},{%8,%9},{%0,%1,%2,%3};"
        : "+f"(c[0]), "+f"(c[1]), "+f"(c[2]), "+f"(c[3])
        : "r"(a[0]), "r"(a[1]), "r"(a[2]), "r"(a[3]), "r"(b[0]), "r"(b[1]));
}

// ============ kernel 1: fused LN + GEMM  zn @ [w_qkv | w_gate], all 4 slabs per block ============
// (unchanged from R9 — validated at 105.7us)
#define GEMM_QKV_SMEM_FLOATS (64*APAD + 128*BPAD + 128 + 128 + 512)
__global__ __launch_bounds__(256, 2) void gemm_qkv_gate(
    const float* __restrict__ z, const float* __restrict__ lng, const float* __restrict__ lnb,
    const float* __restrict__ wqkv, const float* __restrict__ wgate,
    const float* __restrict__ bgate, const float* __restrict__ wpair)
{
    extern __shared__ float sm[];
    float* As  = sm;                    // [64][APAD]
    float* Bs  = sm + 64*APAD;          // [128][BPAD] (k, n)
    float* gS  = Bs + 128*BPAD;         // 128
    float* bS  = gS + 128;              // 128
    float* wpS = bS + 128;              // 512

    int tid = threadIdx.x;
    int m0 = blockIdx.x * 64;

    #pragma unroll
    for (int it = 0; it < 8; it++) {
        int lin = tid + it*256;
        int r = lin >> 5, c4 = lin & 31;
        *(float4*)(As + r*APAD + c4*4) =
            *(const float4*)(z + (size_t)(m0 + r)*CDIM + c4*4);
    }
    #pragma unroll
    for (int it = 0; it < 16; it++) {
        int lin = tid + it*256;
        int k = lin >> 5, c4 = lin & 31;
        float4 w = *(const float4*)(wqkv + (size_t)k*QKVN + c4*4);
        w.x = f2tff(w.x * SQRT32); w.y = f2tff(w.y * SQRT32);
        w.z = f2tff(w.z * SQRT32); w.w = f2tff(w.w * SQRT32);
        *(float4*)(Bs + k*BPAD + c4*4) = w;
    }
    if (tid < 128) { gS[tid] = lng[tid]; bS[tid] = lnb[tid]; }
    wpS[tid] = wpair[tid];
    wpS[tid + 256] = wpair[tid + 256];
    __syncthreads();

    {
        int row = tid >> 2, quad = tid & 3;
        float* Ar = As + row*APAD + quad*4;
        float v[32];
        float s = 0.f, ss = 0.f;
        #pragma unroll
        for (int k = 0; k < 8; k++) {
            float4 t = *(float4*)(Ar + k*16);
            v[k*4] = t.x; v[k*4+1] = t.y; v[k*4+2] = t.z; v[k*4+3] = t.w;
            s  += t.x + t.y + t.z + t.w;
            ss += t.x*t.x + t.y*t.y + t.z*t.z + t.w*t.w;
        }
        s  += __shfl_xor_sync(0xffffffffu, s, 1);  s  += __shfl_xor_sync(0xffffffffu, s, 2);
        ss += __shfl_xor_sync(0xffffffffu, ss, 1); ss += __shfl_xor_sync(0xffffffffu, ss, 2);
        float mu  = s * (1.0f / CDIM);
        float var = ss * (1.0f / CDIM) - mu * mu;
        float rstd = rsqrtf(var + 1e-5f);

        float bh0 = 0.f, bh1 = 0.f, bh2 = 0.f, bh3 = 0.f;
        #pragma unroll
        for (int k = 0; k < 8; k++) {
            float4 o;
            float* ov = &o.x;
            #pragma unroll
            for (int j = 0; j < 4; j++) {
                int c = quad*4 + k*16 + j;
                float zn = (v[k*4+j] - mu) * rstd * gS[c] + bS[c];
                bh0 += zn * wpS[c*4];   bh1 += zn * wpS[c*4+1];
                bh2 += zn * wpS[c*4+2]; bh3 += zn * wpS[c*4+3];
                ov[j] = f2tff(zn);
            }
            *(float4*)(Ar + k*16) = o;
        }
        bh0 += __shfl_xor_sync(0xffffffffu, bh0, 1); bh0 += __shfl_xor_sync(0xffffffffu, bh0, 2);
        bh1 += __shfl_xor_sync(0xffffffffu, bh1, 1); bh1 += __shfl_xor_sync(0xffffffffu, bh1, 2);
        bh2 += __shfl_xor_sync(0xffffffffu, bh2, 1); bh2 += __shfl_xor_sync(0xffffffffu, bh2, 2);
        bh3 += __shfl_xor_sync(0xffffffffu, bh3, 1); bh3 += __shfl_xor_sync(0xffffffffu, bh3, 2);
        if (quad == 0) {
            g_biasT[(size_t)0*NROWS + m0 + row] = bh0;
            g_biasT[(size_t)1*NROWS + m0 + row] = bh1;
            g_biasT[(size_t)2*NROWS + m0 + row] = bh2;
            g_biasT[(size_t)3*NROWS + m0 + row] = bh3;
        }
    }
    __syncthreads();

    int warp = tid >> 5, lane = tid & 31;
    int lr = lane >> 2, lc = lane & 3;
    int wm = warp & 1, wn = warp >> 1;

    #pragma unroll
    for (int nt = 0; nt < 4; nt++) {
        float acc[2][4][4];
        #pragma unroll
        for (int mi = 0; mi < 2; mi++)
            #pragma unroll
            for (int ni = 0; ni < 4; ni++)
                acc[mi][ni][0] = acc[mi][ni][1] = acc[mi][ni][2] = acc[mi][ni][3] = 0.f;

        #pragma unroll
        for (int ks = 0; ks < 16; ks++) {
            int k0 = ks * 8;
            unsigned a[2][4], bf[4][2];
            #pragma unroll
            for (int mi = 0; mi < 2; mi++) {
                int r = wm*32 + mi*16 + lr;
                a[mi][0] = fu(As[r*APAD + k0 + lc]);
                a[mi][1] = fu(As[(r+8)*APAD + k0 + lc]);
                a[mi][2] = fu(As[r*APAD + k0 + 4 + lc]);
                a[mi][3] = fu(As[(r+8)*APAD + k0 + 4 + lc]);
            }
            #pragma unroll
            for (int ni = 0; ni < 4; ni++) {
                int n = wn*32 + ni*8 + lr;
                bf[ni][0] = fu(Bs[(k0 + lc)*BPAD + n]);
                bf[ni][1] = fu(Bs[(k0 + 4 + lc)*BPAD + n]);
            }
            #pragma unroll
            for (int mi = 0; mi < 2; mi++)
                #pragma unroll
                for (int ni = 0; ni < 4; ni++)
                    mma_tf32(acc[mi][ni], a[mi], bf[ni]);
        }

        #pragma unroll
        for (int mi = 0; mi < 2; mi++) {
            #pragma unroll
            for (int ni = 0; ni < 4; ni++) {
                int gr = m0 + wm*32 + mi*16 + lr;
                int cn = wn*32 + ni*8 + lc*2;
                if (nt < 3) {
                    int gc = nt*128 + cn;
                    *(float2*)(g_qkv + (size_t)gr * QKVN + gc) =
                        make_float2(f2tff(acc[mi][ni][0]), f2tff(acc[mi][ni][1]));
                    *(float2*)(g_qkv + (size_t)(gr+8) * QKVN + gc) =
                        make_float2(f2tff(acc[mi][ni][2]), f2tff(acc[mi][ni][3]));
                } else {
                    float b0 = bgate[cn], b1 = bgate[cn+1];
                    *(float2*)(g_gate + (size_t)gr * CDIM + cn) =
                        make_float2(1.f/(1.f + __expf(-(acc[mi][ni][0] + b0))),
                                    1.f/(1.f + __expf(-(acc[mi][ni][1] + b1))));
                    *(float2*)(g_gate + (size_t)(gr+8) * CDIM + cn) =
                        make_float2(1.f/(1.f + __expf(-(acc[mi][ni][2] + b0))),
                                    1.f/(1.f + __expf(-(acc[mi][ni][3] + b1))));
                }
            }
        }

        if (nt < 3) {
            __syncthreads();
            #pragma unroll
            for (int it = 0; it < 16; it++) {
                int lin = tid + it*256;
                int k = lin >> 5, c4 = lin & 31;
                float4 w;
                if (nt + 1 < 3) w = *(const float4*)(wqkv + (size_t)k*QKVN + (nt+1)*128 + c4*4);
                else            w = *(const float4*)(wgate + (size_t)k*CDIM + c4*4);
                w.x = f2tff(w.x); w.y = f2tff(w.y); w.z = f2tff(w.z); w.w = f2tff(w.w);
                *(float4*)(Bs + k*BPAD + c4*4) = w;
            }
            __syncthreads();
        }
    }
}

// ============ kernel 2: attention per (h, r) — warp owns full rows (16 x 256j) ============
// 256 threads, 8 warps, i-chunk 128, 2 chunks. No cross-warp reductions, no obuf.
#define ATTN_SMEM_FLOATS (256*36*2 + 128*36 + 256)
__global__ __launch_bounds__(256, 1) void attn_kernel(const int* __restrict__ src_mask)
{
    extern __shared__ float sm[];
    float* Ks  = sm;                 // [256][36]
    float* Vs  = Ks + 256*36;        // [256][36]
    float* Qs  = Vs + 256*36;        // [128][36]
    float* msk = Qs + 128*36;        // [256]

    int h = blockIdx.x, r = blockIdx.y;
    int tid = threadIdx.x;
    const float* base = g_qkv + (size_t)r * LDIM * QKVN;

    #pragma unroll
    for (int p = 0; p < 8; p++) {
        int lin = tid + p*256;
        int j = lin >> 3, d4 = lin & 7;
        *(float4*)(Ks + j*36 + d4*4) =
            *(const float4*)(base + (size_t)j*QKVN + 128 + h*HDIM + d4*4);
        *(float4*)(Vs + j*36 + d4*4) =
            *(const float4*)(base + (size_t)j*QKVN + 256 + h*HDIM + d4*4);
    }
    msk[tid] = (src_mask[tid] == 0) ? -1.f : 1.f;

    int warp = tid >> 5, lane = tid & 31;
    int lr = lane >> 2, lc = lane & 3;
    int arow = warp*16 + lr;          // warp owns rows [warp*16, warp*16+16)
    const float* biasH = g_biasT + (size_t)h * NROWS;

    int s0l = (lane & ~3) | (lc >> 1);
    int s1l = s0l + 2;
    int sel = lc & 1;

    for (int ic = 0; ic < 2; ic++) {
        int i0 = ic * 128;
        __syncthreads();             // K/V (iter0) or prev-chunk Qs reads complete
        #pragma unroll
        for (int p = 0; p < 4; p++) {
            int lin = tid + p*256;
            int row = lin >> 3, d4 = lin & 7;
            *(float4*)(Qs + row*36 + d4*4) =
                *(const float4*)(base + (size_t)(i0 + row)*QKVN + h*HDIM + d4*4);
        }
        __syncthreads();

        // ---- QK^T: 32 ni tiles of 8 j-cols, full 256 j per warp ----
        float acc[32][4];
        #pragma unroll
        for (int ni = 0; ni < 32; ni++)
            acc[ni][0] = acc[ni][1] = acc[ni][2] = acc[ni][3] = 0.f;

        #pragma unroll
        for (int ks = 0; ks < 4; ks++) {
            int k0 = ks * 8;
            unsigned a[4] = { fu(Qs[arow*36 + k0 + lc]),     fu(Qs[(arow+8)*36 + k0 + lc]),
                              fu(Qs[arow*36 + k0 + 4 + lc]), fu(Qs[(arow+8)*36 + k0 + 4 + lc]) };
            #pragma unroll
            for (int ni = 0; ni < 32; ni++) {
                int j = ni*8 + lr;
                unsigned b[2] = { fu(Ks[j*36 + k0 + lc]), fu(Ks[j*36 + k0 + 4 + lc]) };
                mma_tf32(acc[ni], a, b);
            }
        }

        // ---- bias + mask + row max (in-warp only) ----
        float mi0 = msk[i0 + arow], mi1 = msk[i0 + arow + 8];
        const float* bp0 = biasH + (size_t)(i0 + arow) * LDIM;
        const float* bp1 = bp0 + 8 * LDIM;
        float mx0 = -1e30f, mx1 = -1e30f;
        #pragma unroll
        for (int ni = 0; ni < 32; ni++) {
            int j = ni*8 + lc*2;
            float2 b0 = *(const float2*)(bp0 + j);
            float2 b1 = *(const float2*)(bp1 + j);
            float mj0 = msk[j], mj1 = msk[j+1];
            float v0 = acc[ni][0] + b0.x;
            float v1 = acc[ni][1] + b0.y;
            float v2 = acc[ni][2] + b1.x;
            float v3 = acc[ni][3] + b1.y;
            if (mi0*mj0 < 0.f) v0 = -1e-9f;
            if (mi0*mj1 < 0.f) v1 = -1e-9f;
            if (mi1*mj0 < 0.f) v2 = -1e-9f;
            if (mi1*mj1 < 0.f) v3 = -1e-9f;
            acc[ni][0] = v0; acc[ni][1] = v1; acc[ni][2] = v2; acc[ni][3] = v3;
            mx0 = fmaxf(mx0, fmaxf(v0, v1));
            mx1 = fmaxf(mx1, fmaxf(v2, v3));
        }
        mx0 = fmaxf(mx0, __shfl_xor_sync(0xffffffffu, mx0, 1));
        mx0 = fmaxf(mx0, __shfl_xor_sync(0xffffffffu, mx0, 2));
        mx1 = fmaxf(mx1, __shfl_xor_sync(0xffffffffu, mx1, 1));
        mx1 = fmaxf(mx1, __shfl_xor_sync(0xffffffffu, mx1, 2));

        // ---- exp + row sum (in-warp only) ----
        float sm0 = 0.f, sm1 = 0.f;
        #pragma unroll
        for (int ni = 0; ni < 32; ni++) {
            float e0 = __expf(acc[ni][0] - mx0), e1 = __expf(acc[ni][1] - mx0);
            float e2 = __expf(acc[ni][2] - mx1), e3 = __expf(acc[ni][3] - mx1);
            acc[ni][0] = e0; acc[ni][1] = e1; acc[ni][2] = e2; acc[ni][3] = e3;
            sm0 += e0 + e1; sm1 += e2 + e3;
        }
        sm0 += __shfl_xor_sync(0xffffffffu, sm0, 1);
        sm0 += __shfl_xor_sync(0xffffffffu, sm0, 2);
        sm1 += __shfl_xor_sync(0xffffffffu, sm1, 1);
        sm1 += __shfl_xor_sync(0xffffffffu, sm1, 2);
        float inv0 = 1.f / sm0;
        float inv1 = 1.f / sm1;
        #pragma unroll
        for (int ni = 0; ni < 32; ni++) {
            acc[ni][0] = f2tff(acc[ni][0] * inv0);
            acc[ni][1] = f2tff(acc[ni][1] * inv0);
            acc[ni][2] = f2tff(acc[ni][2] * inv1);
            acc[ni][3] = f2tff(acc[ni][3] * inv1);
        }

        // ---- P @ V over full 256 j ----
        float oc[4][4];
        #pragma unroll
        for (int dt = 0; dt < 4; dt++)
            oc[dt][0] = oc[dt][1] = oc[dt][2] = oc[dt][3] = 0.f;

        #pragma unroll
        for (int ni = 0; ni < 32; ni++) {
            float t00 = __shfl_sync(0xffffffffu, acc[ni][0], s0l);
            float t01 = __shfl_sync(0xffffffffu, acc[ni][1], s0l);
            float t10 = __shfl_sync(0xffffffffu, acc[ni][2], s0l);
            float t11 = __shfl_sync(0xffffffffu, acc[ni][3], s0l);
            float u00 = __shfl_sync(0xffffffffu, acc[ni][0], s1l);
            float u01 = __shfl_sync(0xffffffffu, acc[ni][1], s1l);
            float u10 = __shfl_sync(0xffffffffu, acc[ni][2], s1l);
            float u11 = __shfl_sync(0xffffffffu, acc[ni][3], s1l);
            unsigned a[4];
            a[0] = fu(sel ? t01 : t00);
            a[1] = fu(sel ? t11 : t10);
            a[2] = fu(sel ? u01 : u00);
            a[3] = fu(sel ? u11 : u10);
            int jb = ni*8;
            #pragma unroll
            for (int dt = 0; dt < 4; dt++) {
                unsigned b[2] = { fu(Vs[(jb + lc)*36 + dt*8 + lr]),
                                  fu(Vs[(jb + 4 + lc)*36 + dt*8 + lr]) };
                mma_tf32(oc[dt], a, b);
            }
        }

        // ---- direct store (complete rows — no combine) ----
        size_t ro0 = ((size_t)r*LDIM + i0 + arow) * CDIM + h*HDIM;
        size_t ro1 = ro0 + 8*CDIM;
        #pragma unroll
        for (int dt = 0; dt < 4; dt++) {
            *(float2*)(g_attn + ro0 + dt*8 + lc*2) = make_float2(oc[dt][0], oc[dt][1]);
            *(float2*)(g_attn + ro1 + dt*8 + lc*2) = make_float2(oc[dt][2], oc[dt][3]);
        }
    }
}

// ============ kernel 3: (gate * attn) @ w_out + b_out (unchanged) ============
#define GEMM_OUT_SMEM_FLOATS (64*APAD + 128*BPAD)
__global__ __launch_bounds__(256, 2) void gemm_out_kernel(
    const float* __restrict__ wout, const float* __restrict__ bout,
    float* __restrict__ out)
{
    extern __shared__ float sm[];
    float* As = sm;               // [64][APAD]
    float* Bs = sm + 64*APAD;     // [128][BPAD]
    int tid = threadIdx.x;
    int m0 = blockIdx.x * 64;

    #pragma unroll
    for (int it = 0; it < 8; it++) {
        int lin = tid + it*256;
        int r = lin >> 5, c4 = lin & 31;
        float4 gte = *(const float4*)(g_gate + (size_t)(m0 + r)*CDIM + c4*4);
        float4 att = *(const float4*)(g_attn + (size_t)(m0 + r)*CDIM + c4*4);
        float4 a;
        a.x = f2tff(gte.x * att.x); a.y = f2tff(gte.y * att.y);
        a.z = f2tff(gte.z * att.z); a.w = f2tff(gte.w * att.w);
        *(float4*)(As + r*APAD + c4*4) = a;
    }
    #pragma unroll
    for (int it = 0; it < 16; it++) {
        int lin = tid + it*256;
        int k = lin >> 5, c4 = lin & 31;
        float4 w = *(const float4*)(wout + (size_t)k*CDIM + c4*4);
        w.x = f2tff(w.x); w.y = f2tff(w.y); w.z = f2tff(w.z); w.w = f2tff(w.w);
        *(float4*)(Bs + k*BPAD + c4*4) = w;
    }
    __syncthreads();

    int warp = tid >> 5, lane = tid & 31;
    int lr = lane >> 2, lc = lane & 3;
    int wm = warp & 1, wn = warp >> 1;

    float acc[2][4][4];
    #pragma unroll
    for (int mi = 0; mi < 2; mi++)
        #pragma unroll
        for (int ni = 0; ni < 4; ni++)
            acc[mi][ni][0] = acc[mi][ni][1] = acc[mi][ni][2] = acc[mi][ni][3] = 0.f;

    #pragma unroll
    for (int ks = 0; ks < 16; ks++) {
        int k0 = ks * 8;
        unsigned a[2][4], bf[4][2];
        #pragma unroll
        for (int mi = 0; mi < 2; mi++) {
            int r = wm*32 + mi*16 + lr;
            a[mi][0] = fu(As[r*APAD + k0 + lc]);
            a[mi][1] = fu(As[(r+8)*APAD + k0 + lc]);
            a[mi][2] = fu(As[r*APAD + k0 + 4 + lc]);
            a[mi][3] = fu(As[(r+8)*APAD + k0 + 4 + lc]);
        }
        #pragma unroll
        for (int ni = 0; ni < 4; ni++) {
            int n = wn*32 + ni*8 + lr;
            bf[ni][0] = fu(Bs[(k0 + lc)*BPAD + n]);
            bf[ni][1] = fu(Bs[(k0 + 4 + lc)*BPAD + n]);
        }
        #pragma unroll
        for (int mi = 0; mi < 2; mi++)
            #pragma unroll
            for (int ni = 0; ni < 4; ni++)
                mma_tf32(acc[mi][ni], a[mi], bf[ni]);
    }

    #pragma unroll
    for (int mi = 0; mi < 2; mi++) {
        #pragma unroll
        for (int ni = 0; ni < 4; ni++) {
            int gr = m0 + wm*32 + mi*16 + lr;
            int cn = wn*32 + ni*8 + lc*2;
            float b0 = bout[cn], b1 = bout[cn+1];
            *(float2*)(out + (size_t)gr * CDIM + cn) =
                make_float2(acc[mi][ni][0] + b0, acc[mi][ni][1] + b1);
            *(float2*)(out + (size_t)(gr+8) * CDIM + cn) =
                make_float2(acc[mi][ni][2] + b0, acc[mi][ni][3] + b1);
        }
    }
}

// ---------------- launch ----------------
extern "C" void kernel_launch(void* const* d_in, const int* in_sizes, int n_in,
                              void* d_out, int out_size)
{
    (void)in_sizes; (void)n_in; (void)out_size;
    const float* z        = (const float*)d_in[0];
    const int*   src_mask = (const int*)  d_in[1];
    const float* ln_g     = (const float*)d_in[2];
    const float* ln_b     = (const float*)d_in[3];
    const float* w_qkv    = (const float*)d_in[4];
    const float* w_pair   = (const float*)d_in[5];
    const float* w_gate   = (const float*)d_in[6];
    const float* b_gate   = (const float*)d_in[7];
    const float* w_out    = (const float*)d_in[8];
    const float* b_out    = (const float*)d_in[9];
    float* out = (float*)d_out;

    const int qkv_smem  = GEMM_QKV_SMEM_FLOATS * 4;
    const int out_smem  = GEMM_OUT_SMEM_FLOATS * 4;
    const int attn_smem = ATTN_SMEM_FLOATS * 4;    // 93184
    cudaFuncSetAttribute(gemm_qkv_gate,   cudaFuncAttributeMaxDynamicSharedMemorySize, qkv_smem);
    cudaFuncSetAttribute(attn_kernel,     cudaFuncAttributeMaxDynamicSharedMemorySize, attn_smem);
    cudaFuncSetAttribute(gemm_out_kernel, cudaFuncAttributeMaxDynamicSharedMemorySize, out_smem);

    gemm_qkv_gate<<<NROWS/64, 256, qkv_smem>>>(z, ln_g, ln_b, w_qkv, w_gate, b_gate, w_pair);
    attn_kernel<<<dim3(NH, LDIM), 256, attn_smem>>>(src_mask);
    gemm_out_kernel<<<NROWS/64, 256, out_smem>>>(w_out, b_out, out);
}

// round 11
// speedup vs baseline: 1.0232x; 1.0232x over previous
#include <cuda_runtime.h>
#include <cstdint>

#define LDIM 256
#define CDIM 128
#define NH 4
#define HDIM 32
#define NROWS (LDIM*LDIM)        // 65536
#define QKVN 384
#define SQRT32 5.656854249492380f
#define APAD 140
#define BPAD 136

// ---------------- scratch ----------------
__device__ float g_qkv  [(size_t)NROWS * QKVN];
__device__ float g_gate [(size_t)NROWS * CDIM];
__device__ float g_biasT[(size_t)NH * NROWS];
__device__ float g_attn [(size_t)NROWS * CDIM];   // partial (wn==0 half)
__device__ float g_attn2[(size_t)NROWS * CDIM];   // partial (wn==1 half)

// ---------------- helpers ----------------
__device__ __forceinline__ unsigned f2tf(float f) {
    unsigned r;
    asm("cvt.rna.tf32.f32 %0, %1;" : "=r"(r) : "f"(f));
    return r;
}
__device__ __forceinline__ float f2tff(float f) { return __uint_as_float(f2tf(f)); }
__device__ __forceinline__ unsigned fu(float f) { return __float_as_uint(f); }

__device__ __forceinline__ void mma_tf32(float c[4], const unsigned a[4], const unsigned b[2]) {
    asm volatile(
        "mma.sync.aligned.m16n8k8.row.col.f32.tf32.tf32.f32 "
        "{%0,%1,%2,%3},{%4,%5,%6,%7},{%8,%9},{%0,%1,%2,%3};"
        : "+f"(c[0]), "+f"(c[1]), "+f"(c[2]), "+f"(c[3])
        : "r"(a[0]), "r"(a[1]), "r"(a[2]), "r"(a[3]), "r"(b[0]), "r"(b[1]));
}

// ============ kernel 1: fused LN + GEMM  zn @ [w_qkv | w_gate], all 4 slabs per block ============
// (unchanged from R9 — validated at 105.7us)
#define GEMM_QKV_SMEM_FLOATS (64*APAD + 128*BPAD + 128 + 128 + 512)
__global__ __launch_bounds__(256, 2) void gemm_qkv_gate(
    const float* __restrict__ z, const float* __restrict__ lng, const float* __restrict__ lnb,
    const float* __restrict__ wqkv, const float* __restrict__ wgate,
    const float* __restrict__ bgate, const float* __restrict__ wpair)
{
    extern __shared__ float sm[];
    float* As  = sm;                    // [64][APAD]
    float* Bs  = sm + 64*APAD;          // [128][BPAD] (k, n)
    float* gS  = Bs + 128*BPAD;         // 128
    float* bS  = gS + 128;              // 128
    float* wpS = bS + 128;              // 512

    int tid = threadIdx.x;
    int m0 = blockIdx.x * 64;

    #pragma unroll
    for (int it = 0; it < 8; it++) {
        int lin = tid + it*256;
        int r = lin >> 5, c4 = lin & 31;
        *(float4*)(As + r*APAD + c4*4) =
            *(const float4*)(z + (size_t)(m0 + r)*CDIM + c4*4);
    }
    #pragma unroll
    for (int it = 0; it < 16; it++) {
        int lin = tid + it*256;
        int k = lin >> 5, c4 = lin & 31;
        float4 w = *(const float4*)(wqkv + (size_t)k*QKVN + c4*4);
        w.x = f2tff(w.x * SQRT32); w.y = f2tff(w.y * SQRT32);
        w.z = f2tff(w.z * SQRT32); w.w = f2tff(w.w * SQRT32);
        *(float4*)(Bs + k*BPAD + c4*4) = w;
    }
    if (tid < 128) { gS[tid] = lng[tid]; bS[tid] = lnb[tid]; }
    wpS[tid] = wpair[tid];
    wpS[tid + 256] = wpair[tid + 256];
    __syncthreads();

    {
        int row = tid >> 2, quad = tid & 3;
        float* Ar = As + row*APAD + quad*4;
        float v[32];
        float s = 0.f, ss = 0.f;
        #pragma unroll
        for (int k = 0; k < 8; k++) {
            float4 t = *(float4*)(Ar + k*16);
            v[k*4] = t.x; v[k*4+1] = t.y; v[k*4+2] = t.z; v[k*4+3] = t.w;
            s  += t.x + t.y + t.z + t.w;
            ss += t.x*t.x + t.y*t.y + t.z*t.z + t.w*t.w;
        }
        s  += __shfl_xor_sync(0xffffffffu, s, 1);  s  += __shfl_xor_sync(0xffffffffu, s, 2);
        ss += __shfl_xor_sync(0xffffffffu, ss, 1); ss += __shfl_xor_sync(0xffffffffu, ss, 2);
        float mu  = s * (1.0f / CDIM);
        float var = ss * (1.0f / CDIM) - mu * mu;
        float rstd = rsqrtf(var + 1e-5f);

        float bh0 = 0.f, bh1 = 0.f, bh2 = 0.f, bh3 = 0.f;
        #pragma unroll
        for (int k = 0; k < 8; k++) {
            float4 o;
            float* ov = &o.x;
            #pragma unroll
            for (int j = 0; j < 4; j++) {
                int c = quad*4 + k*16 + j;
                float zn = (v[k*4+j] - mu) * rstd * gS[c] + bS[c];
                bh0 += zn * wpS[c*4];   bh1 += zn * wpS[c*4+1];
                bh2 += zn * wpS[c*4+2]; bh3 += zn * wpS[c*4+3];
                ov[j] = f2tff(zn);
            }
            *(float4*)(Ar + k*16) = o;
        }
        bh0 += __shfl_xor_sync(0xffffffffu, bh0, 1); bh0 += __shfl_xor_sync(0xffffffffu, bh0, 2);
        bh1 += __shfl_xor_sync(0xffffffffu, bh1, 1); bh1 += __shfl_xor_sync(0xffffffffu, bh1, 2);
        bh2 += __shfl_xor_sync(0xffffffffu, bh2, 1); bh2 += __shfl_xor_sync(0xffffffffu, bh2, 2);
        bh3 += __shfl_xor_sync(0xffffffffu, bh3, 1); bh3 += __shfl_xor_sync(0xffffffffu, bh3, 2);
        if (quad == 0) {
            g_biasT[(size_t)0*NROWS + m0 + row] = bh0;
            g_biasT[(size_t)1*NROWS + m0 + row] = bh1;
            g_biasT[(size_t)2*NROWS + m0 + row] = bh2;
            g_biasT[(size_t)3*NROWS + m0 + row] = bh3;
        }
    }
    __syncthreads();

    int warp = tid >> 5, lane = tid & 31;
    int lr = lane >> 2, lc = lane & 3;
    int wm = warp & 1, wn = warp >> 1;

    #pragma unroll
    for (int nt = 0; nt < 4; nt++) {
        float acc[2][4][4];
        #pragma unroll
        for (int mi = 0; mi < 2; mi++)
            #pragma unroll
            for (int ni = 0; ni < 4; ni++)
                acc[mi][ni][0] = acc[mi][ni][1] = acc[mi][ni][2] = acc[mi][ni][3] = 0.f;

        #pragma unroll
        for (int ks = 0; ks < 16; ks++) {
            int k0 = ks * 8;
            unsigned a[2][4], bf[4][2];
            #pragma unroll
            for (int mi = 0; mi < 2; mi++) {
                int r = wm*32 + mi*16 + lr;
                a[mi][0] = fu(As[r*APAD + k0 + lc]);
                a[mi][1] = fu(As[(r+8)*APAD + k0 + lc]);
                a[mi][2] = fu(As[r*APAD + k0 + 4 + lc]);
                a[mi][3] = fu(As[(r+8)*APAD + k0 + 4 + lc]);
            }
            #pragma unroll
            for (int ni = 0; ni < 4; ni++) {
                int n = wn*32 + ni*8 + lr;
                bf[ni][0] = fu(Bs[(k0 + lc)*BPAD + n]);
                bf[ni][1] = fu(Bs[(k0 + 4 + lc)*BPAD + n]);
            }
            #pragma unroll
            for (int mi = 0; mi < 2; mi++)
                #pragma unroll
                for (int ni = 0; ni < 4; ni++)
                    mma_tf32(acc[mi][ni], a[mi], bf[ni]);
        }

        #pragma unroll
        for (int mi = 0; mi < 2; mi++) {
            #pragma unroll
            for (int ni = 0; ni < 4; ni++) {
                int gr = m0 + wm*32 + mi*16 + lr;
                int cn = wn*32 + ni*8 + lc*2;
                if (nt < 3) {
                    int gc = nt*128 + cn;
                    *(float2*)(g_qkv + (size_t)gr * QKVN + gc) =
                        make_float2(f2tff(acc[mi][ni][0]), f2tff(acc[mi][ni][1]));
                    *(float2*)(g_qkv + (size_t)(gr+8) * QKVN + gc) =
                        make_float2(f2tff(acc[mi][ni][2]), f2tff(acc[mi][ni][3]));
                } else {
                    float b0 = bgate[cn], b1 = bgate[cn+1];
                    *(float2*)(g_gate + (size_t)gr * CDIM + cn) =
                        make_float2(1.f/(1.f + __expf(-(acc[mi][ni][0] + b0))),
                                    1.f/(1.f + __expf(-(acc[mi][ni][1] + b1))));
                    *(float2*)(g_gate + (size_t)(gr+8) * CDIM + cn) =
                        make_float2(1.f/(1.f + __expf(-(acc[mi][ni][2] + b0))),
                                    1.f/(1.f + __expf(-(acc[mi][ni][3] + b1))));
                }
            }
        }

        if (nt < 3) {
            __syncthreads();
            #pragma unroll
            for (int it = 0; it < 16; it++) {
                int lin = tid + it*256;
                int k = lin >> 5, c4 = lin & 31;
                float4 w;
                if (nt + 1 < 3) w = *(const float4*)(wqkv + (size_t)k*QKVN + (nt+1)*128 + c4*4);
                else            w = *(const float4*)(wgate + (size_t)k*CDIM + c4*4);
                w.x = f2tff(w.x); w.y = f2tff(w.y); w.z = f2tff(w.z); w.w = f2tff(w.w);
                *(float4*)(Bs + k*BPAD + c4*4) = w;
            }
            __syncthreads();
        }
    }
}

// ============ kernel 2: attention per (h, r) — j-split, merged reduction, partial outputs ============
// 256 threads, 8 warps: wm = warp>>1 (16-row strip of 64-chunk), wn = warp&1 (j half of 128).
#define ATTN_SMEM_FLOATS (256*36*2 + 64*36 + 128 + 128 + 256)
__global__ __launch_bounds__(256, 2) void attn_kernel(const int* __restrict__ src_mask)
{
    extern __shared__ float sm[];
    float* Ks    = sm;                 // [256][36]
    float* Vs    = Ks + 256*36;        // [256][36]
    float* Qs    = Vs + 256*36;        // [64][36]
    float* redmx = Qs + 64*36;         // [2][64]
    float* redsm = redmx + 128;        // [2][64]
    float* msk   = redsm + 128;        // [256]

    int h = blockIdx.x, r = blockIdx.y;
    int tid = threadIdx.x;
    const float* base = g_qkv + (size_t)r * LDIM * QKVN;

    #pragma unroll
    for (int p = 0; p < 8; p++) {
        int lin = tid + p*256;
        int j = lin >> 3, d4 = lin & 7;
        *(float4*)(Ks + j*36 + d4*4) =
            *(const float4*)(base + (size_t)j*QKVN + 128 + h*HDIM + d4*4);
        *(float4*)(Vs + j*36 + d4*4) =
            *(const float4*)(base + (size_t)j*QKVN + 256 + h*HDIM + d4*4);
    }
    msk[tid] = (src_mask[tid] == 0) ? -1.f : 1.f;

    int warp = tid >> 5, lane = tid & 31;
    int lr = lane >> 2, lc = lane & 3;
    int wm = warp >> 1, wn = warp & 1;
    int arow = wm*16 + lr;
    const float* biasH = g_biasT + (size_t)h * NROWS;
    float* outP = wn ? g_attn2 : g_attn;

    int s0l = (lane & ~3) | (lc >> 1);
    int s1l = s0l + 2;
    int sel = lc & 1;

    for (int ic = 0; ic < 4; ic++) {
        int i0 = ic * 64;
        __syncthreads();   // K/V ready (ic=0); prior chunk's Qs reads complete (ic>0)
        #pragma unroll
        for (int p = 0; p < 2; p++) {
            int lin = tid + p*256;
            int row = lin >> 3, d4 = lin & 7;
            *(float4*)(Qs + row*36 + d4*4) =
                *(const float4*)(base + (size_t)(i0 + row)*QKVN + h*HDIM + d4*4);
        }
        __syncthreads();

        // ---- QK^T over this warp's 128 j-cols ----
        float acc[16][4];
        #pragma unroll
        for (int ni = 0; ni < 16; ni++)
            acc[ni][0] = acc[ni][1] = acc[ni][2] = acc[ni][3] = 0.f;

        #pragma unroll
        for (int ks = 0; ks < 4; ks++) {
            int k0 = ks * 8;
            unsigned a[4] = { fu(Qs[arow*36 + k0 + lc]),     fu(Qs[(arow+8)*36 + k0 + lc]),
                              fu(Qs[arow*36 + k0 + 4 + lc]), fu(Qs[(arow+8)*36 + k0 + 4 + lc]) };
            #pragma unroll
            for (int ni = 0; ni < 16; ni++) {
                int j = wn*128 + ni*8 + lr;
                unsigned b[2] = { fu(Ks[j*36 + k0 + lc]), fu(Ks[j*36 + k0 + 4 + lc]) };
                mma_tf32(acc[ni], a, b);
            }
        }

        // ---- bias + mask + local max ----
        float mi0 = msk[i0 + arow], mi1 = msk[i0 + arow + 8];
        const float* bp0 = biasH + (size_t)(i0 + arow) * LDIM;
        const float* bp1 = bp0 + 8 * LDIM;
        float mx0 = -1e30f, mx1 = -1e30f;
        #pragma unroll
        for (int ni = 0; ni < 16; ni++) {
            int j = wn*128 + ni*8 + lc*2;
            float2 b0 = *(const float2*)(bp0 + j);
            float2 b1 = *(const float2*)(bp1 + j);
            float mj0 = msk[j], mj1 = msk[j+1];
            float v0 = acc[ni][0] + b0.x;
            float v1 = acc[ni][1] + b0.y;
            float v2 = acc[ni][2] + b1.x;
            float v3 = acc[ni][3] + b1.y;
            if (mi0*mj0 < 0.f) v0 = -1e-9f;
            if (mi0*mj1 < 0.f) v1 = -1e-9f;
            if (mi1*mj0 < 0.f) v2 = -1e-9f;
            if (mi1*mj1 < 0.f) v3 = -1e-9f;
            acc[ni][0] = v0; acc[ni][1] = v1; acc[ni][2] = v2; acc[ni][3] = v3;
            mx0 = fmaxf(mx0, fmaxf(v0, v1));
            mx1 = fmaxf(mx1, fmaxf(v2, v3));
        }
        mx0 = fmaxf(mx0, __shfl_xor_sync(0xffffffffu, mx0, 1));
        mx0 = fmaxf(mx0, __shfl_xor_sync(0xffffffffu, mx0, 2));
        mx1 = fmaxf(mx1, __shfl_xor_sync(0xffffffffu, mx1, 1));
        mx1 = fmaxf(mx1, __shfl_xor_sync(0xffffffffu, mx1, 2));

        // ---- exp with local max + local sum ----
        float sm0 = 0.f, sm1 = 0.f;
        #pragma unroll
        for (int ni = 0; ni < 16; ni++) {
            float e0 = __expf(acc[ni][0] - mx0), e1 = __expf(acc[ni][1] - mx0);
            float e2 = __expf(acc[ni][2] - mx1), e3 = __expf(acc[ni][3] - mx1);
            acc[ni][0] = e0; acc[ni][1] = e1; acc[ni][2] = e2; acc[ni][3] = e3;
            sm0 += e0 + e1; sm1 += e2 + e3;
        }
        sm0 += __shfl_xor_sync(0xffffffffu, sm0, 1);
        sm0 += __shfl_xor_sync(0xffffffffu, sm0, 2);
        sm1 += __shfl_xor_sync(0xffffffffu, sm1, 1);
        sm1 += __shfl_xor_sync(0xffffffffu, sm1, 2);

        // ---- single reduction round: publish (mx, sm) per half ----
        if (lc == 0) {
            redmx[wn*64 + arow] = mx0;     redmx[wn*64 + arow + 8] = mx1;
            redsm[wn*64 + arow] = sm0;     redsm[wn*64 + arow + 8] = sm1;
        }
        __syncthreads();
        // global softmax factors, reconstructed analytically
        float mA0 = redmx[arow],     mB0 = redmx[64 + arow];
        float mA1 = redmx[arow + 8], mB1 = redmx[64 + arow + 8];
        float gm0 = fmaxf(mA0, mB0), gm1 = fmaxf(mA1, mB1);
        float tot0 = redsm[arow]     * __expf(mA0 - gm0) + redsm[64 + arow]     * __expf(mB0 - gm0);
        float tot1 = redsm[arow + 8] * __expf(mA1 - gm1) + redsm[64 + arow + 8] * __expf(mB1 - gm1);
        float scale0 = __expf(mx0 - gm0) / tot0;
        float scale1 = __expf(mx1 - gm1) / tot1;

        #pragma unroll
        for (int ni = 0; ni < 16; ni++) {
            acc[ni][0] = f2tff(acc[ni][0] * scale0);
            acc[ni][1] = f2tff(acc[ni][1] * scale0);
            acc[ni][2] = f2tff(acc[ni][2] * scale1);
            acc[ni][3] = f2tff(acc[ni][3] * scale1);
        }

        // ---- P @ V over this warp's 128 j-cols ----
        float oc[4][4];
        #pragma unroll
        for (int dt = 0; dt < 4; dt++)
            oc[dt][0] = oc[dt][1] = oc[dt][2] = oc[dt][3] = 0.f;

        #pragma unroll
        for (int ni = 0; ni < 16; ni++) {
            float t00 = __shfl_sync(0xffffffffu, acc[ni][0], s0l);
            float t01 = __shfl_sync(0xffffffffu, acc[ni][1], s0l);
            float t10 = __shfl_sync(0xffffffffu, acc[ni][2], s0l);
            float t11 = __shfl_sync(0xffffffffu, acc[ni][3], s0l);
            float u00 = __shfl_sync(0xffffffffu, acc[ni][0], s1l);
            float u01 = __shfl_sync(0xffffffffu, acc[ni][1], s1l);
            float u10 = __shfl_sync(0xffffffffu, acc[ni][2], s1l);
            float u11 = __shfl_sync(0xffffffffu, acc[ni][3], s1l);
            unsigned a[4];
            a[0] = fu(sel ? t01 : t00);
            a[1] = fu(sel ? t11 : t10);
            a[2] = fu(sel ? u01 : u00);
            a[3] = fu(sel ? u11 : u10);
            int jb = wn*128 + ni*8;
            #pragma unroll
            for (int dt = 0; dt < 4; dt++) {
                unsigned b[2] = { fu(Vs[(jb + lc)*36 + dt*8 + lr]),
                                  fu(Vs[(jb + 4 + lc)*36 + dt*8 + lr]) };
                mma_tf32(oc[dt], a, b);
            }
        }

        // ---- partial store (no combine, no sync) ----
        size_t ro0 = ((size_t)r*LDIM + i0 + arow) * CDIM + h*HDIM;
        size_t ro1 = ro0 + 8*CDIM;
        #pragma unroll
        for (int dt = 0; dt < 4; dt++) {
            *(float2*)(outP + ro0 + dt*8 + lc*2) = make_float2(oc[dt][0], oc[dt][1]);
            *(float2*)(outP + ro1 + dt*8 + lc*2) = make_float2(oc[dt][2], oc[dt][3]);
        }
    }
}

// ============ kernel 3: (gate * (attn0+attn1)) @ w_out + b_out ============
#define GEMM_OUT_SMEM_FLOATS (64*APAD + 128*BPAD)
__global__ __launch_bounds__(256, 2) void gemm_out_kernel(
    const float* __restrict__ wout, const float* __restrict__ bout,
    float* __restrict__ out)
{
    extern __shared__ float sm[];
    float* As = sm;               // [64][APAD]
    float* Bs = sm + 64*APAD;     // [128][BPAD]
    int tid = threadIdx.x;
    int m0 = blockIdx.x * 64;

    #pragma unroll
    for (int it = 0; it < 8; it++) {
        int lin = tid + it*256;
        int r = lin >> 5, c4 = lin & 31;
        float4 gte = *(const float4*)(g_gate  + (size_t)(m0 + r)*CDIM + c4*4);
        float4 a0  = *(const float4*)(g_attn  + (size_t)(m0 + r)*CDIM + c4*4);
        float4 a1  = *(const float4*)(g_attn2 + (size_t)(m0 + r)*CDIM + c4*4);
        float4 a;
        a.x = f2tff(gte.x * (a0.x + a1.x)); a.y = f2tff(gte.y * (a0.y + a1.y));
        a.z = f2tff(gte.z * (a0.z + a1.z)); a.w = f2tff(gte.w * (a0.w + a1.w));
        *(float4*)(As + r*APAD + c4*4) = a;
    }
    #pragma unroll
    for (int it = 0; it < 16; it++) {
        int lin = tid + it*256;
        int k = lin >> 5, c4 = lin & 31;
        float4 w = *(const float4*)(wout + (size_t)k*CDIM + c4*4);
        w.x = f2tff(w.x); w.y = f2tff(w.y); w.z = f2tff(w.z); w.w = f2tff(w.w);
        *(float4*)(Bs + k*BPAD + c4*4) = w;
    }
    __syncthreads();

    int warp = tid >> 5, lane = tid & 31;
    int lr = lane >> 2, lc = lane & 3;
    int wm = warp & 1, wn = warp >> 1;

    float acc[2][4][4];
    #pragma unroll
    for (int mi = 0; mi < 2; mi++)
        #pragma unroll
        for (int ni = 0; ni < 4; ni++)
            acc[mi][ni][0] = acc[mi][ni][1] = acc[mi][ni][2] = acc[mi][ni][3] = 0.f;

    #pragma unroll
    for (int ks = 0; ks < 16; ks++) {
        int k0 = ks * 8;
        unsigned a[2][4], bf[4][2];
        #pragma unroll
        for (int mi = 0; mi < 2; mi++) {
            int r = wm*32 + mi*16 + lr;
            a[mi][0] = fu(As[r*APAD + k0 + lc]);
            a[mi][1] = fu(As[(r+8)*APAD + k0 + lc]);
            a[mi][2] = fu(As[r*APAD + k0 + 4 + lc]);
            a[mi][3] = fu(As[(r+8)*APAD + k0 + 4 + lc]);
        }
        #pragma unroll
        for (int ni = 0; ni < 4; ni++) {
            int n = wn*32 + ni*8 + lr;
            bf[ni][0] = fu(Bs[(k0 + lc)*BPAD + n]);
            bf[ni][1] = fu(Bs[(k0 + 4 + lc)*BPAD + n]);
        }
        #pragma unroll
        for (int mi = 0; mi < 2; mi++)
            #pragma unroll
            for (int ni = 0; ni < 4; ni++)
                mma_tf32(acc[mi][ni], a[mi], bf[ni]);
    }

    #pragma unroll
    for (int mi = 0; mi < 2; mi++) {
        #pragma unroll
        for (int ni = 0; ni < 4; ni++) {
            int gr = m0 + wm*32 + mi*16 + lr;
            int cn = wn*32 + ni*8 + lc*2;
            float b0 = bout[cn], b1 = bout[cn+1];
            *(float2*)(out + (size_t)gr * CDIM + cn) =
                make_float2(acc[mi][ni][0] + b0, acc[mi][ni][1] + b1);
            *(float2*)(out + (size_t)(gr+8) * CDIM + cn) =
                make_float2(acc[mi][ni][2] + b0, acc[mi][ni][3] + b1);
        }
    }
}

// ---------------- launch ----------------
extern "C" void kernel_launch(void* const* d_in, const int* in_sizes, int n_in,
                              void* d_out, int out_size)
{
    (void)in_sizes; (void)n_in; (void)out_size;
    const float* z        = (const float*)d_in[0];
    const int*   src_mask = (const int*)  d_in[1];
    const float* ln_g     = (const float*)d_in[2];
    const float* ln_b     = (const float*)d_in[3];
    const float* w_qkv    = (const float*)d_in[4];
    const float* w_pair   = (const float*)d_in[5];
    const float* w_gate   = (const float*)d_in[6];
    const float* b_gate   = (const float*)d_in[7];
    const float* w_out    = (const float*)d_in[8];
    const float* b_out    = (const float*)d_in[9];
    float* out = (float*)d_out;

    const int qkv_smem  = GEMM_QKV_SMEM_FLOATS * 4;
    const int out_smem  = GEMM_OUT_SMEM_FLOATS * 4;
    const int attn_smem = ATTN_SMEM_FLOATS * 4;
    cudaFuncSetAttribute(gemm_qkv_gate,   cudaFuncAttributeMaxDynamicSharedMemorySize, qkv_smem);
    cudaFuncSetAttribute(attn_kernel,     cudaFuncAttributeMaxDynamicSharedMemorySize, attn_smem);
    cudaFuncSetAttribute(gemm_out_kernel, cudaFuncAttributeMaxDynamicSharedMemorySize, out_smem);

    gemm_qkv_gate<<<NROWS/64, 256, qkv_smem>>>(z, ln_g, ln_b, w_qkv, w_gate, b_gate, w_pair);
    attn_kernel<<<dim3(NH, LDIM), 256, attn_smem>>>(src_mask);
    gemm_out_kernel<<<NROWS/64, 256, out_smem>>>(w_out, b_out, out);
}

// round 12
// speedup vs baseline: 1.0534x; 1.0294x over previous
#include <cuda_runtime.h>
#include <cstdint>

#define LDIM 256
#define CDIM 128
#define NH 4
#define HDIM 32
#define NROWS (LDIM*LDIM)        // 65536
#define QKVN 384
#define SQRT32 5.656854249492380f
#define APAD 140
#define BPAD 136

// ---------------- scratch ----------------
__device__ float g_qkv  [(size_t)NROWS * QKVN];
__device__ float g_gate [(size_t)NROWS * CDIM];
__device__ float g_biasT[(size_t)NH * NROWS];
__device__ float g_attn [(size_t)NROWS * CDIM];

// ---------------- helpers ----------------
__device__ __forceinline__ unsigned f2tf(float f) {
    unsigned r;
    asm("cvt.rna.tf32.f32 %0, %1;" : "=r"(r) : "f"(f));
    return r;
}
__device__ __forceinline__ float f2tff(float f) { return __uint_as_float(f2tf(f)); }
__device__ __forceinline__ unsigned fu(float f) { return __float_as_uint(f); }

__device__ __forceinline__ void mma_tf32(float c[4], const unsigned a[4], const unsigned b[2]) {
    asm volatile(
        "mma.sync.aligned.m16n8k8.row.col.f32.tf32.tf32.f32 "
        "{%0,%1,%2,%3},{%4,%5,%6,%7},{%8,%9},{%0,%1,%2,%3};"
        : "+f"(c[0]), "+f"(c[1]), "+f"(c[2]), "+f"(c[3])
        : "r"(a[0]), "r"(a[1]), "r"(a[2]), "r"(a[3]), "r"(b[0]), "r"(b[1]));
}

// ============ kernel 1: fused LN + GEMM  zn @ [w_qkv | w_gate], all 4 slabs per block ============
// (unchanged from R9 — validated at 105.7us)
#define GEMM_QKV_SMEM_FLOATS (64*APAD + 128*BPAD + 128 + 128 + 512)
__global__ __launch_bounds__(256, 2) void gemm_qkv_gate(
    const float* __restrict__ z, const float* __restrict__ lng, const float* __restrict__ lnb,
    const float* __restrict__ wqkv, const float* __restrict__ wgate,
    const float* __restrict__ bgate, const float* __restrict__ wpair)
{
    extern __shared__ float sm[];
    float* As  = sm;                    // [64][APAD]
    float* Bs  = sm + 64*APAD;          // [128][BPAD] (k, n)
    float* gS  = Bs + 128*BPAD;         // 128
    float* bS  = gS + 128;              // 128
    float* wpS = bS + 128;              // 512

    int tid = threadIdx.x;
    int m0 = blockIdx.x * 64;

    #pragma unroll
    for (int it = 0; it < 8; it++) {
        int lin = tid + it*256;
        int r = lin >> 5, c4 = lin & 31;
        *(float4*)(As + r*APAD + c4*4) =
            *(const float4*)(z + (size_t)(m0 + r)*CDIM + c4*4);
    }
    #pragma unroll
    for (int it = 0; it < 16; it++) {
        int lin = tid + it*256;
        int k = lin >> 5, c4 = lin & 31;
        float4 w = *(const float4*)(wqkv + (size_t)k*QKVN + c4*4);
        w.x = f2tff(w.x * SQRT32); w.y = f2tff(w.y * SQRT32);
        w.z = f2tff(w.z * SQRT32); w.w = f2tff(w.w * SQRT32);
        *(float4*)(Bs + k*BPAD + c4*4) = w;
    }
    if (tid < 128) { gS[tid] = lng[tid]; bS[tid] = lnb[tid]; }
    wpS[tid] = wpair[tid];
    wpS[tid + 256] = wpair[tid + 256];
    __syncthreads();

    {
        int row = tid >> 2, quad = tid & 3;
        float* Ar = As + row*APAD + quad*4;
        float v[32];
        float s = 0.f, ss = 0.f;
        #pragma unroll
        for (int k = 0; k < 8; k++) {
            float4 t = *(float4*)(Ar + k*16);
            v[k*4] = t.x; v[k*4+1] = t.y; v[k*4+2] = t.z; v[k*4+3] = t.w;
            s  += t.x + t.y + t.z + t.w;
            ss += t.x*t.x + t.y*t.y + t.z*t.z + t.w*t.w;
        }
        s  += __shfl_xor_sync(0xffffffffu, s, 1);  s  += __shfl_xor_sync(0xffffffffu, s, 2);
        ss += __shfl_xor_sync(0xffffffffu, ss, 1); ss += __shfl_xor_sync(0xffffffffu, ss, 2);
        float mu  = s * (1.0f / CDIM);
        float var = ss * (1.0f / CDIM) - mu * mu;
        float rstd = rsqrtf(var + 1e-5f);

        float bh0 = 0.f, bh1 = 0.f, bh2 = 0.f, bh3 = 0.f;
        #pragma unroll
        for (int k = 0; k < 8; k++) {
            float4 o;
            float* ov = &o.x;
            #pragma unroll
            for (int j = 0; j < 4; j++) {
                int c = quad*4 + k*16 + j;
                float zn = (v[k*4+j] - mu) * rstd * gS[c] + bS[c];
                bh0 += zn * wpS[c*4];   bh1 += zn * wpS[c*4+1];
                bh2 += zn * wpS[c*4+2]; bh3 += zn * wpS[c*4+3];
                ov[j] = f2tff(zn);
            }
            *(float4*)(Ar + k*16) = o;
        }
        bh0 += __shfl_xor_sync(0xffffffffu, bh0, 1); bh0 += __shfl_xor_sync(0xffffffffu, bh0, 2);
        bh1 += __shfl_xor_sync(0xffffffffu, bh1, 1); bh1 += __shfl_xor_sync(0xffffffffu, bh1, 2);
        bh2 += __shfl_xor_sync(0xffffffffu, bh2, 1); bh2 += __shfl_xor_sync(0xffffffffu, bh2, 2);
        bh3 += __shfl_xor_sync(0xffffffffu, bh3, 1); bh3 += __shfl_xor_sync(0xffffffffu, bh3, 2);
        if (quad == 0) {
            g_biasT[(size_t)0*NROWS + m0 + row] = bh0;
            g_biasT[(size_t)1*NROWS + m0 + row] = bh1;
            g_biasT[(size_t)2*NROWS + m0 + row] = bh2;
            g_biasT[(size_t)3*NROWS + m0 + row] = bh3;
        }
    }
    __syncthreads();

    int warp = tid >> 5, lane = tid & 31;
    int lr = lane >> 2, lc = lane & 3;
    int wm = warp & 1, wn = warp >> 1;

    #pragma unroll
    for (int nt = 0; nt < 4; nt++) {
        float acc[2][4][4];
        #pragma unroll
        for (int mi = 0; mi < 2; mi++)
            #pragma unroll
            for (int ni = 0; ni < 4; ni++)
                acc[mi][ni][0] = acc[mi][ni][1] = acc[mi][ni][2] = acc[mi][ni][3] = 0.f;

        #pragma unroll
        for (int ks = 0; ks < 16; ks++) {
            int k0 = ks * 8;
            unsigned a[2][4], bf[4][2];
            #pragma unroll
            for (int mi = 0; mi < 2; mi++) {
                int r = wm*32 + mi*16 + lr;
                a[mi][0] = fu(As[r*APAD + k0 + lc]);
                a[mi][1] = fu(As[(r+8)*APAD + k0 + lc]);
                a[mi][2] = fu(As[r*APAD + k0 + 4 + lc]);
                a[mi][3] = fu(As[(r+8)*APAD + k0 + 4 + lc]);
            }
            #pragma unroll
            for (int ni = 0; ni < 4; ni++) {
                int n = wn*32 + ni*8 + lr;
                bf[ni][0] = fu(Bs[(k0 + lc)*BPAD + n]);
                bf[ni][1] = fu(Bs[(k0 + 4 + lc)*BPAD + n]);
            }
            #pragma unroll
            for (int mi = 0; mi < 2; mi++)
                #pragma unroll
                for (int ni = 0; ni < 4; ni++)
                    mma_tf32(acc[mi][ni], a[mi], bf[ni]);
        }

        #pragma unroll
        for (int mi = 0; mi < 2; mi++) {
            #pragma unroll
            for (int ni = 0; ni < 4; ni++) {
                int gr = m0 + wm*32 + mi*16 + lr;
                int cn = wn*32 + ni*8 + lc*2;
                if (nt < 3) {
                    int gc = nt*128 + cn;
                    *(float2*)(g_qkv + (size_t)gr * QKVN + gc) =
                        make_float2(f2tff(acc[mi][ni][0]), f2tff(acc[mi][ni][1]));
                    *(float2*)(g_qkv + (size_t)(gr+8) * QKVN + gc) =
                        make_float2(f2tff(acc[mi][ni][2]), f2tff(acc[mi][ni][3]));
                } else {
                    float b0 = bgate[cn], b1 = bgate[cn+1];
                    *(float2*)(g_gate + (size_t)gr * CDIM + cn) =
                        make_float2(1.f/(1.f + __expf(-(acc[mi][ni][0] + b0))),
                                    1.f/(1.f + __expf(-(acc[mi][ni][1] + b1))));
                    *(float2*)(g_gate + (size_t)(gr+8) * CDIM + cn) =
                        make_float2(1.f/(1.f + __expf(-(acc[mi][ni][2] + b0))),
                                    1.f/(1.f + __expf(-(acc[mi][ni][3] + b1))));
                }
            }
        }

        if (nt < 3) {
            __syncthreads();
            #pragma unroll
            for (int it = 0; it < 16; it++) {
                int lin = tid + it*256;
                int k = lin >> 5, c4 = lin & 31;
                float4 w;
                if (nt + 1 < 3) w = *(const float4*)(wqkv + (size_t)k*QKVN + (nt+1)*128 + c4*4);
                else            w = *(const float4*)(wgate + (size_t)k*CDIM + c4*4);
                w.x = f2tff(w.x); w.y = f2tff(w.y); w.z = f2tff(w.z); w.w = f2tff(w.w);
                *(float4*)(Bs + k*BPAD + c4*4) = w;
            }
            __syncthreads();
        }
    }
}

// ============ kernel 2: attention per (h, r) — R9 structure, no-max softmax ============
// 256 threads, 8 warps: wm = warp>>1 (16-row strip of 64-chunk), wn = warp&1 (j half of 128).
#define ATTN_SMEM_FLOATS (256*36*2 + 64*36 + 128 + 64*32 + 256)
__global__ __launch_bounds__(256, 2) void attn_kernel(const int* __restrict__ src_mask)
{
    extern __shared__ float sm[];
    float* Ks     = sm;                 // [256][36]
    float* Vs     = Ks + 256*36;        // [256][36]
    float* Qs     = Vs + 256*36;        // [64][36]
    float* redsum = Qs + 64*36;         // [2][64]
    float* obuf   = redsum + 128;       // [64][32]
    float* msk    = obuf + 64*32;       // [256]

    int h = blockIdx.x, r = blockIdx.y;
    int tid = threadIdx.x;
    const float* base = g_qkv + (size_t)r * LDIM * QKVN;

    #pragma unroll
    for (int p = 0; p < 8; p++) {
        int lin = tid + p*256;
        int j = lin >> 3, d4 = lin & 7;
        *(float4*)(Ks + j*36 + d4*4) =
            *(const float4*)(base + (size_t)j*QKVN + 128 + h*HDIM + d4*4);
        *(float4*)(Vs + j*36 + d4*4) =
            *(const float4*)(base + (size_t)j*QKVN + 256 + h*HDIM + d4*4);
    }
    msk[tid] = (src_mask[tid] == 0) ? -1.f : 1.f;

    int warp = tid >> 5, lane = tid & 31;
    int lr = lane >> 2, lc = lane & 3;
    int wm = warp >> 1, wn = warp & 1;
    int arow = wm*16 + lr;
    const float* biasH = g_biasT + (size_t)h * NROWS;

    int s0l = (lane & ~3) | (lc >> 1);
    int s1l = s0l + 2;
    int sel = lc & 1;

    for (int ic = 0; ic < 4; ic++) {
        int i0 = ic * 64;
        __syncthreads();   // K/V ready (ic=0); prior chunk's Qs/obuf reads complete (ic>0)
        #pragma unroll
        for (int p = 0; p < 2; p++) {
            int lin = tid + p*256;
            int row = lin >> 3, d4 = lin & 7;
            *(float4*)(Qs + row*36 + d4*4) =
                *(const float4*)(base + (size_t)(i0 + row)*QKVN + h*HDIM + d4*4);
        }
        __syncthreads();

        // ---- QK^T over this warp's 128 j-cols ----
        float acc[16][4];
        #pragma unroll
        for (int ni = 0; ni < 16; ni++)
            acc[ni][0] = acc[ni][1] = acc[ni][2] = acc[ni][3] = 0.f;

        #pragma unroll
        for (int ks = 0; ks < 4; ks++) {
            int k0 = ks * 8;
            unsigned a[4] = { fu(Qs[arow*36 + k0 + lc]),     fu(Qs[(arow+8)*36 + k0 + lc]),
                              fu(Qs[arow*36 + k0 + 4 + lc]), fu(Qs[(arow+8)*36 + k0 + 4 + lc]) };
            #pragma unroll
            for (int ni = 0; ni < 16; ni++) {
                int j = wn*128 + ni*8 + lr;
                unsigned b[2] = { fu(Ks[j*36 + k0 + lc]), fu(Ks[j*36 + k0 + 4 + lc]) };
                mma_tf32(acc[ni], a, b);
            }
        }

        // ---- bias + mask + direct exp (no max shift: |logits| << 88) + local sum ----
        float mi0 = msk[i0 + arow], mi1 = msk[i0 + arow + 8];
        const float* bp0 = biasH + (size_t)(i0 + arow) * LDIM;
        const float* bp1 = bp0 + 8 * LDIM;
        float sm0 = 0.f, sm1 = 0.f;
        #pragma unroll
        for (int ni = 0; ni < 16; ni++) {
            int j = wn*128 + ni*8 + lc*2;
            float2 b0 = *(const float2*)(bp0 + j);
            float2 b1 = *(const float2*)(bp1 + j);
            float mj0 = msk[j], mj1 = msk[j+1];
            float v0 = acc[ni][0] + b0.x;
            float v1 = acc[ni][1] + b0.y;
            float v2 = acc[ni][2] + b1.x;
            float v3 = acc[ni][3] + b1.y;
            if (mi0*mj0 < 0.f) v0 = -1e-9f;
            if (mi0*mj1 < 0.f) v1 = -1e-9f;
            if (mi1*mj0 < 0.f) v2 = -1e-9f;
            if (mi1*mj1 < 0.f) v3 = -1e-9f;
            float e0 = __expf(v0), e1 = __expf(v1);
            float e2 = __expf(v2), e3 = __expf(v3);
            acc[ni][0] = e0; acc[ni][1] = e1; acc[ni][2] = e2; acc[ni][3] = e3;
            sm0 += e0 + e1; sm1 += e2 + e3;
        }
        sm0 += __shfl_xor_sync(0xffffffffu, sm0, 1);
        sm0 += __shfl_xor_sync(0xffffffffu, sm0, 2);
        sm1 += __shfl_xor_sync(0xffffffffu, sm1, 1);
        sm1 += __shfl_xor_sync(0xffffffffu, sm1, 2);
        if (lc == 0) { redsum[wn*64 + arow] = sm0; redsum[wn*64 + arow + 8] = sm1; }
        __syncthreads();
        float inv0 = 1.f / (redsum[arow]     + redsum[64 + arow]);
        float inv1 = 1.f / (redsum[arow + 8] + redsum[64 + arow + 8]);
        #pragma unroll
        for (int ni = 0; ni < 16; ni++) {
            acc[ni][0] = f2tff(acc[ni][0] * inv0);
            acc[ni][1] = f2tff(acc[ni][1] * inv0);
            acc[ni][2] = f2tff(acc[ni][2] * inv1);
            acc[ni][3] = f2tff(acc[ni][3] * inv1);
        }

        // ---- P @ V over this warp's 128 j-cols ----
        float oc[4][4];
        #pragma unroll
        for (int dt = 0; dt < 4; dt++)
            oc[dt][0] = oc[dt][1] = oc[dt][2] = oc[dt][3] = 0.f;

        #pragma unroll
        for (int ni = 0; ni < 16; ni++) {
            float t00 = __shfl_sync(0xffffffffu, acc[ni][0], s0l);
            float t01 = __shfl_sync(0xffffffffu, acc[ni][1], s0l);
            float t10 = __shfl_sync(0xffffffffu, acc[ni][2], s0l);
            float t11 = __shfl_sync(0xffffffffu, acc[ni][3], s0l);
            float u00 = __shfl_sync(0xffffffffu, acc[ni][0], s1l);
            float u01 = __shfl_sync(0xffffffffu, acc[ni][1], s1l);
            float u10 = __shfl_sync(0xffffffffu, acc[ni][2], s1l);
            float u11 = __shfl_sync(0xffffffffu, acc[ni][3], s1l);
            unsigned a[4];
            a[0] = fu(sel ? t01 : t00);
            a[1] = fu(sel ? t11 : t10);
            a[2] = fu(sel ? u01 : u00);
            a[3] = fu(sel ? u11 : u10);
            int jb = wn*128 + ni*8;
            #pragma unroll
            for (int dt = 0; dt < 4; dt++) {
                unsigned b[2] = { fu(Vs[(jb + lc)*36 + dt*8 + lr]),
                                  fu(Vs[(jb + 4 + lc)*36 + dt*8 + lr]) };
                mma_tf32(oc[dt], a, b);
            }
        }

        // ---- combine the two j-halves and store ----
        if (wn == 1) {
            #pragma unroll
            for (int dt = 0; dt < 4; dt++) {
                *(float2*)(obuf + arow*32 + dt*8 + lc*2)      = make_float2(oc[dt][0], oc[dt][1]);
                *(float2*)(obuf + (arow+8)*32 + dt*8 + lc*2)  = make_float2(oc[dt][2], oc[dt][3]);
            }
        }
        __syncthreads();
        if (wn == 0) {
            size_t ro0 = ((size_t)r*LDIM + i0 + arow) * CDIM + h*HDIM;
            size_t ro1 = ro0 + 8*CDIM;
            #pragma unroll
            for (int dt = 0; dt < 4; dt++) {
                float2 p0 = *(float2*)(obuf + arow*32 + dt*8 + lc*2);
                float2 p1 = *(float2*)(obuf + (arow+8)*32 + dt*8 + lc*2);
                *(float2*)(g_attn + ro0 + dt*8 + lc*2) = make_float2(oc[dt][0] + p0.x, oc[dt][1] + p0.y);
                *(float2*)(g_attn + ro1 + dt*8 + lc*2) = make_float2(oc[dt][2] + p1.x, oc[dt][3] + p1.y);
            }
        }
    }
}

// ============ kernel 3: (gate * attn) @ w_out + b_out (R9 config, validated) ============
#define GEMM_OUT_SMEM_FLOATS (64*APAD + 128*BPAD)
__global__ __launch_bounds__(256, 2) void gemm_out_kernel(
    const float* __restrict__ wout, const float* __restrict__ bout,
    float* __restrict__ out)
{
    extern __shared__ float sm[];
    float* As = sm;               // [64][APAD]
    float* Bs = sm + 64*APAD;     // [128][BPAD]
    int tid = threadIdx.x;
    int m0 = blockIdx.x * 64;

    #pragma unroll
    for (int it = 0; it < 8; it++) {
        int lin = tid + it*256;
        int r = lin >> 5, c4 = lin & 31;
        float4 gte = *(const float4*)(g_gate + (size_t)(m0 + r)*CDIM + c4*4);
        float4 att = *(const float4*)(g_attn + (size_t)(m0 + r)*CDIM + c4*4);
        float4 a;
        a.x = f2tff(gte.x * att.x); a.y = f2tff(gte.y * att.y);
        a.z = f2tff(gte.z * att.z); a.w = f2tff(gte.w * att.w);
        *(float4*)(As + r*APAD + c4*4) = a;
    }
    #pragma unroll
    for (int it = 0; it < 16; it++) {
        int lin = tid + it*256;
        int k = lin >> 5, c4 = lin & 31;
        float4 w = *(const float4*)(wout + (size_t)k*CDIM + c4*4);
        w.x = f2tff(w.x); w.y = f2tff(w.y); w.z = f2tff(w.z); w.w = f2tff(w.w);
        *(float4*)(Bs + k*BPAD + c4*4) = w;
    }
    __syncthreads();

    int warp = tid >> 5, lane = tid & 31;
    int lr = lane >> 2, lc = lane & 3;
    int wm = warp & 1, wn = warp >> 1;

    float acc[2][4][4];
    #pragma unroll
    for (int mi = 0; mi < 2; mi++)
        #pragma unroll
        for (int ni = 0; ni < 4; ni++)
            acc[mi][ni][0] = acc[mi][ni][1] = acc[mi][ni][2] = acc[mi][ni][3] = 0.f;

    #pragma unroll
    for (int ks = 0; ks < 16; ks++) {
        int k0 = ks * 8;
        unsigned a[2][4], bf[4][2];
        #pragma unroll
        for (int mi = 0; mi < 2; mi++) {
            int r = wm*32 + mi*16 + lr;
            a[mi][0] = fu(As[r*APAD + k0 + lc]);
            a[mi][1] = fu(As[(r+8)*APAD + k0 + lc]);
            a[mi][2] = fu(As[r*APAD + k0 + 4 + lc]);
            a[mi][3] = fu(As[(r+8)*APAD + k0 + 4 + lc]);
        }
        #pragma unroll
        for (int ni = 0; ni < 4; ni++) {
            int n = wn*32 + ni*8 + lr;
            bf[ni][0] = fu(Bs[(k0 + lc)*BPAD + n]);
            bf[ni][1] = fu(Bs[(k0 + 4 + lc)*BPAD + n]);
        }
        #pragma unroll
        for (int mi = 0; mi < 2; mi++)
            #pragma unroll
            for (int ni = 0; ni < 4; ni++)
                mma_tf32(acc[mi][ni], a[mi], bf[ni]);
    }

    #pragma unroll
    for (int mi = 0; mi < 2; mi++) {
        #pragma unroll
        for (int ni = 0; ni < 4; ni++) {
            int gr = m0 + wm*32 + mi*16 + lr;
            int cn = wn*32 + ni*8 + lc*2;
            float b0 = bout[cn], b1 = bout[cn+1];
            *(float2*)(out + (size_t)gr * CDIM + cn) =
                make_float2(acc[mi][ni][0] + b0, acc[mi][ni][1] + b1);
            *(float2*)(out + (size_t)(gr+8) * CDIM + cn) =
                make_float2(acc[mi][ni][2] + b0, acc[mi][ni][3] + b1);
        }
    }
}

// ---------------- launch ----------------
extern "C" void kernel_launch(void* const* d_in, const int* in_sizes, int n_in,
                              void* d_out, int out_size)
{
    (void)in_sizes; (void)n_in; (void)out_size;
    const float* z        = (const float*)d_in[0];
    const int*   src_mask = (const int*)  d_in[1];
    const float* ln_g     = (const float*)d_in[2];
    const float* ln_b     = (const float*)d_in[3];
    const float* w_qkv    = (const float*)d_in[4];
    const float* w_pair   = (const float*)d_in[5];
    const float* w_gate   = (const float*)d_in[6];
    const float* b_gate   = (const float*)d_in[7];
    const float* w_out    = (const float*)d_in[8];
    const float* b_out    = (const float*)d_in[9];
    float* out = (float*)d_out;

    const int qkv_smem  = GEMM_QKV_SMEM_FLOATS * 4;
    const int out_smem  = GEMM_OUT_SMEM_FLOATS * 4;
    const int attn_smem = ATTN_SMEM_FLOATS * 4;
    cudaFuncSetAttribute(gemm_qkv_gate,   cudaFuncAttributeMaxDynamicSharedMemorySize, qkv_smem);
    cudaFuncSetAttribute(attn_kernel,     cudaFuncAttributeMaxDynamicSharedMemorySize, attn_smem);
    cudaFuncSetAttribute(gemm_out_kernel, cudaFuncAttributeMaxDynamicSharedMemorySize, out_smem);

    gemm_qkv_gate<<<NROWS/64, 256, qkv_smem>>>(z, ln_g, ln_b, w_qkv, w_gate, b_gate, w_pair);
    attn_kernel<<<dim3(NH, LDIM), 256, attn_smem>>>(src_mask);
    gemm_out_kernel<<<NROWS/64, 256, out_smem>>>(w_out, b_out, out);
}

// round 13
// speedup vs baseline: 1.0617x; 1.0079x over previous
#include <cuda_runtime.h>
#include <cstdint>

#define LDIM 256
#define CDIM 128
#define NH 4
#define HDIM 32
#define NROWS (LDIM*LDIM)        // 65536
#define QKVN 384
#define SQRT32 5.656854249492380f
#define APAD 140
#define BPAD 136

// ---------------- scratch ----------------
__device__ float g_qkv  [(size_t)NROWS * QKVN];
__device__ float g_gate [(size_t)NROWS * CDIM];
__device__ float g_biasT[(size_t)NH * NROWS];
__device__ float g_attn [(size_t)NROWS * CDIM];

// ---------------- helpers ----------------
__device__ __forceinline__ unsigned f2tf(float f) {
    unsigned r;
    asm("cvt.rna.tf32.f32 %0, %1;" : "=r"(r) : "f"(f));
    return r;
}
__device__ __forceinline__ float f2tff(float f) { return __uint_as_float(f2tf(f)); }
__device__ __forceinline__ unsigned fu(float f) { return __float_as_uint(f); }

__device__ __forceinline__ void mma_tf32(float c[4], const unsigned a[4], const unsigned b[2]) {
    asm volatile(
        "mma.sync.aligned.m16n8k8.row.col.f32.tf32.tf32.f32 "
        "{%0,%1,%2,%3},{%4,%5,%6,%7},{%8,%9},{%0,%1,%2,%3};"
        : "+f"(c[0]), "+f"(c[1]), "+f"(c[2]), "+f"(c[3])
        : "r"(a[0]), "r"(a[1]), "r"(a[2]), "r"(a[3]), "r"(b[0]), "r"(b[1]));
}

__device__ __forceinline__ void cp_async16(float* smem_dst, const float* gsrc) {
    unsigned s = (unsigned)__cvta_generic_to_shared(smem_dst);
    asm volatile("cp.async.cg.shared.global [%0], [%1], 16;" :: "r"(s), "l"(gsrc));
}
__device__ __forceinline__ void cp_commit() { asm volatile("cp.async.commit_group;"); }
template<int N> __device__ __forceinline__ void cp_wait() {
    asm volatile("cp.async.wait_group %0;" :: "n"(N));
}

// ============ kernel 1: fused LN + GEMM  zn @ [w_qkv | w_gate], all 4 slabs per block ============
// (unchanged from R9 — validated at 105.7us)
#define GEMM_QKV_SMEM_FLOATS (64*APAD + 128*BPAD + 128 + 128 + 512)
__global__ __launch_bounds__(256, 2) void gemm_qkv_gate(
    const float* __restrict__ z, const float* __restrict__ lng, const float* __restrict__ lnb,
    const float* __restrict__ wqkv, const float* __restrict__ wgate,
    const float* __restrict__ bgate, const float* __restrict__ wpair)
{
    extern __shared__ float sm[];
    float* As  = sm;                    // [64][APAD]
    float* Bs  = sm + 64*APAD;          // [128][BPAD] (k, n)
    float* gS  = Bs + 128*BPAD;         // 128
    float* bS  = gS + 128;              // 128
    float* wpS = bS + 128;              // 512

    int tid = threadIdx.x;
    int m0 = blockIdx.x * 64;

    #pragma unroll
    for (int it = 0; it < 8; it++) {
        int lin = tid + it*256;
        int r = lin >> 5, c4 = lin & 31;
        *(float4*)(As + r*APAD + c4*4) =
            *(const float4*)(z + (size_t)(m0 + r)*CDIM + c4*4);
    }
    #pragma unroll
    for (int it = 0; it < 16; it++) {
        int lin = tid + it*256;
        int k = lin >> 5, c4 = lin & 31;
        float4 w = *(const float4*)(wqkv + (size_t)k*QKVN + c4*4);
        w.x = f2tff(w.x * SQRT32); w.y = f2tff(w.y * SQRT32);
        w.z = f2tff(w.z * SQRT32); w.w = f2tff(w.w * SQRT32);
        *(float4*)(Bs + k*BPAD + c4*4) = w;
    }
    if (tid < 128) { gS[tid] = lng[tid]; bS[tid] = lnb[tid]; }
    wpS[tid] = wpair[tid];
    wpS[tid + 256] = wpair[tid + 256];
    __syncthreads();

    {
        int row = tid >> 2, quad = tid & 3;
        float* Ar = As + row*APAD + quad*4;
        float v[32];
        float s = 0.f, ss = 0.f;
        #pragma unroll
        for (int k = 0; k < 8; k++) {
            float4 t = *(float4*)(Ar + k*16);
            v[k*4] = t.x; v[k*4+1] = t.y; v[k*4+2] = t.z; v[k*4+3] = t.w;
            s  += t.x + t.y + t.z + t.w;
            ss += t.x*t.x + t.y*t.y + t.z*t.z + t.w*t.w;
        }
        s  += __shfl_xor_sync(0xffffffffu, s, 1);  s  += __shfl_xor_sync(0xffffffffu, s, 2);
        ss += __shfl_xor_sync(0xffffffffu, ss, 1); ss += __shfl_xor_sync(0xffffffffu, ss, 2);
        float mu  = s * (1.0f / CDIM);
        float var = ss * (1.0f / CDIM) - mu * mu;
        float rstd = rsqrtf(var + 1e-5f);

        float bh0 = 0.f, bh1 = 0.f, bh2 = 0.f, bh3 = 0.f;
        #pragma unroll
        for (int k = 0; k < 8; k++) {
            float4 o;
            float* ov = &o.x;
            #pragma unroll
            for (int j = 0; j < 4; j++) {
                int c = quad*4 + k*16 + j;
                float zn = (v[k*4+j] - mu) * rstd * gS[c] + bS[c];
                bh0 += zn * wpS[c*4];   bh1 += zn * wpS[c*4+1];
                bh2 += zn * wpS[c*4+2]; bh3 += zn * wpS[c*4+3];
                ov[j] = f2tff(zn);
            }
            *(float4*)(Ar + k*16) = o;
        }
        bh0 += __shfl_xor_sync(0xffffffffu, bh0, 1); bh0 += __shfl_xor_sync(0xffffffffu, bh0, 2);
        bh1 += __shfl_xor_sync(0xffffffffu, bh1, 1); bh1 += __shfl_xor_sync(0xffffffffu, bh1, 2);
        bh2 += __shfl_xor_sync(0xffffffffu, bh2, 1); bh2 += __shfl_xor_sync(0xffffffffu, bh2, 2);
        bh3 += __shfl_xor_sync(0xffffffffu, bh3, 1); bh3 += __shfl_xor_sync(0xffffffffu, bh3, 2);
        if (quad == 0) {
            g_biasT[(size_t)0*NROWS + m0 + row] = bh0;
            g_biasT[(size_t)1*NROWS + m0 + row] = bh1;
            g_biasT[(size_t)2*NROWS + m0 + row] = bh2;
            g_biasT[(size_t)3*NROWS + m0 + row] = bh3;
        }
    }
    __syncthreads();

    int warp = tid >> 5, lane = tid & 31;
    int lr = lane >> 2, lc = lane & 3;
    int wm = warp & 1, wn = warp >> 1;

    #pragma unroll
    for (int nt = 0; nt < 4; nt++) {
        float acc[2][4][4];
        #pragma unroll
        for (int mi = 0; mi < 2; mi++)
            #pragma unroll
            for (int ni = 0; ni < 4; ni++)
                acc[mi][ni][0] = acc[mi][ni][1] = acc[mi][ni][2] = acc[mi][ni][3] = 0.f;

        #pragma unroll
        for (int ks = 0; ks < 16; ks++) {
            int k0 = ks * 8;
            unsigned a[2][4], bf[4][2];
            #pragma unroll
            for (int mi = 0; mi < 2; mi++) {
                int r = wm*32 + mi*16 + lr;
                a[mi][0] = fu(As[r*APAD + k0 + lc]);
                a[mi][1] = fu(As[(r+8)*APAD + k0 + lc]);
                a[mi][2] = fu(As[r*APAD + k0 + 4 + lc]);
                a[mi][3] = fu(As[(r+8)*APAD + k0 + 4 + lc]);
            }
            #pragma unroll
            for (int ni = 0; ni < 4; ni++) {
                int n = wn*32 + ni*8 + lr;
                bf[ni][0] = fu(Bs[(k0 + lc)*BPAD + n]);
                bf[ni][1] = fu(Bs[(k0 + 4 + lc)*BPAD + n]);
            }
            #pragma unroll
            for (int mi = 0; mi < 2; mi++)
                #pragma unroll
                for (int ni = 0; ni < 4; ni++)
                    mma_tf32(acc[mi][ni], a[mi], bf[ni]);
        }

        #pragma unroll
        for (int mi = 0; mi < 2; mi++) {
            #pragma unroll
            for (int ni = 0; ni < 4; ni++) {
                int gr = m0 + wm*32 + mi*16 + lr;
                int cn = wn*32 + ni*8 + lc*2;
                if (nt < 3) {
                    int gc = nt*128 + cn;
                    *(float2*)(g_qkv + (size_t)gr * QKVN + gc) =
                        make_float2(f2tff(acc[mi][ni][0]), f2tff(acc[mi][ni][1]));
                    *(float2*)(g_qkv + (size_t)(gr+8) * QKVN + gc) =
                        make_float2(f2tff(acc[mi][ni][2]), f2tff(acc[mi][ni][3]));
                } else {
                    float b0 = bgate[cn], b1 = bgate[cn+1];
                    *(float2*)(g_gate + (size_t)gr * CDIM + cn) =
                        make_float2(1.f/(1.f + __expf(-(acc[mi][ni][0] + b0))),
                                    1.f/(1.f + __expf(-(acc[mi][ni][1] + b1))));
                    *(float2*)(g_gate + (size_t)(gr+8) * CDIM + cn) =
                        make_float2(1.f/(1.f + __expf(-(acc[mi][ni][2] + b0))),
                                    1.f/(1.f + __expf(-(acc[mi][ni][3] + b1))));
                }
            }
        }

        if (nt < 3) {
            __syncthreads();
            #pragma unroll
            for (int it = 0; it < 16; it++) {
                int lin = tid + it*256;
                int k = lin >> 5, c4 = lin & 31;
                float4 w;
                if (nt + 1 < 3) w = *(const float4*)(wqkv + (size_t)k*QKVN + (nt+1)*128 + c4*4);
                else            w = *(const float4*)(wgate + (size_t)k*CDIM + c4*4);
                w.x = f2tff(w.x); w.y = f2tff(w.y); w.z = f2tff(w.z); w.w = f2tff(w.w);
                *(float4*)(Bs + k*BPAD + c4*4) = w;
            }
            __syncthreads();
        }
    }
}

// ============ kernel 2: attention per (h, r, zhalf) — R12 compute, 2 chunks/block, cp.async staging ============
#define ATTN_SMEM_FLOATS (256*36*2 + 64*36 + 128 + 64*32 + 256)
__global__ __launch_bounds__(256, 2) void attn_kernel(const int* __restrict__ src_mask)
{
    extern __shared__ float sm[];
    float* Ks     = sm;                 // [256][36]
    float* Vs     = Ks + 256*36;        // [256][36]
    float* Qs     = Vs + 256*36;        // [64][36]
    float* redsum = Qs + 64*36;         // [2][64]
    float* obuf   = redsum + 128;       // [64][32]
    float* msk    = obuf + 64*32;       // [256]

    int h = blockIdx.x, r = blockIdx.y, zh = blockIdx.z;
    int tid = threadIdx.x;
    const float* base = g_qkv + (size_t)r * LDIM * QKVN;

    // K/V staging via cp.async (single L1 pass)
    #pragma unroll
    for (int p = 0; p < 8; p++) {
        int lin = tid + p*256;
        int j = lin >> 3, d4 = lin & 7;
        cp_async16(Ks + j*36 + d4*4, base + (size_t)j*QKVN + 128 + h*HDIM + d4*4);
        cp_async16(Vs + j*36 + d4*4, base + (size_t)j*QKVN + 256 + h*HDIM + d4*4);
    }
    cp_commit();
    msk[tid] = (src_mask[tid] == 0) ? -1.f : 1.f;

    int warp = tid >> 5, lane = tid & 31;
    int lr = lane >> 2, lc = lane & 3;
    int wm = warp >> 1, wn = warp & 1;
    int arow = wm*16 + lr;
    const float* biasH = g_biasT + (size_t)h * NROWS;

    int s0l = (lane & ~3) | (lc >> 1);
    int s1l = s0l + 2;
    int sel = lc & 1;

    for (int icl = 0; icl < 2; icl++) {
        int ic = zh*2 + icl;
        int i0 = ic * 64;
        if (icl) __syncthreads();    // prior chunk's Qs/obuf reads complete
        #pragma unroll
        for (int p = 0; p < 2; p++) {
            int lin = tid + p*256;
            int row = lin >> 3, d4 = lin & 7;
            cp_async16(Qs + row*36 + d4*4, base + (size_t)(i0 + row)*QKVN + h*HDIM + d4*4);
        }
        cp_commit();
        cp_wait<0>();               // all staging complete (K/V included on first iter)
        __syncthreads();

        // ---- QK^T over this warp's 128 j-cols ----
        float acc[16][4];
        #pragma unroll
        for (int ni = 0; ni < 16; ni++)
            acc[ni][0] = acc[ni][1] = acc[ni][2] = acc[ni][3] = 0.f;

        #pragma unroll
        for (int ks = 0; ks < 4; ks++) {
            int k0 = ks * 8;
            unsigned a[4] = { fu(Qs[arow*36 + k0 + lc]),     fu(Qs[(arow+8)*36 + k0 + lc]),
                              fu(Qs[arow*36 + k0 + 4 + lc]), fu(Qs[(arow+8)*36 + k0 + 4 + lc]) };
            #pragma unroll
            for (int ni = 0; ni < 16; ni++) {
                int j = wn*128 + ni*8 + lr;
                unsigned b[2] = { fu(Ks[j*36 + k0 + lc]), fu(Ks[j*36 + k0 + 4 + lc]) };
                mma_tf32(acc[ni], a, b);
            }
        }

        // ---- bias + mask + direct exp + local sum ----
        float mi0 = msk[i0 + arow], mi1 = msk[i0 + arow + 8];
        const float* bp0 = biasH + (size_t)(i0 + arow) * LDIM;
        const float* bp1 = bp0 + 8 * LDIM;
        float sm0 = 0.f, sm1 = 0.f;
        #pragma unroll
        for (int ni = 0; ni < 16; ni++) {
            int j = wn*128 + ni*8 + lc*2;
            float2 b0 = *(const float2*)(bp0 + j);
            float2 b1 = *(const float2*)(bp1 + j);
            float mj0 = msk[j], mj1 = msk[j+1];
            float v0 = acc[ni][0] + b0.x;
            float v1 = acc[ni][1] + b0.y;
            float v2 = acc[ni][2] + b1.x;
            float v3 = acc[ni][3] + b1.y;
            if (mi0*mj0 < 0.f) v0 = -1e-9f;
            if (mi0*mj1 < 0.f) v1 = -1e-9f;
            if (mi1*mj0 < 0.f) v2 = -1e-9f;
            if (mi1*mj1 < 0.f) v3 = -1e-9f;
            float e0 = __expf(v0), e1 = __expf(v1);
            float e2 = __expf(v2), e3 = __expf(v3);
            acc[ni][0] = e0; acc[ni][1] = e1; acc[ni][2] = e2; acc[ni][3] = e3;
            sm0 += e0 + e1; sm1 += e2 + e3;
        }
        sm0 += __shfl_xor_sync(0xffffffffu, sm0, 1);
        sm0 += __shfl_xor_sync(0xffffffffu, sm0, 2);
        sm1 += __shfl_xor_sync(0xffffffffu, sm1, 1);
        sm1 += __shfl_xor_sync(0xffffffffu, sm1, 2);
        if (lc == 0) { redsum[wn*64 + arow] = sm0; redsum[wn*64 + arow + 8] = sm1; }
        __syncthreads();
        float inv0 = 1.f / (redsum[arow]     + redsum[64 + arow]);
        float inv1 = 1.f / (redsum[arow + 8] + redsum[64 + arow + 8]);
        #pragma unroll
        for (int ni = 0; ni < 16; ni++) {
            acc[ni][0] = f2tff(acc[ni][0] * inv0);
            acc[ni][1] = f2tff(acc[ni][1] * inv0);
            acc[ni][2] = f2tff(acc[ni][2] * inv1);
            acc[ni][3] = f2tff(acc[ni][3] * inv1);
        }

        // ---- P @ V over this warp's 128 j-cols ----
        float oc[4][4];
        #pragma unroll
        for (int dt = 0; dt < 4; dt++)
            oc[dt][0] = oc[dt][1] = oc[dt][2] = oc[dt][3] = 0.f;

        #pragma unroll
        for (int ni = 0; ni < 16; ni++) {
            float t00 = __shfl_sync(0xffffffffu, acc[ni][0], s0l);
            float t01 = __shfl_sync(0xffffffffu, acc[ni][1], s0l);
            float t10 = __shfl_sync(0xffffffffu, acc[ni][2], s0l);
            float t11 = __shfl_sync(0xffffffffu, acc[ni][3], s0l);
            float u00 = __shfl_sync(0xffffffffu, acc[ni][0], s1l);
            float u01 = __shfl_sync(0xffffffffu, acc[ni][1], s1l);
            float u10 = __shfl_sync(0xffffffffu, acc[ni][2], s1l);
            float u11 = __shfl_sync(0xffffffffu, acc[ni][3], s1l);
            unsigned a[4];
            a[0] = fu(sel ? t01 : t00);
            a[1] = fu(sel ? t11 : t10);
            a[2] = fu(sel ? u01 : u00);
            a[3] = fu(sel ? u11 : u10);
            int jb = wn*128 + ni*8;
            #pragma unroll
            for (int dt = 0; dt < 4; dt++) {
                unsigned b[2] = { fu(Vs[(jb + lc)*36 + dt*8 + lr]),
                                  fu(Vs[(jb + 4 + lc)*36 + dt*8 + lr]) };
                mma_tf32(oc[dt], a, b);
            }
        }

        // ---- combine the two j-halves and store ----
        if (wn == 1) {
            #pragma unroll
            for (int dt = 0; dt < 4; dt++) {
                *(float2*)(obuf + arow*32 + dt*8 + lc*2)      = make_float2(oc[dt][0], oc[dt][1]);
                *(float2*)(obuf + (arow+8)*32 + dt*8 + lc*2)  = make_float2(oc[dt][2], oc[dt][3]);
            }
        }
        __syncthreads();
        if (wn == 0) {
            size_t ro0 = ((size_t)r*LDIM + i0 + arow) * CDIM + h*HDIM;
            size_t ro1 = ro0 + 8*CDIM;
            #pragma unroll
            for (int dt = 0; dt < 4; dt++) {
                float2 p0 = *(float2*)(obuf + arow*32 + dt*8 + lc*2);
                float2 p1 = *(float2*)(obuf + (arow+8)*32 + dt*8 + lc*2);
                *(float2*)(g_attn + ro0 + dt*8 + lc*2) = make_float2(oc[dt][0] + p0.x, oc[dt][1] + p0.y);
                *(float2*)(g_attn + ro1 + dt*8 + lc*2) = make_float2(oc[dt][2] + p1.x, oc[dt][3] + p1.y);
            }
        }
    }
}

// ============ kernel 3: (gate * attn) @ w_out + b_out (validated config) ============
#define GEMM_OUT_SMEM_FLOATS (64*APAD + 128*BPAD)
__global__ __launch_bounds__(256, 2) void gemm_out_kernel(
    const float* __restrict__ wout, const float* __restrict__ bout,
    float* __restrict__ out)
{
    extern __shared__ float sm[];
    float* As = sm;               // [64][APAD]
    float* Bs = sm + 64*APAD;     // [128][BPAD]
    int tid = threadIdx.x;
    int m0 = blockIdx.x * 64;

    #pragma unroll
    for (int it = 0; it < 8; it++) {
        int lin = tid + it*256;
        int r = lin >> 5, c4 = lin & 31;
        float4 gte = *(const float4*)(g_gate + (size_t)(m0 + r)*CDIM + c4*4);
        float4 att = *(const float4*)(g_attn + (size_t)(m0 + r)*CDIM + c4*4);
        float4 a;
        a.x = f2tff(gte.x * att.x); a.y = f2tff(gte.y * att.y);
        a.z = f2tff(gte.z * att.z); a.w = f2tff(gte.w * att.w);
        *(float4*)(As + r*APAD + c4*4) = a;
    }
    #pragma unroll
    for (int it = 0; it < 16; it++) {
        int lin = tid + it*256;
        int k = lin >> 5, c4 = lin & 31;
        float4 w = *(const float4*)(wout + (size_t)k*CDIM + c4*4);
        w.x = f2tff(w.x); w.y = f2tff(w.y); w.z = f2tff(w.z); w.w = f2tff(w.w);
        *(float4*)(Bs + k*BPAD + c4*4) = w;
    }
    __syncthreads();

    int warp = tid >> 5, lane = tid & 31;
    int lr = lane >> 2, lc = lane & 3;
    int wm = warp & 1, wn = warp >> 1;

    float acc[2][4][4];
    #pragma unroll
    for (int mi = 0; mi < 2; mi++)
        #pragma unroll
        for (int ni = 0; ni < 4; ni++)
            acc[mi][ni][0] = acc[mi][ni][1] = acc[mi][ni][2] = acc[mi][ni][3] = 0.f;

    #pragma unroll
    for (int ks = 0; ks < 16; ks++) {
        int k0 = ks * 8;
        unsigned a[2][4], bf[4][2];
        #pragma unroll
        for (int mi = 0; mi < 2; mi++) {
            int r = wm*32 + mi*16 + lr;
            a[mi][0] = fu(As[r*APAD + k0 + lc]);
            a[mi][1] = fu(As[(r+8)*APAD + k0 + lc]);
            a[mi][2] = fu(As[r*APAD + k0 + 4 + lc]);
            a[mi][3] = fu(As[(r+8)*APAD + k0 + 4 + lc]);
        }
        #pragma unroll
        for (int ni = 0; ni < 4; ni++) {
            int n = wn*32 + ni*8 + lr;
            bf[ni][0] = fu(Bs[(k0 + lc)*BPAD + n]);
            bf[ni][1] = fu(Bs[(k0 + 4 + lc)*BPAD + n]);
        }
        #pragma unroll
        for (int mi = 0; mi < 2; mi++)
            #pragma unroll
            for (int ni = 0; ni < 4; ni++)
                mma_tf32(acc[mi][ni], a[mi], bf[ni]);
    }

    #pragma unroll
    for (int mi = 0; mi < 2; mi++) {
        #pragma unroll
        for (int ni = 0; ni < 4; ni++) {
            int gr = m0 + wm*32 + mi*16 + lr;
            int cn = wn*32 + ni*8 + lc*2;
            float b0 = bout[cn], b1 = bout[cn+1];
            *(float2*)(out + (size_t)gr * CDIM + cn) =
                make_float2(acc[mi][ni][0] + b0, acc[mi][ni][1] + b1);
            *(float2*)(out + (size_t)(gr+8) * CDIM + cn) =
                make_float2(acc[mi][ni][2] + b0, acc[mi][ni][3] + b1);
        }
    }
}

// ---------------- launch ----------------
extern "C" void kernel_launch(void* const* d_in, const int* in_sizes, int n_in,
                              void* d_out, int out_size)
{
    (void)in_sizes; (void)n_in; (void)out_size;
    const float* z        = (const float*)d_in[0];
    const int*   src_mask = (const int*)  d_in[1];
    const float* ln_g     = (const float*)d_in[2];
    const float* ln_b     = (const float*)d_in[3];
    const float* w_qkv    = (const float*)d_in[4];
    const float* w_pair   = (const float*)d_in[5];
    const float* w_gate   = (const float*)d_in[6];
    const float* b_gate   = (const float*)d_in[7];
    const float* w_out    = (const float*)d_in[8];
    const float* b_out    = (const float*)d_in[9];
    float* out = (float*)d_out;

    const int qkv_smem  = GEMM_QKV_SMEM_FLOATS * 4;
    const int out_smem  = GEMM_OUT_SMEM_FLOATS * 4;
    const int attn_smem = ATTN_SMEM_FLOATS * 4;
    cudaFuncSetAttribute(gemm_qkv_gate,   cudaFuncAttributeMaxDynamicSharedMemorySize, qkv_smem);
    cudaFuncSetAttribute(attn_kernel,     cudaFuncAttributeMaxDynamicSharedMemorySize, attn_smem);
    cudaFuncSetAttribute(gemm_out_kernel, cudaFuncAttributeMaxDynamicSharedMemorySize, out_smem);

    gemm_qkv_gate<<<NROWS/64, 256, qkv_smem>>>(z, ln_g, ln_b, w_qkv, w_gate, b_gate, w_pair);
    attn_kernel<<<dim3(NH, LDIM, 2), 256, attn_smem>>>(src_mask);
    gemm_out_kernel<<<NROWS/64, 256, out_smem>>>(w_out, b_out, out);
}

// round 14
// speedup vs baseline: 1.0811x; 1.0183x over previous
#include <cuda_runtime.h>
#include <cstdint>

#define LDIM 256
#define CDIM 128
#define NH 4
#define HDIM 32
#define NROWS (LDIM*LDIM)        // 65536
#define QKVN 384
#define SQRT32 5.656854249492380f
#define APAD 140
#define BPAD 136

// ---------------- scratch ----------------
__device__ float g_qkv  [(size_t)NROWS * QKVN];
__device__ float g_gate [(size_t)NROWS * CDIM];
__device__ float g_biasT[(size_t)NH * NROWS];
__device__ float g_attn [(size_t)NROWS * CDIM];

// ---------------- helpers ----------------
__device__ __forceinline__ unsigned f2tf(float f) {
    unsigned r;
    asm("cvt.rna.tf32.f32 %0, %1;" : "=r"(r) : "f"(f));
    return r;
}
__device__ __forceinline__ float f2tff(float f) { return __uint_as_float(f2tf(f)); }
__device__ __forceinline__ unsigned fu(float f) { return __float_as_uint(f); }

__device__ __forceinline__ void mma_tf32(float c[4], const unsigned a[4], const unsigned b[2]) {
    asm volatile(
        "mma.sync.aligned.m16n8k8.row.col.f32.tf32.tf32.f32 "
        "{%0,%1,%2,%3},{%4,%5,%6,%7},{%8,%9},{%0,%1,%2,%3};"
        : "+f"(c[0]), "+f"(c[1]), "+f"(c[2]), "+f"(c[3])
        : "r"(a[0]), "r"(a[1]), "r"(a[2]), "r"(a[3]), "r"(b[0]), "r"(b[1]));
}

__device__ __forceinline__ void cp_async16(float* smem_dst, const float* gsrc) {
    unsigned s = (unsigned)__cvta_generic_to_shared(smem_dst);
    asm volatile("cp.async.cg.shared.global [%0], [%1], 16;" :: "r"(s), "l"(gsrc));
}
__device__ __forceinline__ void cp_commit() { asm volatile("cp.async.commit_group;"); }
template<int N> __device__ __forceinline__ void cp_wait() {
    asm volatile("cp.async.wait_group %0;" :: "n"(N));
}

// ============ kernel 1: fused LN + GEMM  zn @ [w_qkv | w_gate] (validated, unchanged) ============
#define GEMM_QKV_SMEM_FLOATS (64*APAD + 128*BPAD + 128 + 128 + 512)
__global__ __launch_bounds__(256, 2) void gemm_qkv_gate(
    const float* __restrict__ z, const float* __restrict__ lng, const float* __restrict__ lnb,
    const float* __restrict__ wqkv, const float* __restrict__ wgate,
    const float* __restrict__ bgate, const float* __restrict__ wpair)
{
    extern __shared__ float sm[];
    float* As  = sm;
    float* Bs  = sm + 64*APAD;
    float* gS  = Bs + 128*BPAD;
    float* bS  = gS + 128;
    float* wpS = bS + 128;

    int tid = threadIdx.x;
    int m0 = blockIdx.x * 64;

    #pragma unroll
    for (int it = 0; it < 8; it++) {
        int lin = tid + it*256;
        int r = lin >> 5, c4 = lin & 31;
        *(float4*)(As + r*APAD + c4*4) =
            *(const float4*)(z + (size_t)(m0 + r)*CDIM + c4*4);
    }
    #pragma unroll
    for (int it = 0; it < 16; it++) {
        int lin = tid + it*256;
        int k = lin >> 5, c4 = lin & 31;
        float4 w = *(const float4*)(wqkv + (size_t)k*QKVN + c4*4);
        w.x = f2tff(w.x * SQRT32); w.y = f2tff(w.y * SQRT32);
        w.z = f2tff(w.z * SQRT32); w.w = f2tff(w.w * SQRT32);
        *(float4*)(Bs + k*BPAD + c4*4) = w;
    }
    if (tid < 128) { gS[tid] = lng[tid]; bS[tid] = lnb[tid]; }
    wpS[tid] = wpair[tid];
    wpS[tid + 256] = wpair[tid + 256];
    __syncthreads();

    {
        int row = tid >> 2, quad = tid & 3;
        float* Ar = As + row*APAD + quad*4;
        float v[32];
        float s = 0.f, ss = 0.f;
        #pragma unroll
        for (int k = 0; k < 8; k++) {
            float4 t = *(float4*)(Ar + k*16);
            v[k*4] = t.x; v[k*4+1] = t.y; v[k*4+2] = t.z; v[k*4+3] = t.w;
            s  += t.x + t.y + t.z + t.w;
            ss += t.x*t.x + t.y*t.y + t.z*t.z + t.w*t.w;
        }
        s  += __shfl_xor_sync(0xffffffffu, s, 1);  s  += __shfl_xor_sync(0xffffffffu, s, 2);
        ss += __shfl_xor_sync(0xffffffffu, ss, 1); ss += __shfl_xor_sync(0xffffffffu, ss, 2);
        float mu  = s * (1.0f / CDIM);
        float var = ss * (1.0f / CDIM) - mu * mu;
        float rstd = rsqrtf(var + 1e-5f);

        float bh0 = 0.f, bh1 = 0.f, bh2 = 0.f, bh3 = 0.f;
        #pragma unroll
        for (int k = 0; k < 8; k++) {
            float4 o;
            float* ov = &o.x;
            #pragma unroll
            for (int j = 0; j < 4; j++) {
                int c = quad*4 + k*16 + j;
                float zn = (v[k*4+j] - mu) * rstd * gS[c] + bS[c];
                bh0 += zn * wpS[c*4];   bh1 += zn * wpS[c*4+1];
                bh2 += zn * wpS[c*4+2]; bh3 += zn * wpS[c*4+3];
                ov[j] = f2tff(zn);
            }
            *(float4*)(Ar + k*16) = o;
        }
        bh0 += __shfl_xor_sync(0xffffffffu, bh0, 1); bh0 += __shfl_xor_sync(0xffffffffu, bh0, 2);
        bh1 += __shfl_xor_sync(0xffffffffu, bh1, 1); bh1 += __shfl_xor_sync(0xffffffffu, bh1, 2);
        bh2 += __shfl_xor_sync(0xffffffffu, bh2, 1); bh2 += __shfl_xor_sync(0xffffffffu, bh2, 2);
        bh3 += __shfl_xor_sync(0xffffffffu, bh3, 1); bh3 += __shfl_xor_sync(0xffffffffu, bh3, 2);
        if (quad == 0) {
            g_biasT[(size_t)0*NROWS + m0 + row] = bh0;
            g_biasT[(size_t)1*NROWS + m0 + row] = bh1;
            g_biasT[(size_t)2*NROWS + m0 + row] = bh2;
            g_biasT[(size_t)3*NROWS + m0 + row] = bh3;
        }
    }
    __syncthreads();

    int warp = tid >> 5, lane = tid & 31;
    int lr = lane >> 2, lc = lane & 3;
    int wm = warp & 1, wn = warp >> 1;

    #pragma unroll
    for (int nt = 0; nt < 4; nt++) {
        float acc[2][4][4];
        #pragma unroll
        for (int mi = 0; mi < 2; mi++)
            #pragma unroll
            for (int ni = 0; ni < 4; ni++)
                acc[mi][ni][0] = acc[mi][ni][1] = acc[mi][ni][2] = acc[mi][ni][3] = 0.f;

        #pragma unroll
        for (int ks = 0; ks < 16; ks++) {
            int k0 = ks * 8;
            unsigned a[2][4], bf[4][2];
            #pragma unroll
            for (int mi = 0; mi < 2; mi++) {
                int r = wm*32 + mi*16 + lr;
                a[mi][0] = fu(As[r*APAD + k0 + lc]);
                a[mi][1] = fu(As[(r+8)*APAD + k0 + lc]);
                a[mi][2] = fu(As[r*APAD + k0 + 4 + lc]);
                a[mi][3] = fu(As[(r+8)*APAD + k0 + 4 + lc]);
            }
            #pragma unroll
            for (int ni = 0; ni < 4; ni++) {
                int n = wn*32 + ni*8 + lr;
                bf[ni][0] = fu(Bs[(k0 + lc)*BPAD + n]);
                bf[ni][1] = fu(Bs[(k0 + 4 + lc)*BPAD + n]);
            }
            #pragma unroll
            for (int mi = 0; mi < 2; mi++)
                #pragma unroll
                for (int ni = 0; ni < 4; ni++)
                    mma_tf32(acc[mi][ni], a[mi], bf[ni]);
        }

        #pragma unroll
        for (int mi = 0; mi < 2; mi++) {
            #pragma unroll
            for (int ni = 0; ni < 4; ni++) {
                int gr = m0 + wm*32 + mi*16 + lr;
                int cn = wn*32 + ni*8 + lc*2;
                if (nt < 3) {
                    int gc = nt*128 + cn;
                    *(float2*)(g_qkv + (size_t)gr * QKVN + gc) =
                        make_float2(f2tff(acc[mi][ni][0]), f2tff(acc[mi][ni][1]));
                    *(float2*)(g_qkv + (size_t)(gr+8) * QKVN + gc) =
                        make_float2(f2tff(acc[mi][ni][2]), f2tff(acc[mi][ni][3]));
                } else {
                    float b0 = bgate[cn], b1 = bgate[cn+1];
                    *(float2*)(g_gate + (size_t)gr * CDIM + cn) =
                        make_float2(1.f/(1.f + __expf(-(acc[mi][ni][0] + b0))),
                                    1.f/(1.f + __expf(-(acc[mi][ni][1] + b1))));
                    *(float2*)(g_gate + (size_t)(gr+8) * CDIM + cn) =
                        make_float2(1.f/(1.f + __expf(-(acc[mi][ni][2] + b0))),
                                    1.f/(1.f + __expf(-(acc[mi][ni][3] + b1))));
                }
            }
        }

        if (nt < 3) {
            __syncthreads();
            #pragma unroll
            for (int it = 0; it < 16; it++) {
                int lin = tid + it*256;
                int k = lin >> 5, c4 = lin & 31;
                float4 w;
                if (nt + 1 < 3) w = *(const float4*)(wqkv + (size_t)k*QKVN + (nt+1)*128 + c4*4);
                else            w = *(const float4*)(wgate + (size_t)k*CDIM + c4*4);
                w.x = f2tff(w.x); w.y = f2tff(w.y); w.z = f2tff(w.z); w.w = f2tff(w.w);
                *(float4*)(Bs + k*BPAD + c4*4) = w;
            }
            __syncthreads();
        }
    }
}

// ============ kernel 2: attention per (h, r, zh) — 32x64 warp tiles, 4-way j split ============
// 8 warps: wm = warp&1 (32-row strip of 64-chunk), wn = warp>>1 (j quarter of 64).
#define ATTN_SMEM_FLOATS (256*36*2 + 64*36 + 256 + 2*64*36 + 256)
__global__ __launch_bounds__(256, 2) void attn_kernel(const int* __restrict__ src_mask)
{
    extern __shared__ float sm[];
    float* Ks     = sm;                 // [256][36]
    float* Vs     = Ks + 256*36;        // [256][36]
    float* Qs     = Vs + 256*36;        // [64][36]
    float* redsum = Qs + 64*36;         // [4][64]
    float* obuf0  = redsum + 256;       // [64][36]
    float* obuf1  = obuf0 + 64*36;      // [64][36]
    float* msk    = obuf1 + 64*36;      // [256]

    int h = blockIdx.x, r = blockIdx.y, zh = blockIdx.z;
    int tid = threadIdx.x;
    const float* base = g_qkv + (size_t)r * LDIM * QKVN;

    #pragma unroll
    for (int p = 0; p < 8; p++) {
        int lin = tid + p*256;
        int j = lin >> 3, d4 = lin & 7;
        cp_async16(Ks + j*36 + d4*4, base + (size_t)j*QKVN + 128 + h*HDIM + d4*4);
        cp_async16(Vs + j*36 + d4*4, base + (size_t)j*QKVN + 256 + h*HDIM + d4*4);
    }
    cp_commit();
    msk[tid] = (src_mask[tid] == 0) ? -1.f : 1.f;

    int warp = tid >> 5, lane = tid & 31;
    int lr = lane >> 2, lc = lane & 3;
    int wm = warp & 1, wn = warp >> 1;       // wm: 2 strips, wn: 4 quarters
    const float* biasH = g_biasT + (size_t)h * NROWS;

    int s0l = (lane & ~3) | (lc >> 1);
    int s1l = s0l + 2;
    int sel = lc & 1;

    for (int icl = 0; icl < 2; icl++) {
        int ic = zh*2 + icl;
        int i0 = ic * 64;
        if (icl) __syncthreads();
        #pragma unroll
        for (int p = 0; p < 2; p++) {
            int lin = tid + p*256;
            int row = lin >> 3, d4 = lin & 7;
            cp_async16(Qs + row*36 + d4*4, base + (size_t)(i0 + row)*QKVN + h*HDIM + d4*4);
        }
        cp_commit();
        cp_wait<0>();
        __syncthreads();

        // ---- QK^T: warp covers rows [wm*32, +32), cols [wn*64, +64) ----
        float acc[2][8][4];
        #pragma unroll
        for (int mi = 0; mi < 2; mi++)
            #pragma unroll
            for (int ni = 0; ni < 8; ni++)
                acc[mi][ni][0] = acc[mi][ni][1] = acc[mi][ni][2] = acc[mi][ni][3] = 0.f;

        #pragma unroll
        for (int ks = 0; ks < 4; ks++) {
            int k0 = ks * 8;
            unsigned a[2][4];
            #pragma unroll
            for (int mi = 0; mi < 2; mi++) {
                int rrow = wm*32 + mi*16 + lr;
                a[mi][0] = fu(Qs[rrow*36 + k0 + lc]);
                a[mi][1] = fu(Qs[(rrow+8)*36 + k0 + lc]);
                a[mi][2] = fu(Qs[rrow*36 + k0 + 4 + lc]);
                a[mi][3] = fu(Qs[(rrow+8)*36 + k0 + 4 + lc]);
            }
            #pragma unroll
            for (int ni = 0; ni < 8; ni++) {
                int j = wn*64 + ni*8 + lr;
                unsigned b[2] = { fu(Ks[j*36 + k0 + lc]), fu(Ks[j*36 + k0 + 4 + lc]) };
                mma_tf32(acc[0][ni], a[0], b);
                mma_tf32(acc[1][ni], a[1], b);
            }
        }

        // ---- bias + mask + direct exp + local sums (per mi) ----
        float smv[2][2] = {{0.f,0.f},{0.f,0.f}};
        #pragma unroll
        for (int mi = 0; mi < 2; mi++) {
            int rl = wm*32 + mi*16 + lr;
            float mi0 = msk[i0 + rl], mi1 = msk[i0 + rl + 8];
            const float* bp0 = biasH + (size_t)(i0 + rl) * LDIM;
            const float* bp1 = bp0 + 8 * LDIM;
            #pragma unroll
            for (int ni = 0; ni < 8; ni++) {
                int j = wn*64 + ni*8 + lc*2;
                float2 b0 = *(const float2*)(bp0 + j);
                float2 b1 = *(const float2*)(bp1 + j);
                float mj0 = msk[j], mj1 = msk[j+1];
                float v0 = acc[mi][ni][0] + b0.x;
                float v1 = acc[mi][ni][1] + b0.y;
                float v2 = acc[mi][ni][2] + b1.x;
                float v3 = acc[mi][ni][3] + b1.y;
                if (mi0*mj0 < 0.f) v0 = -1e-9f;
                if (mi0*mj1 < 0.f) v1 = -1e-9f;
                if (mi1*mj0 < 0.f) v2 = -1e-9f;
                if (mi1*mj1 < 0.f) v3 = -1e-9f;
                float e0 = __expf(v0), e1 = __expf(v1);
                float e2 = __expf(v2), e3 = __expf(v3);
                acc[mi][ni][0] = e0; acc[mi][ni][1] = e1;
                acc[mi][ni][2] = e2; acc[mi][ni][3] = e3;
                smv[mi][0] += e0 + e1; smv[mi][1] += e2 + e3;
            }
        }
        #pragma unroll
        for (int mi = 0; mi < 2; mi++) {
            smv[mi][0] += __shfl_xor_sync(0xffffffffu, smv[mi][0], 1);
            smv[mi][0] += __shfl_xor_sync(0xffffffffu, smv[mi][0], 2);
            smv[mi][1] += __shfl_xor_sync(0xffffffffu, smv[mi][1], 1);
            smv[mi][1] += __shfl_xor_sync(0xffffffffu, smv[mi][1], 2);
        }
        if (lc == 0) {
            #pragma unroll
            for (int mi = 0; mi < 2; mi++) {
                int rl = wm*32 + mi*16 + lr;
                redsum[wn*64 + rl]     = smv[mi][0];
                redsum[wn*64 + rl + 8] = smv[mi][1];
            }
        }
        __syncthreads();
        float inv[2][2];
        #pragma unroll
        for (int mi = 0; mi < 2; mi++) {
            int rl = wm*32 + mi*16 + lr;
            inv[mi][0] = 1.f / (redsum[rl] + redsum[64 + rl] + redsum[128 + rl] + redsum[192 + rl]);
            int rl8 = rl + 8;
            inv[mi][1] = 1.f / (redsum[rl8] + redsum[64 + rl8] + redsum[128 + rl8] + redsum[192 + rl8]);
        }
        #pragma unroll
        for (int mi = 0; mi < 2; mi++)
            #pragma unroll
            for (int ni = 0; ni < 8; ni++) {
                acc[mi][ni][0] = f2tff(acc[mi][ni][0] * inv[mi][0]);
                acc[mi][ni][1] = f2tff(acc[mi][ni][1] * inv[mi][0]);
                acc[mi][ni][2] = f2tff(acc[mi][ni][2] * inv[mi][1]);
                acc[mi][ni][3] = f2tff(acc[mi][ni][3] * inv[mi][1]);
            }

        // ---- P @ V over this warp's 64 j (8 k-steps); Vs b-frags shared across mi ----
        float oc[2][4][4];
        #pragma unroll
        for (int mi = 0; mi < 2; mi++)
            #pragma unroll
            for (int dt = 0; dt < 4; dt++)
                oc[mi][dt][0] = oc[mi][dt][1] = oc[mi][dt][2] = oc[mi][dt][3] = 0.f;

        #pragma unroll
        for (int ni = 0; ni < 8; ni++) {
            unsigned aP[2][4];
            #pragma unroll
            for (int mi = 0; mi < 2; mi++) {
                float t00 = __shfl_sync(0xffffffffu, acc[mi][ni][0], s0l);
                float t01 = __shfl_sync(0xffffffffu, acc[mi][ni][1], s0l);
                float t10 = __shfl_sync(0xffffffffu, acc[mi][ni][2], s0l);
                float t11 = __shfl_sync(0xffffffffu, acc[mi][ni][3], s0l);
                float u00 = __shfl_sync(0xffffffffu, acc[mi][ni][0], s1l);
                float u01 = __shfl_sync(0xffffffffu, acc[mi][ni][1], s1l);
                float u10 = __shfl_sync(0xffffffffu, acc[mi][ni][2], s1l);
                float u11 = __shfl_sync(0xffffffffu, acc[mi][ni][3], s1l);
                aP[mi][0] = fu(sel ? t01 : t00);
                aP[mi][1] = fu(sel ? t11 : t10);
                aP[mi][2] = fu(sel ? u01 : u00);
                aP[mi][3] = fu(sel ? u11 : u10);
            }
            int jb = wn*64 + ni*8;
            #pragma unroll
            for (int dt = 0; dt < 4; dt++) {
                unsigned b[2] = { fu(Vs[(jb + lc)*36 + dt*8 + lr]),
                                  fu(Vs[(jb + 4 + lc)*36 + dt*8 + lr]) };
                mma_tf32(oc[0][dt], aP[0], b);
                mma_tf32(oc[1][dt], aP[1], b);
            }
        }

        // ---- 4-way combine via obuf0/obuf1 (2 stages) ----
        if (wn == 1 || wn == 3) {
            float* ob = (wn == 1) ? obuf0 : obuf1;
            #pragma unroll
            for (int mi = 0; mi < 2; mi++) {
                int rl = wm*32 + mi*16 + lr;
                #pragma unroll
                for (int dt = 0; dt < 4; dt++) {
                    *(float2*)(ob + rl*36 + dt*8 + lc*2)     = make_float2(oc[mi][dt][0], oc[mi][dt][1]);
                    *(float2*)(ob + (rl+8)*36 + dt*8 + lc*2) = make_float2(oc[mi][dt][2], oc[mi][dt][3]);
                }
            }
        }
        __syncthreads();
        if (wn == 0 || wn == 2) {
            float* ob = (wn == 0) ? obuf0 : obuf1;
            #pragma unroll
            for (int mi = 0; mi < 2; mi++) {
                int rl = wm*32 + mi*16 + lr;
                #pragma unroll
                for (int dt = 0; dt < 4; dt++) {
                    float2 p0 = *(float2*)(ob + rl*36 + dt*8 + lc*2);
                    float2 p1 = *(float2*)(ob + (rl+8)*36 + dt*8 + lc*2);
                    oc[mi][dt][0] += p0.x; oc[mi][dt][1] += p0.y;
                    oc[mi][dt][2] += p1.x; oc[mi][dt][3] += p1.y;
                }
            }
        }
        if (wn == 2) {   // write half-sum (wn2+wn3) back to obuf1 (same addrs this thread read)
            #pragma unroll
            for (int mi = 0; mi < 2; mi++) {
                int rl = wm*32 + mi*16 + lr;
                #pragma unroll
                for (int dt = 0; dt < 4; dt++) {
                    *(float2*)(obuf1 + rl*36 + dt*8 + lc*2)     = make_float2(oc[mi][dt][0], oc[mi][dt][1]);
                    *(float2*)(obuf1 + (rl+8)*36 + dt*8 + lc*2) = make_float2(oc[mi][dt][2], oc[mi][dt][3]);
                }
            }
        }
        __syncthreads();
        if (wn == 0) {   // final: (wn0+wn1) + (wn2+wn3), store
            #pragma unroll
            for (int mi = 0; mi < 2; mi++) {
                int rl = wm*32 + mi*16 + lr;
                size_t ro0 = ((size_t)r*LDIM + i0 + rl) * CDIM + h*HDIM;
                size_t ro1 = ro0 + 8*CDIM;
                #pragma unroll
                for (int dt = 0; dt < 4; dt++) {
                    float2 p0 = *(float2*)(obuf1 + rl*36 + dt*8 + lc*2);
                    float2 p1 = *(float2*)(obuf1 + (rl+8)*36 + dt*8 + lc*2);
                    *(float2*)(g_attn + ro0 + dt*8 + lc*2) =
                        make_float2(oc[mi][dt][0] + p0.x, oc[mi][dt][1] + p0.y);
                    *(float2*)(g_attn + ro1 + dt*8 + lc*2) =
                        make_float2(oc[mi][dt][2] + p1.x, oc[mi][dt][3] + p1.y);
                }
            }
        }
    }
}

// ============ kernel 3: (gate * attn) @ w_out + b_out (validated, unchanged) ============
#define GEMM_OUT_SMEM_FLOATS (64*APAD + 128*BPAD)
__global__ __launch_bounds__(256, 2) void gemm_out_kernel(
    const float* __restrict__ wout, const float* __restrict__ bout,
    float* __restrict__ out)
{
    extern __shared__ float sm[];
    float* As = sm;
    float* Bs = sm + 64*APAD;
    int tid = threadIdx.x;
    int m0 = blockIdx.x * 64;

    #pragma unroll
    for (int it = 0; it < 8; it++) {
        int lin = tid + it*256;
        int r = lin >> 5, c4 = lin & 31;
        float4 gte = *(const float4*)(g_gate + (size_t)(m0 + r)*CDIM + c4*4);
        float4 att = *(const float4*)(g_attn + (size_t)(m0 + r)*CDIM + c4*4);
        float4 a;
        a.x = f2tff(gte.x * att.x); a.y = f2tff(gte.y * att.y);
        a.z = f2tff(gte.z * att.z); a.w = f2tff(gte.w * att.w);
        *(float4*)(As + r*APAD + c4*4) = a;
    }
    #pragma unroll
    for (int it = 0; it < 16; it++) {
        int lin = tid + it*256;
        int k = lin >> 5, c4 = lin & 31;
        float4 w = *(const float4*)(wout + (size_t)k*CDIM + c4*4);
        w.x = f2tff(w.x); w.y = f2tff(w.y); w.z = f2tff(w.z); w.w = f2tff(w.w);
        *(float4*)(Bs + k*BPAD + c4*4) = w;
    }
    __syncthreads();

    int warp = tid >> 5, lane = tid & 31;
    int lr = lane >> 2, lc = lane & 3;
    int wm = warp & 1, wn = warp >> 1;

    float acc[2][4][4];
    #pragma unroll
    for (int mi = 0; mi < 2; mi++)
        #pragma unroll
        for (int ni = 0; ni < 4; ni++)
            acc[mi][ni][0] = acc[mi][ni][1] = acc[mi][ni][2] = acc[mi][ni][3] = 0.f;

    #pragma unroll
    for (int ks = 0; ks < 16; ks++) {
        int k0 = ks * 8;
        unsigned a[2][4], bf[4][2];
        #pragma unroll
        for (int mi = 0; mi < 2; mi++) {
            int r = wm*32 + mi*16 + lr;
            a[mi][0] = fu(As[r*APAD + k0 + lc]);
            a[mi][1] = fu(As[(r+8)*APAD + k0 + lc]);
            a[mi][2] = fu(As[r*APAD + k0 + 4 + lc]);
            a[mi][3] = fu(As[(r+8)*APAD + k0 + 4 + lc]);
        }
        #pragma unroll
        for (int ni = 0; ni < 4; ni++) {
            int n = wn*32 + ni*8 + lr;
            bf[ni][0] = fu(Bs[(k0 + lc)*BPAD + n]);
            bf[ni][1] = fu(Bs[(k0 + 4 + lc)*BPAD + n]);
        }
        #pragma unroll
        for (int mi = 0; mi < 2; mi++)
            #pragma unroll
            for (int ni = 0; ni < 4; ni++)
                mma_tf32(acc[mi][ni], a[mi], bf[ni]);
    }

    #pragma unroll
    for (int mi = 0; mi < 2; mi++) {
        #pragma unroll
        for (int ni = 0; ni < 4; ni++) {
            int gr = m0 + wm*32 + mi*16 + lr;
            int cn = wn*32 + ni*8 + lc*2;
            float b0 = bout[cn], b1 = bout[cn+1];
            *(float2*)(out + (size_t)gr * CDIM + cn) =
                make_float2(acc[mi][ni][0] + b0, acc[mi][ni][1] + b1);
            *(float2*)(out + (size_t)(gr+8) * CDIM + cn) =
                make_float2(acc[mi][ni][2] + b0, acc[mi][ni][3] + b1);
        }
    }
}

// ---------------- launch ----------------
extern "C" void kernel_launch(void* const* d_in, const int* in_sizes, int n_in,
                              void* d_out, int out_size)
{
    (void)in_sizes; (void)n_in; (void)out_size;
    const float* z        = (const float*)d_in[0];
    const int*   src_mask = (const int*)  d_in[1];
    const float* ln_g     = (const float*)d_in[2];
    const float* ln_b     = (const float*)d_in[3];
    const float* w_qkv    = (const float*)d_in[4];
    const float* w_pair   = (const float*)d_in[5];
    const float* w_gate   = (const float*)d_in[6];
    const float* b_gate   = (const float*)d_in[7];
    const float* w_out    = (const float*)d_in[8];
    const float* b_out    = (const float*)d_in[9];
    float* out = (float*)d_out;

    const int qkv_smem  = GEMM_QKV_SMEM_FLOATS * 4;
    const int out_smem  = GEMM_OUT_SMEM_FLOATS * 4;
    const int attn_smem = ATTN_SMEM_FLOATS * 4;    // ~103 KB
    cudaFuncSetAttribute(gemm_qkv_gate,   cudaFuncAttributeMaxDynamicSharedMemorySize, qkv_smem);
    cudaFuncSetAttribute(attn_kernel,     cudaFuncAttributeMaxDynamicSharedMemorySize, attn_smem);
    cudaFuncSetAttribute(gemm_out_kernel, cudaFuncAttributeMaxDynamicSharedMemorySize, out_smem);

    gemm_qkv_gate<<<NROWS/64, 256, qkv_smem>>>(z, ln_g, ln_b, w_qkv, w_gate, b_gate, w_pair);
    attn_kernel<<<dim3(NH, LDIM, 2), 256, attn_smem>>>(src_mask);
    gemm_out_kernel<<<NROWS/64, 256, out_smem>>>(w_out, b_out, out);
}

// round 15
// speedup vs baseline: 1.1496x; 1.0633x over previous
#include <cuda_runtime.h>
#include <cstdint>

#define LDIM 256
#define CDIM 128
#define NH 4
#define HDIM 32
#define NROWS (LDIM*LDIM)        // 65536
#define QKVN 384
#define SQRT32 5.656854249492380f
#define APAD 140
#define BPAD 136

// ---------------- scratch ----------------
__device__ float g_qkv  [(size_t)NROWS * QKVN];
__device__ float g_gate [(size_t)NROWS * CDIM];
__device__ float g_biasT[(size_t)NH * NROWS];
__device__ float g_attn [(size_t)NROWS * CDIM];
__device__ float g_wtf  [4 * 128 * 128];     // pre-converted [slab][k][n]: q*sqrt32, k, v, gate
__device__ float g_wouttf[128 * 128];        // pre-converted w_out

// ---------------- helpers ----------------
__device__ __forceinline__ unsigned f2tf(float f) {
    unsigned r;
    asm("cvt.rna.tf32.f32 %0, %1;" : "=r"(r) : "f"(f));
    return r;
}
__device__ __forceinline__ float f2tff(float f) { return __uint_as_float(f2tf(f)); }
__device__ __forceinline__ unsigned fu(float f) { return __float_as_uint(f); }

__device__ __forceinline__ void mma_tf32(float c[4], const unsigned a[4], const unsigned b[2]) {
    asm volatile(
        "mma.sync.aligned.m16n8k8.row.col.f32.tf32.tf32.f32 "
        "{%0,%1,%2,%3},{%4,%5,%6,%7},{%8,%9},{%0,%1,%2,%3};"
        : "+f"(c[0]), "+f"(c[1]), "+f"(c[2]), "+f"(c[3])
        : "r"(a[0]), "r"(a[1]), "r"(a[2]), "r"(a[3]), "r"(b[0]), "r"(b[1]));
}

__device__ __forceinline__ void cp_async16(float* smem_dst, const float* gsrc) {
    unsigned s = (unsigned)__cvta_generic_to_shared(smem_dst);
    asm volatile("cp.async.cg.shared.global [%0], [%1], 16;" :: "r"(s), "l"(gsrc));
}
__device__ __forceinline__ void cp_commit() { asm volatile("cp.async.commit_group;"); }
template<int N> __device__ __forceinline__ void cp_wait() {
    asm volatile("cp.async.wait_group %0;" :: "n"(N));
}

// ============ kernel 0: one-time weight conversion ============
__global__ __launch_bounds__(256) void prep_weights(
    const float* __restrict__ wqkv, const float* __restrict__ wgate,
    const float* __restrict__ wout)
{
    int idx4 = (blockIdx.x * 256 + threadIdx.x) * 4;   // grid 80 -> 81920 floats
    if (idx4 < 4*128*128) {
        int nt = idx4 >> 14, wi = idx4 & 16383, k = wi >> 7, n = wi & 127;
        float4 w;
        if (nt < 3) w = *(const float4*)(wqkv + (size_t)k*QKVN + nt*128 + n);
        else        w = *(const float4*)(wgate + (size_t)k*CDIM + n);
        if (nt == 0) { w.x *= SQRT32; w.y *= SQRT32; w.z *= SQRT32; w.w *= SQRT32; }
        w.x = f2tff(w.x); w.y = f2tff(w.y); w.z = f2tff(w.z); w.w = f2tff(w.w);
        *(float4*)(g_wtf + idx4) = w;
    } else {
        int j = idx4 - 4*128*128;
        float4 w = *(const float4*)(wout + j);
        w.x = f2tff(w.x); w.y = f2tff(w.y); w.z = f2tff(w.z); w.w = f2tff(w.w);
        *(float4*)(g_wouttf + j) = w;
    }
}

// ============ kernel 1: fused LN + GEMM  zn @ [w_qkv | w_gate], cp.async staging ============
#define GEMM_QKV_SMEM_FLOATS (64*APAD + 128*BPAD + 128 + 128 + 512)
__global__ __launch_bounds__(256, 2) void gemm_qkv_gate(
    const float* __restrict__ z, const float* __restrict__ lng, const float* __restrict__ lnb,
    const float* __restrict__ bgate, const float* __restrict__ wpair)
{
    extern __shared__ float sm[];
    float* As  = sm;                    // [64][APAD]
    float* Bs  = sm + 64*APAD;          // [128][BPAD] (k, n)
    float* gS  = Bs + 128*BPAD;         // 128
    float* bS  = gS + 128;              // 128
    float* wpS = bS + 128;              // 512

    int tid = threadIdx.x;
    int m0 = blockIdx.x * 64;

    // ---- stage z tile + W slab 0 via cp.async ----
    #pragma unroll
    for (int it = 0; it < 8; it++) {
        int lin = tid + it*256;
        int r = lin >> 5, c4 = lin & 31;
        cp_async16(As + r*APAD + c4*4, z + (size_t)(m0 + r)*CDIM + c4*4);
    }
    #pragma unroll
    for (int it = 0; it < 16; it++) {
        int lin = tid + it*256;
        int k = lin >> 5, c4 = lin & 31;
        cp_async16(Bs + k*BPAD + c4*4, g_wtf + k*128 + c4*4);
    }
    cp_commit();
    if (tid < 128) { gS[tid] = lng[tid]; bS[tid] = lnb[tid]; }
    wpS[tid] = wpair[tid];
    wpS[tid + 256] = wpair[tid + 256];
    cp_wait<0>();
    __syncthreads();

    // ---- LayerNorm in place (once) ----
    {
        int row = tid >> 2, quad = tid & 3;
        float* Ar = As + row*APAD + quad*4;
        float v[32];
        float s = 0.f, ss = 0.f;
        #pragma unroll
        for (int k = 0; k < 8; k++) {
            float4 t = *(float4*)(Ar + k*16);
            v[k*4] = t.x; v[k*4+1] = t.y; v[k*4+2] = t.z; v[k*4+3] = t.w;
            s  += t.x + t.y + t.z + t.w;
            ss += t.x*t.x + t.y*t.y + t.z*t.z + t.w*t.w;
        }
        s  += __shfl_xor_sync(0xffffffffu, s, 1);  s  += __shfl_xor_sync(0xffffffffu, s, 2);
        ss += __shfl_xor_sync(0xffffffffu, ss, 1); ss += __shfl_xor_sync(0xffffffffu, ss, 2);
        float mu  = s * (1.0f / CDIM);
        float var = ss * (1.0f / CDIM) - mu * mu;
        float rstd = rsqrtf(var + 1e-5f);

        float bh0 = 0.f, bh1 = 0.f, bh2 = 0.f, bh3 = 0.f;
        #pragma unroll
        for (int k = 0; k < 8; k++) {
            float4 o;
            float* ov = &o.x;
            #pragma unroll
            for (int j = 0; j < 4; j++) {
                int c = quad*4 + k*16 + j;
                float zn = (v[k*4+j] - mu) * rstd * gS[c] + bS[c];
                bh0 += zn * wpS[c*4];   bh1 += zn * wpS[c*4+1];
                bh2 += zn * wpS[c*4+2]; bh3 += zn * wpS[c*4+3];
                ov[j] = f2tff(zn);
            }
            *(float4*)(Ar + k*16) = o;
        }
        bh0 += __shfl_xor_sync(0xffffffffu, bh0, 1); bh0 += __shfl_xor_sync(0xffffffffu, bh0, 2);
        bh1 += __shfl_xor_sync(0xffffffffu, bh1, 1); bh1 += __shfl_xor_sync(0xffffffffu, bh1, 2);
        bh2 += __shfl_xor_sync(0xffffffffu, bh2, 1); bh2 += __shfl_xor_sync(0xffffffffu, bh2, 2);
        bh3 += __shfl_xor_sync(0xffffffffu, bh3, 1); bh3 += __shfl_xor_sync(0xffffffffu, bh3, 2);
        if (quad == 0) {
            g_biasT[(size_t)0*NROWS + m0 + row] = bh0;
            g_biasT[(size_t)1*NROWS + m0 + row] = bh1;
            g_biasT[(size_t)2*NROWS + m0 + row] = bh2;
            g_biasT[(size_t)3*NROWS + m0 + row] = bh3;
        }
    }
    __syncthreads();

    int warp = tid >> 5, lane = tid & 31;
    int lr = lane >> 2, lc = lane & 3;
    int wm = warp & 1, wn = warp >> 1;

    #pragma unroll
    for (int nt = 0; nt < 4; nt++) {
        float acc[2][4][4];
        #pragma unroll
        for (int mi = 0; mi < 2; mi++)
            #pragma unroll
            for (int ni = 0; ni < 4; ni++)
                acc[mi][ni][0] = acc[mi][ni][1] = acc[mi][ni][2] = acc[mi][ni][3] = 0.f;

        #pragma unroll
        for (int ks = 0; ks < 16; ks++) {
            int k0 = ks * 8;
            unsigned a[2][4], bf[4][2];
            #pragma unroll
            for (int mi = 0; mi < 2; mi++) {
                int r = wm*32 + mi*16 + lr;
                a[mi][0] = fu(As[r*APAD + k0 + lc]);
                a[mi][1] = fu(As[(r+8)*APAD + k0 + lc]);
                a[mi][2] = fu(As[r*APAD + k0 + 4 + lc]);
                a[mi][3] = fu(As[(r+8)*APAD + k0 + 4 + lc]);
            }
            #pragma unroll
            for (int ni = 0; ni < 4; ni++) {
                int n = wn*32 + ni*8 + lr;
                bf[ni][0] = fu(Bs[(k0 + lc)*BPAD + n]);
                bf[ni][1] = fu(Bs[(k0 + 4 + lc)*BPAD + n]);
            }
            #pragma unroll
            for (int mi = 0; mi < 2; mi++)
                #pragma unroll
                for (int ni = 0; ni < 4; ni++)
                    mma_tf32(acc[mi][ni], a[mi], bf[ni]);
        }

        #pragma unroll
        for (int mi = 0; mi < 2; mi++) {
            #pragma unroll
            for (int ni = 0; ni < 4; ni++) {
                int gr = m0 + wm*32 + mi*16 + lr;
                int cn = wn*32 + ni*8 + lc*2;
                if (nt < 3) {
                    int gc = nt*128 + cn;
                    *(float2*)(g_qkv + (size_t)gr * QKVN + gc) =
                        make_float2(f2tff(acc[mi][ni][0]), f2tff(acc[mi][ni][1]));
                    *(float2*)(g_qkv + (size_t)(gr+8) * QKVN + gc) =
                        make_float2(f2tff(acc[mi][ni][2]), f2tff(acc[mi][ni][3]));
                } else {
                    float b0 = bgate[cn], b1 = bgate[cn+1];
                    *(float2*)(g_gate + (size_t)gr * CDIM + cn) =
                        make_float2(1.f/(1.f + __expf(-(acc[mi][ni][0] + b0))),
                                    1.f/(1.f + __expf(-(acc[mi][ni][1] + b1))));
                    *(float2*)(g_gate + (size_t)(gr+8) * CDIM + cn) =
                        make_float2(1.f/(1.f + __expf(-(acc[mi][ni][2] + b0))),
                                    1.f/(1.f + __expf(-(acc[mi][ni][3] + b1))));
                }
            }
        }

        if (nt < 3) {
            __syncthreads();   // all MMA reads of Bs complete
            #pragma unroll
            for (int it = 0; it < 16; it++) {
                int lin = tid + it*256;
                int k = lin >> 5, c4 = lin & 31;
                cp_async16(Bs + k*BPAD + c4*4, g_wtf + (nt+1)*16384 + k*128 + c4*4);
            }
            cp_commit();
            cp_wait<0>();
            __syncthreads();
        }
    }
}

// ============ kernel 2: attention per (h, r, zh) — R14 (validated, unchanged) ============
#define ATTN_SMEM_FLOATS (256*36*2 + 64*36 + 256 + 2*64*36 + 256)
__global__ __launch_bounds__(256, 2) void attn_kernel(const int* __restrict__ src_mask)
{
    extern __shared__ float sm[];
    float* Ks     = sm;
    float* Vs     = Ks + 256*36;
    float* Qs     = Vs + 256*36;
    float* redsum = Qs + 64*36;
    float* obuf0  = redsum + 256;
    float* obuf1  = obuf0 + 64*36;
    float* msk    = obuf1 + 64*36;

    int h = blockIdx.x, r = blockIdx.y, zh = blockIdx.z;
    int tid = threadIdx.x;
    const float* base = g_qkv + (size_t)r * LDIM * QKVN;

    #pragma unroll
    for (int p = 0; p < 8; p++) {
        int lin = tid + p*256;
        int j = lin >> 3, d4 = lin & 7;
        cp_async16(Ks + j*36 + d4*4, base + (size_t)j*QKVN + 128 + h*HDIM + d4*4);
        cp_async16(Vs + j*36 + d4*4, base + (size_t)j*QKVN + 256 + h*HDIM + d4*4);
    }
    cp_commit();
    msk[tid] = (src_mask[tid] == 0) ? -1.f : 1.f;

    int warp = tid >> 5, lane = tid & 31;
    int lr = lane >> 2, lc = lane & 3;
    int wm = warp & 1, wn = warp >> 1;
    const float* biasH = g_biasT + (size_t)h * NROWS;

    int s0l = (lane & ~3) | (lc >> 1);
    int s1l = s0l + 2;
    int sel = lc & 1;

    for (int icl = 0; icl < 2; icl++) {
        int ic = zh*2 + icl;
        int i0 = ic * 64;
        if (icl) __syncthreads();
        #pragma unroll
        for (int p = 0; p < 2; p++) {
            int lin = tid + p*256;
            int row = lin >> 3, d4 = lin & 7;
            cp_async16(Qs + row*36 + d4*4, base + (size_t)(i0 + row)*QKVN + h*HDIM + d4*4);
        }
        cp_commit();
        cp_wait<0>();
        __syncthreads();

        float acc[2][8][4];
        #pragma unroll
        for (int mi = 0; mi < 2; mi++)
            #pragma unroll
            for (int ni = 0; ni < 8; ni++)
                acc[mi][ni][0] = acc[mi][ni][1] = acc[mi][ni][2] = acc[mi][ni][3] = 0.f;

        #pragma unroll
        for (int ks = 0; ks < 4; ks++) {
            int k0 = ks * 8;
            unsigned a[2][4];
            #pragma unroll
            for (int mi = 0; mi < 2; mi++) {
                int rrow = wm*32 + mi*16 + lr;
                a[mi][0] = fu(Qs[rrow*36 + k0 + lc]);
                a[mi][1] = fu(Qs[(rrow+8)*36 + k0 + lc]);
                a[mi][2] = fu(Qs[rrow*36 + k0 + 4 + lc]);
                a[mi][3] = fu(Qs[(rrow+8)*36 + k0 + 4 + lc]);
            }
            #pragma unroll
            for (int ni = 0; ni < 8; ni++) {
                int j = wn*64 + ni*8 + lr;
                unsigned b[2] = { fu(Ks[j*36 + k0 + lc]), fu(Ks[j*36 + k0 + 4 + lc]) };
                mma_tf32(acc[0][ni], a[0], b);
                mma_tf32(acc[1][ni], a[1], b);
            }
        }

        float smv[2][2] = {{0.f,0.f},{0.f,0.f}};
        #pragma unroll
        for (int mi = 0; mi < 2; mi++) {
            int rl = wm*32 + mi*16 + lr;
            float mi0 = msk[i0 + rl], mi1 = msk[i0 + rl + 8];
            const float* bp0 = biasH + (size_t)(i0 + rl) * LDIM;
            const float* bp1 = bp0 + 8 * LDIM;
            #pragma unroll
            for (int ni = 0; ni < 8; ni++) {
                int j = wn*64 + ni*8 + lc*2;
                float2 b0 = *(const float2*)(bp0 + j);
                float2 b1 = *(const float2*)(bp1 + j);
                float mj0 = msk[j], mj1 = msk[j+1];
                float v0 = acc[mi][ni][0] + b0.x;
                float v1 = acc[mi][ni][1] + b0.y;
                float v2 = acc[mi][ni][2] + b1.x;
                float v3 = acc[mi][ni][3] + b1.y;
                if (mi0*mj0 < 0.f) v0 = -1e-9f;
                if (mi0*mj1 < 0.f) v1 = -1e-9f;
                if (mi1*mj0 < 0.f) v2 = -1e-9f;
                if (mi1*mj1 < 0.f) v3 = -1e-9f;
                float e0 = __expf(v0), e1 = __expf(v1);
                float e2 = __expf(v2), e3 = __expf(v3);
                acc[mi][ni][0] = e0; acc[mi][ni][1] = e1;
                acc[mi][ni][2] = e2; acc[mi][ni][3] = e3;
                smv[mi][0] += e0 + e1; smv[mi][1] += e2 + e3;
            }
        }
        #pragma unroll
        for (int mi = 0; mi < 2; mi++) {
            smv[mi][0] += __shfl_xor_sync(0xffffffffu, smv[mi][0], 1);
            smv[mi][0] += __shfl_xor_sync(0xffffffffu, smv[mi][0], 2);
            smv[mi][1] += __shfl_xor_sync(0xffffffffu, smv[mi][1], 1);
            smv[mi][1] += __shfl_xor_sync(0xffffffffu, smv[mi][1], 2);
        }
        if (lc == 0) {
            #pragma unroll
            for (int mi = 0; mi < 2; mi++) {
                int rl = wm*32 + mi*16 + lr;
                redsum[wn*64 + rl]     = smv[mi][0];
                redsum[wn*64 + rl + 8] = smv[mi][1];
            }
        }
        __syncthreads();
        float inv[2][2];
        #pragma unroll
        for (int mi = 0; mi < 2; mi++) {
            int rl = wm*32 + mi*16 + lr;
            inv[mi][0] = 1.f / (redsum[rl] + redsum[64 + rl] + redsum[128 + rl] + redsum[192 + rl]);
            int rl8 = rl + 8;
            inv[mi][1] = 1.f / (redsum[rl8] + redsum[64 + rl8] + redsum[128 + rl8] + redsum[192 + rl8]);
        }
        #pragma unroll
        for (int mi = 0; mi < 2; mi++)
            #pragma unroll
            for (int ni = 0; ni < 8; ni++) {
                acc[mi][ni][0] = f2tff(acc[mi][ni][0] * inv[mi][0]);
                acc[mi][ni][1] = f2tff(acc[mi][ni][1] * inv[mi][0]);
                acc[mi][ni][2] = f2tff(acc[mi][ni][2] * inv[mi][1]);
                acc[mi][ni][3] = f2tff(acc[mi][ni][3] * inv[mi][1]);
            }

        float oc[2][4][4];
        #pragma unroll
        for (int mi = 0; mi < 2; mi++)
            #pragma unroll
            for (int dt = 0; dt < 4; dt++)
                oc[mi][dt][0] = oc[mi][dt][1] = oc[mi][dt][2] = oc[mi][dt][3] = 0.f;

        #pragma unroll
        for (int ni = 0; ni < 8; ni++) {
            unsigned aP[2][4];
            #pragma unroll
            for (int mi = 0; mi < 2; mi++) {
                float t00 = __shfl_sync(0xffffffffu, acc[mi][ni][0], s0l);
                float t01 = __shfl_sync(0xffffffffu, acc[mi][ni][1], s0l);
                float t10 = __shfl_sync(0xffffffffu, acc[mi][ni][2], s0l);
                float t11 = __shfl_sync(0xffffffffu, acc[mi][ni][3], s0l);
                float u00 = __shfl_sync(0xffffffffu, acc[mi][ni][0], s1l);
                float u01 = __shfl_sync(0xffffffffu, acc[mi][ni][1], s1l);
                float u10 = __shfl_sync(0xffffffffu, acc[mi][ni][2], s1l);
                float u11 = __shfl_sync(0xffffffffu, acc[mi][ni][3], s1l);
                aP[mi][0] = fu(sel ? t01 : t00);
                aP[mi][1] = fu(sel ? t11 : t10);
                aP[mi][2] = fu(sel ? u01 : u00);
                aP[mi][3] = fu(sel ? u11 : u10);
            }
            int jb = wn*64 + ni*8;
            #pragma unroll
            for (int dt = 0; dt < 4; dt++) {
                unsigned b[2] = { fu(Vs[(jb + lc)*36 + dt*8 + lr]),
                                  fu(Vs[(jb + 4 + lc)*36 + dt*8 + lr]) };
                mma_tf32(oc[0][dt], aP[0], b);
                mma_tf32(oc[1][dt], aP[1], b);
            }
        }

        if (wn == 1 || wn == 3) {
            float* ob = (wn == 1) ? obuf0 : obuf1;
            #pragma unroll
            for (int mi = 0; mi < 2; mi++) {
                int rl = wm*32 + mi*16 + lr;
                #pragma unroll
                for (int dt = 0; dt < 4; dt++) {
                    *(float2*)(ob + rl*36 + dt*8 + lc*2)     = make_float2(oc[mi][dt][0], oc[mi][dt][1]);
                    *(float2*)(ob + (rl+8)*36 + dt*8 + lc*2) = make_float2(oc[mi][dt][2], oc[mi][dt][3]);
                }
            }
        }
        __syncthreads();
        if (wn == 0 || wn == 2) {
            float* ob = (wn == 0) ? obuf0 : obuf1;
            #pragma unroll
            for (int mi = 0; mi < 2; mi++) {
                int rl = wm*32 + mi*16 + lr;
                #pragma unroll
                for (int dt = 0; dt < 4; dt++) {
                    float2 p0 = *(float2*)(ob + rl*36 + dt*8 + lc*2);
                    float2 p1 = *(float2*)(ob + (rl+8)*36 + dt*8 + lc*2);
                    oc[mi][dt][0] += p0.x; oc[mi][dt][1] += p0.y;
                    oc[mi][dt][2] += p1.x; oc[mi][dt][3] += p1.y;
                }
            }
        }
        if (wn == 2) {
            #pragma unroll
            for (int mi = 0; mi < 2; mi++) {
                int rl = wm*32 + mi*16 + lr;
                #pragma unroll
                for (int dt = 0; dt < 4; dt++) {
                    *(float2*)(obuf1 + rl*36 + dt*8 + lc*2)     = make_float2(oc[mi][dt][0], oc[mi][dt][1]);
                    *(float2*)(obuf1 + (rl+8)*36 + dt*8 + lc*2) = make_float2(oc[mi][dt][2], oc[mi][dt][3]);
                }
            }
        }
        __syncthreads();
        if (wn == 0) {
            #pragma unroll
            for (int mi = 0; mi < 2; mi++) {
                int rl = wm*32 + mi*16 + lr;
                size_t ro0 = ((size_t)r*LDIM + i0 + rl) * CDIM + h*HDIM;
                size_t ro1 = ro0 + 8*CDIM;
                #pragma unroll
                for (int dt = 0; dt < 4; dt++) {
                    float2 p0 = *(float2*)(obuf1 + rl*36 + dt*8 + lc*2);
                    float2 p1 = *(float2*)(obuf1 + (rl+8)*36 + dt*8 + lc*2);
                    *(float2*)(g_attn + ro0 + dt*8 + lc*2) =
                        make_float2(oc[mi][dt][0] + p0.x, oc[mi][dt][1] + p0.y);
                    *(float2*)(g_attn + ro1 + dt*8 + lc*2) =
                        make_float2(oc[mi][dt][2] + p1.x, oc[mi][dt][3] + p1.y);
                }
            }
        }
    }
}

// ============ kernel 3: (gate * attn) @ w_out + b_out — W via cp.async from preconverted ============
#define GEMM_OUT_SMEM_FLOATS (64*APAD + 128*BPAD)
__global__ __launch_bounds__(256, 2) void gemm_out_kernel(
    const float* __restrict__ bout, float* __restrict__ out)
{
    extern __shared__ float sm[];
    float* As = sm;               // [64][APAD]
    float* Bs = sm + 64*APAD;     // [128][BPAD]
    int tid = threadIdx.x;
    int m0 = blockIdx.x * 64;

    // W staging via cp.async (no conversion), overlapped with A-tile math
    #pragma unroll
    for (int it = 0; it < 16; it++) {
        int lin = tid + it*256;
        int k = lin >> 5, c4 = lin & 31;
        cp_async16(Bs + k*BPAD + c4*4, g_wouttf + k*128 + c4*4);
    }
    cp_commit();

    #pragma unroll
    for (int it = 0; it < 8; it++) {
        int lin = tid + it*256;
        int r = lin >> 5, c4 = lin & 31;
        float4 gte = *(const float4*)(g_gate + (size_t)(m0 + r)*CDIM + c4*4);
        float4 att = *(const float4*)(g_attn + (size_t)(m0 + r)*CDIM + c4*4);
        float4 a;
        a.x = f2tff(gte.x * att.x); a.y = f2tff(gte.y * att.y);
        a.z = f2tff(gte.z * att.z); a.w = f2tff(gte.w * att.w);
        *(float4*)(As + r*APAD + c4*4) = a;
    }
    cp_wait<0>();
    __syncthreads();

    int warp = tid >> 5, lane = tid & 31;
    int lr = lane >> 2, lc = lane & 3;
    int wm = warp & 1, wn = warp >> 1;

    float acc[2][4][4];
    #pragma unroll
    for (int mi = 0; mi < 2; mi++)
        #pragma unroll
        for (int ni = 0; ni < 4; ni++)
            acc[mi][ni][0] = acc[mi][ni][1] = acc[mi][ni][2] = acc[mi][ni][3] = 0.f;

    #pragma unroll
    for (int ks = 0; ks < 16; ks++) {
        int k0 = ks * 8;
        unsigned a[2][4], bf[4][2];
        #pragma unroll
        for (int mi = 0; mi < 2; mi++) {
            int r = wm*32 + mi*16 + lr;
            a[mi][0] = fu(As[r*APAD + k0 + lc]);
            a[mi][1] = fu(As[(r+8)*APAD + k0 + lc]);
            a[mi][2] = fu(As[r*APAD + k0 + 4 + lc]);
            a[mi][3] = fu(As[(r+8)*APAD + k0 + 4 + lc]);
        }
        #pragma unroll
        for (int ni = 0; ni < 4; ni++) {
            int n = wn*32 + ni*8 + lr;
            bf[ni][0] = fu(Bs[(k0 + lc)*BPAD + n]);
            bf[ni][1] = fu(Bs[(k0 + 4 + lc)*BPAD + n]);
        }
        #pragma unroll
        for (int mi = 0; mi < 2; mi++)
            #pragma unroll
            for (int ni = 0; ni < 4; ni++)
                mma_tf32(acc[mi][ni], a[mi], bf[ni]);
    }

    #pragma unroll
    for (int mi = 0; mi < 2; mi++) {
        #pragma unroll
        for (int ni = 0; ni < 4; ni++) {
            int gr = m0 + wm*32 + mi*16 + lr;
            int cn = wn*32 + ni*8 + lc*2;
            float b0 = bout[cn], b1 = bout[cn+1];
            *(float2*)(out + (size_t)gr * CDIM + cn) =
                make_float2(acc[mi][ni][0] + b0, acc[mi][ni][1] + b1);
            *(float2*)(out + (size_t)(gr+8) * CDIM + cn) =
                make_float2(acc[mi][ni][2] + b0, acc[mi][ni][3] + b1);
        }
    }
}

// ---------------- launch ----------------
extern "C" void kernel_launch(void* const* d_in, const int* in_sizes, int n_in,
                              void* d_out, int out_size)
{
    (void)in_sizes; (void)n_in; (void)out_size;
    const float* z        = (const float*)d_in[0];
    const int*   src_mask = (const int*)  d_in[1];
    const float* ln_g     = (const float*)d_in[2];
    const float* ln_b     = (const float*)d_in[3];
    const float* w_qkv    = (const float*)d_in[4];
    const float* w_pair   = (const float*)d_in[5];
    const float* w_gate   = (const float*)d_in[6];
    const float* b_gate   = (const float*)d_in[7];
    const float* w_out    = (const float*)d_in[8];
    const float* b_out    = (const float*)d_in[9];
    float* out = (float*)d_out;

    const int qkv_smem  = GEMM_QKV_SMEM_FLOATS * 4;
    const int out_smem  = GEMM_OUT_SMEM_FLOATS * 4;
    const int attn_smem = ATTN_SMEM_FLOATS * 4;
    cudaFuncSetAttribute(gemm_qkv_gate,   cudaFuncAttributeMaxDynamicSharedMemorySize, qkv_smem);
    cudaFuncSetAttribute(attn_kernel,     cudaFuncAttributeMaxDynamicSharedMemorySize, attn_smem);
    cudaFuncSetAttribute(gemm_out_kernel, cudaFuncAttributeMaxDynamicSharedMemorySize, out_smem);

    prep_weights<<<80, 256>>>(w_qkv, w_gate, w_out);
    gemm_qkv_gate<<<NROWS/64, 256, qkv_smem>>>(z, ln_g, ln_b, b_gate, w_pair);
    attn_kernel<<<dim3(NH, LDIM, 2), 256, attn_smem>>>(src_mask);
    gemm_out_kernel<<<NROWS/64, 256, out_smem>>>(b_out, out);
}

// round 16
// speedup vs baseline: 1.1735x; 1.0208x over previous
#include <cuda_runtime.h>
#include <cstdint>

#define LDIM 256
#define CDIM 128
#define NH 4
#define HDIM 32
#define NROWS (LDIM*LDIM)        // 65536
#define QKVN 384
#define SQRT32 5.656854249492380f
#define APAD 140
#define BPAD 136

// ---------------- scratch ----------------
__device__ float g_qkv  [(size_t)NROWS * QKVN];
__device__ float g_gate [(size_t)NROWS * CDIM];
__device__ float g_biasT[(size_t)NH * NROWS];
__device__ float g_attn [(size_t)NROWS * CDIM];
__device__ float g_wtf  [4 * 128 * 128];     // pre-converted [slab][k][n]
__device__ float g_wouttf[128 * 128];        // pre-converted w_out

// ---------------- helpers ----------------
__device__ __forceinline__ unsigned f2tf(float f) {
    unsigned r;
    asm("cvt.rna.tf32.f32 %0, %1;" : "=r"(r) : "f"(f));
    return r;
}
__device__ __forceinline__ float f2tff(float f) { return __uint_as_float(f2tf(f)); }
__device__ __forceinline__ unsigned fu(float f) { return __float_as_uint(f); }

__device__ __forceinline__ void mma_tf32(float c[4], const unsigned a[4], const unsigned b[2]) {
    asm volatile(
        "mma.sync.aligned.m16n8k8.row.col.f32.tf32.tf32.f32 "
        "{%0,%1,%2,%3},{%4,%5,%6,%7},{%8,%9},{%0,%1,%2,%3};"
        : "+f"(c[0]), "+f"(c[1]), "+f"(c[2]), "+f"(c[3])
        : "r"(a[0]), "r"(a[1]), "r"(a[2]), "r"(a[3]), "r"(b[0]), "r"(b[1]));
}

__device__ __forceinline__ void cp_async16(float* smem_dst, const float* gsrc) {
    unsigned s = (unsigned)__cvta_generic_to_shared(smem_dst);
    asm volatile("cp.async.cg.shared.global [%0], [%1], 16;" :: "r"(s), "l"(gsrc));
}
__device__ __forceinline__ void cp_commit() { asm volatile("cp.async.commit_group;"); }
template<int N> __device__ __forceinline__ void cp_wait() {
    asm volatile("cp.async.wait_group %0;" :: "n"(N));
}

// ============ kernel 0: one-time weight conversion (validated) ============
__global__ __launch_bounds__(256) void prep_weights(
    const float* __restrict__ wqkv, const float* __restrict__ wgate,
    const float* __restrict__ wout)
{
    int idx4 = (blockIdx.x * 256 + threadIdx.x) * 4;
    if (idx4 < 4*128*128) {
        int nt = idx4 >> 14, wi = idx4 & 16383, k = wi >> 7, n = wi & 127;
        float4 w;
        if (nt < 3) w = *(const float4*)(wqkv + (size_t)k*QKVN + nt*128 + n);
        else        w = *(const float4*)(wgate + (size_t)k*CDIM + n);
        if (nt == 0) { w.x *= SQRT32; w.y *= SQRT32; w.z *= SQRT32; w.w *= SQRT32; }
        w.x = f2tff(w.x); w.y = f2tff(w.y); w.z = f2tff(w.z); w.w = f2tff(w.w);
        *(float4*)(g_wtf + idx4) = w;
    } else {
        int j = idx4 - 4*128*128;
        float4 w = *(const float4*)(wout + j);
        w.x = f2tff(w.x); w.y = f2tff(w.y); w.z = f2tff(w.z); w.w = f2tff(w.w);
        *(float4*)(g_wouttf + j) = w;
    }
}

// ============ kernel 1: fused LN + GEMM (validated at ~89us, unchanged) ============
#define GEMM_QKV_SMEM_FLOATS (64*APAD + 128*BPAD + 128 + 128 + 512)
__global__ __launch_bounds__(256, 2) void gemm_qkv_gate(
    const float* __restrict__ z, const float* __restrict__ lng, const float* __restrict__ lnb,
    const float* __restrict__ bgate, const float* __restrict__ wpair)
{
    extern __shared__ float sm[];
    float* As  = sm;
    float* Bs  = sm + 64*APAD;
    float* gS  = Bs + 128*BPAD;
    float* bS  = gS + 128;
    float* wpS = bS + 128;

    int tid = threadIdx.x;
    int m0 = blockIdx.x * 64;

    #pragma unroll
    for (int it = 0; it < 8; it++) {
        int lin = tid + it*256;
        int r = lin >> 5, c4 = lin & 31;
        cp_async16(As + r*APAD + c4*4, z + (size_t)(m0 + r)*CDIM + c4*4);
    }
    #pragma unroll
    for (int it = 0; it < 16; it++) {
        int lin = tid + it*256;
        int k = lin >> 5, c4 = lin & 31;
        cp_async16(Bs + k*BPAD + c4*4, g_wtf + k*128 + c4*4);
    }
    cp_commit();
    if (tid < 128) { gS[tid] = lng[tid]; bS[tid] = lnb[tid]; }
    wpS[tid] = wpair[tid];
    wpS[tid + 256] = wpair[tid + 256];
    cp_wait<0>();
    __syncthreads();

    {
        int row = tid >> 2, quad = tid & 3;
        float* Ar = As + row*APAD + quad*4;
        float v[32];
        float s = 0.f, ss = 0.f;
        #pragma unroll
        for (int k = 0; k < 8; k++) {
            float4 t = *(float4*)(Ar + k*16);
            v[k*4] = t.x; v[k*4+1] = t.y; v[k*4+2] = t.z; v[k*4+3] = t.w;
            s  += t.x + t.y + t.z + t.w;
            ss += t.x*t.x + t.y*t.y + t.z*t.z + t.w*t.w;
        }
        s  += __shfl_xor_sync(0xffffffffu, s, 1);  s  += __shfl_xor_sync(0xffffffffu, s, 2);
        ss += __shfl_xor_sync(0xffffffffu, ss, 1); ss += __shfl_xor_sync(0xffffffffu, ss, 2);
        float mu  = s * (1.0f / CDIM);
        float var = ss * (1.0f / CDIM) - mu * mu;
        float rstd = rsqrtf(var + 1e-5f);

        float bh0 = 0.f, bh1 = 0.f, bh2 = 0.f, bh3 = 0.f;
        #pragma unroll
        for (int k = 0; k < 8; k++) {
            float4 o;
            float* ov = &o.x;
            #pragma unroll
            for (int j = 0; j < 4; j++) {
                int c = quad*4 + k*16 + j;
                float zn = (v[k*4+j] - mu) * rstd * gS[c] + bS[c];
                bh0 += zn * wpS[c*4];   bh1 += zn * wpS[c*4+1];
                bh2 += zn * wpS[c*4+2]; bh3 += zn * wpS[c*4+3];
                ov[j] = f2tff(zn);
            }
            *(float4*)(Ar + k*16) = o;
        }
        bh0 += __shfl_xor_sync(0xffffffffu, bh0, 1); bh0 += __shfl_xor_sync(0xffffffffu, bh0, 2);
        bh1 += __shfl_xor_sync(0xffffffffu, bh1, 1); bh1 += __shfl_xor_sync(0xffffffffu, bh1, 2);
        bh2 += __shfl_xor_sync(0xffffffffu, bh2, 1); bh2 += __shfl_xor_sync(0xffffffffu, bh2, 2);
        bh3 += __shfl_xor_sync(0xffffffffu, bh3, 1); bh3 += __shfl_xor_sync(0xffffffffu, bh3, 2);
        if (quad == 0) {
            g_biasT[(size_t)0*NROWS + m0 + row] = bh0;
            g_biasT[(size_t)1*NROWS + m0 + row] = bh1;
            g_biasT[(size_t)2*NROWS + m0 + row] = bh2;
            g_biasT[(size_t)3*NROWS + m0 + row] = bh3;
        }
    }
    __syncthreads();

    int warp = tid >> 5, lane = tid & 31;
    int lr = lane >> 2, lc = lane & 3;
    int wm = warp & 1, wn = warp >> 1;

    #pragma unroll
    for (int nt = 0; nt < 4; nt++) {
        float acc[2][4][4];
        #pragma unroll
        for (int mi = 0; mi < 2; mi++)
            #pragma unroll
            for (int ni = 0; ni < 4; ni++)
                acc[mi][ni][0] = acc[mi][ni][1] = acc[mi][ni][2] = acc[mi][ni][3] = 0.f;

        #pragma unroll
        for (int ks = 0; ks < 16; ks++) {
            int k0 = ks * 8;
            unsigned a[2][4], bf[4][2];
            #pragma unroll
            for (int mi = 0; mi < 2; mi++) {
                int r = wm*32 + mi*16 + lr;
                a[mi][0] = fu(As[r*APAD + k0 + lc]);
                a[mi][1] = fu(As[(r+8)*APAD + k0 + lc]);
                a[mi][2] = fu(As[r*APAD + k0 + 4 + lc]);
                a[mi][3] = fu(As[(r+8)*APAD + k0 + 4 + lc]);
            }
            #pragma unroll
            for (int ni = 0; ni < 4; ni++) {
                int n = wn*32 + ni*8 + lr;
                bf[ni][0] = fu(Bs[(k0 + lc)*BPAD + n]);
                bf[ni][1] = fu(Bs[(k0 + 4 + lc)*BPAD + n]);
            }
            #pragma unroll
            for (int mi = 0; mi < 2; mi++)
                #pragma unroll
                for (int ni = 0; ni < 4; ni++)
                    mma_tf32(acc[mi][ni], a[mi], bf[ni]);
        }

        #pragma unroll
        for (int mi = 0; mi < 2; mi++) {
            #pragma unroll
            for (int ni = 0; ni < 4; ni++) {
                int gr = m0 + wm*32 + mi*16 + lr;
                int cn = wn*32 + ni*8 + lc*2;
                if (nt < 3) {
                    int gc = nt*128 + cn;
                    *(float2*)(g_qkv + (size_t)gr * QKVN + gc) =
                        make_float2(f2tff(acc[mi][ni][0]), f2tff(acc[mi][ni][1]));
                    *(float2*)(g_qkv + (size_t)(gr+8) * QKVN + gc) =
                        make_float2(f2tff(acc[mi][ni][2]), f2tff(acc[mi][ni][3]));
                } else {
                    float b0 = bgate[cn], b1 = bgate[cn+1];
                    *(float2*)(g_gate + (size_t)gr * CDIM + cn) =
                        make_float2(1.f/(1.f + __expf(-(acc[mi][ni][0] + b0))),
                                    1.f/(1.f + __expf(-(acc[mi][ni][1] + b1))));
                    *(float2*)(g_gate + (size_t)(gr+8) * CDIM + cn) =
                        make_float2(1.f/(1.f + __expf(-(acc[mi][ni][2] + b0))),
                                    1.f/(1.f + __expf(-(acc[mi][ni][3] + b1))));
                }
            }
        }

        if (nt < 3) {
            __syncthreads();
            #pragma unroll
            for (int it = 0; it < 16; it++) {
                int lin = tid + it*256;
                int k = lin >> 5, c4 = lin & 31;
                cp_async16(Bs + k*BPAD + c4*4, g_wtf + (nt+1)*16384 + k*128 + c4*4);
            }
            cp_commit();
            cp_wait<0>();
            __syncthreads();
        }
    }
}

// ============ kernel 2: attention per (h, r) — 4 chunks/block, double-buffered Q prefetch ============
// 8 warps: wm = warp&1 (32-row strip), wn = warp>>1 (j quarter of 64).
#define ATTN_SMEM_FLOATS (256*36*2 + 2*64*36 + 256 + 2*64*36 + 256)
__global__ __launch_bounds__(256, 2) void attn_kernel(const int* __restrict__ src_mask)
{
    extern __shared__ float sm[];
    float* Ks     = sm;                 // [256][36]
    float* Vs     = Ks + 256*36;        // [256][36]
    float* Qs0    = Vs + 256*36;        // [64][36]
    float* Qs1    = Qs0 + 64*36;        // [64][36]
    float* redsum = Qs1 + 64*36;        // [4][64]
    float* obuf0  = redsum + 256;       // [64][36]
    float* obuf1  = obuf0 + 64*36;      // [64][36]
    float* msk    = obuf1 + 64*36;      // [256]

    int h = blockIdx.x, r = blockIdx.y;
    int tid = threadIdx.x;
    const float* base = g_qkv + (size_t)r * LDIM * QKVN;

    // prologue: K/V + Q0 in one group
    #pragma unroll
    for (int p = 0; p < 8; p++) {
        int lin = tid + p*256;
        int j = lin >> 3, d4 = lin & 7;
        cp_async16(Ks + j*36 + d4*4, base + (size_t)j*QKVN + 128 + h*HDIM + d4*4);
        cp_async16(Vs + j*36 + d4*4, base + (size_t)j*QKVN + 256 + h*HDIM + d4*4);
    }
    #pragma unroll
    for (int p = 0; p < 2; p++) {
        int lin = tid + p*256;
        int row = lin >> 3, d4 = lin & 7;
        cp_async16(Qs0 + row*36 + d4*4, base + (size_t)row*QKVN + h*HDIM + d4*4);
    }
    cp_commit();
    msk[tid] = (src_mask[tid] == 0) ? -1.f : 1.f;

    int warp = tid >> 5, lane = tid & 31;
    int lr = lane >> 2, lc = lane & 3;
    int wm = warp & 1, wn = warp >> 1;
    const float* biasH = g_biasT + (size_t)h * NROWS;

    int s0l = (lane & ~3) | (lc >> 1);
    int s1l = s0l + 2;
    int sel = lc & 1;

    for (int ic = 0; ic < 4; ic++) {
        int i0 = ic * 64;
        float* Qs = (ic & 1) ? Qs1 : Qs0;
        // prefetch next chunk's Q into the other buffer
        if (ic < 3) {
            float* Qn = (ic & 1) ? Qs0 : Qs1;
            #pragma unroll
            for (int p = 0; p < 2; p++) {
                int lin = tid + p*256;
                int row = lin >> 3, d4 = lin & 7;
                cp_async16(Qn + row*36 + d4*4,
                           base + (size_t)(i0 + 64 + row)*QKVN + h*HDIM + d4*4);
            }
            cp_commit();
            cp_wait<1>();     // current buffer (and K/V on ic=0) complete; prefetch in flight
        } else {
            cp_wait<0>();
        }
        __syncthreads();

        // ---- QK^T: warp covers rows [wm*32, +32), cols [wn*64, +64) ----
        float acc[2][8][4];
        #pragma unroll
        for (int mi = 0; mi < 2; mi++)
            #pragma unroll
            for (int ni = 0; ni < 8; ni++)
                acc[mi][ni][0] = acc[mi][ni][1] = acc[mi][ni][2] = acc[mi][ni][3] = 0.f;

        #pragma unroll
        for (int ks = 0; ks < 4; ks++) {
            int k0 = ks * 8;
            unsigned a[2][4];
            #pragma unroll
            for (int mi = 0; mi < 2; mi++) {
                int rrow = wm*32 + mi*16 + lr;
                a[mi][0] = fu(Qs[rrow*36 + k0 + lc]);
                a[mi][1] = fu(Qs[(rrow+8)*36 + k0 + lc]);
                a[mi][2] = fu(Qs[rrow*36 + k0 + 4 + lc]);
                a[mi][3] = fu(Qs[(rrow+8)*36 + k0 + 4 + lc]);
            }
            #pragma unroll
            for (int ni = 0; ni < 8; ni++) {
                int j = wn*64 + ni*8 + lr;
                unsigned b[2] = { fu(Ks[j*36 + k0 + lc]), fu(Ks[j*36 + k0 + 4 + lc]) };
                mma_tf32(acc[0][ni], a[0], b);
                mma_tf32(acc[1][ni], a[1], b);
            }
        }

        // ---- bias + mask + direct exp + local sums ----
        float smv[2][2] = {{0.f,0.f},{0.f,0.f}};
        #pragma unroll
        for (int mi = 0; mi < 2; mi++) {
            int rl = wm*32 + mi*16 + lr;
            float mi0 = msk[i0 + rl], mi1 = msk[i0 + rl + 8];
            const float* bp0 = biasH + (size_t)(i0 + rl) * LDIM;
            const float* bp1 = bp0 + 8 * LDIM;
            #pragma unroll
            for (int ni = 0; ni < 8; ni++) {
                int j = wn*64 + ni*8 + lc*2;
                float2 b0 = *(const float2*)(bp0 + j);
                float2 b1 = *(const float2*)(bp1 + j);
                float mj0 = msk[j], mj1 = msk[j+1];
                float v0 = acc[mi][ni][0] + b0.x;
                float v1 = acc[mi][ni][1] + b0.y;
                float v2 = acc[mi][ni][2] + b1.x;
                float v3 = acc[mi][ni][3] + b1.y;
                if (mi0*mj0 < 0.f) v0 = -1e-9f;
                if (mi0*mj1 < 0.f) v1 = -1e-9f;
                if (mi1*mj0 < 0.f) v2 = -1e-9f;
                if (mi1*mj1 < 0.f) v3 = -1e-9f;
                float e0 = __expf(v0), e1 = __expf(v1);
                float e2 = __expf(v2), e3 = __expf(v3);
                acc[mi][ni][0] = e0; acc[mi][ni][1] = e1;
                acc[mi][ni][2] = e2; acc[mi][ni][3] = e3;
                smv[mi][0] += e0 + e1; smv[mi][1] += e2 + e3;
            }
        }
        #pragma unroll
        for (int mi = 0; mi < 2; mi++) {
            smv[mi][0] += __shfl_xor_sync(0xffffffffu, smv[mi][0], 1);
            smv[mi][0] += __shfl_xor_sync(0xffffffffu, smv[mi][0], 2);
            smv[mi][1] += __shfl_xor_sync(0xffffffffu, smv[mi][1], 1);
            smv[mi][1] += __shfl_xor_sync(0xffffffffu, smv[mi][1], 2);
        }
        if (lc == 0) {
            #pragma unroll
            for (int mi = 0; mi < 2; mi++) {
                int rl = wm*32 + mi*16 + lr;
                redsum[wn*64 + rl]     = smv[mi][0];
                redsum[wn*64 + rl + 8] = smv[mi][1];
            }
        }
        __syncthreads();
        float inv[2][2];
        #pragma unroll
        for (int mi = 0; mi < 2; mi++) {
            int rl = wm*32 + mi*16 + lr;
            inv[mi][0] = 1.f / (redsum[rl] + redsum[64 + rl] + redsum[128 + rl] + redsum[192 + rl]);
            int rl8 = rl + 8;
            inv[mi][1] = 1.f / (redsum[rl8] + redsum[64 + rl8] + redsum[128 + rl8] + redsum[192 + rl8]);
        }
        #pragma unroll
        for (int mi = 0; mi < 2; mi++)
            #pragma unroll
            for (int ni = 0; ni < 8; ni++) {
                acc[mi][ni][0] = f2tff(acc[mi][ni][0] * inv[mi][0]);
                acc[mi][ni][1] = f2tff(acc[mi][ni][1] * inv[mi][0]);
                acc[mi][ni][2] = f2tff(acc[mi][ni][2] * inv[mi][1]);
                acc[mi][ni][3] = f2tff(acc[mi][ni][3] * inv[mi][1]);
            }

        // ---- P @ V ----
        float oc[2][4][4];
        #pragma unroll
        for (int mi = 0; mi < 2; mi++)
            #pragma unroll
            for (int dt = 0; dt < 4; dt++)
                oc[mi][dt][0] = oc[mi][dt][1] = oc[mi][dt][2] = oc[mi][dt][3] = 0.f;

        #pragma unroll
        for (int ni = 0; ni < 8; ni++) {
            unsigned aP[2][4];
            #pragma unroll
            for (int mi = 0; mi < 2; mi++) {
                float t00 = __shfl_sync(0xffffffffu, acc[mi][ni][0], s0l);
                float t01 = __shfl_sync(0xffffffffu, acc[mi][ni][1], s0l);
                float t10 = __shfl_sync(0xffffffffu, acc[mi][ni][2], s0l);
                float t11 = __shfl_sync(0xffffffffu, acc[mi][ni][3], s0l);
                float u00 = __shfl_sync(0xffffffffu, acc[mi][ni][0], s1l);
                float u01 = __shfl_sync(0xffffffffu, acc[mi][ni][1], s1l);
                float u10 = __shfl_sync(0xffffffffu, acc[mi][ni][2], s1l);
                float u11 = __shfl_sync(0xffffffffu, acc[mi][ni][3], s1l);
                aP[mi][0] = fu(sel ? t01 : t00);
                aP[mi][1] = fu(sel ? t11 : t10);
                aP[mi][2] = fu(sel ? u01 : u00);
                aP[mi][3] = fu(sel ? u11 : u10);
            }
            int jb = wn*64 + ni*8;
            #pragma unroll
            for (int dt = 0; dt < 4; dt++) {
                unsigned b[2] = { fu(Vs[(jb + lc)*36 + dt*8 + lr]),
                                  fu(Vs[(jb + 4 + lc)*36 + dt*8 + lr]) };
                mma_tf32(oc[0][dt], aP[0], b);
                mma_tf32(oc[1][dt], aP[1], b);
            }
        }

        // ---- 4-way combine (2 stages) ----
        if (wn == 1 || wn == 3) {
            float* ob = (wn == 1) ? obuf0 : obuf1;
            #pragma unroll
            for (int mi = 0; mi < 2; mi++) {
                int rl = wm*32 + mi*16 + lr;
                #pragma unroll
                for (int dt = 0; dt < 4; dt++) {
                    *(float2*)(ob + rl*36 + dt*8 + lc*2)     = make_float2(oc[mi][dt][0], oc[mi][dt][1]);
                    *(float2*)(ob + (rl+8)*36 + dt*8 + lc*2) = make_float2(oc[mi][dt][2], oc[mi][dt][3]);
                }
            }
        }
        __syncthreads();
        if (wn == 0 || wn == 2) {
            float* ob = (wn == 0) ? obuf0 : obuf1;
            #pragma unroll
            for (int mi = 0; mi < 2; mi++) {
                int rl = wm*32 + mi*16 + lr;
                #pragma unroll
                for (int dt = 0; dt < 4; dt++) {
                    float2 p0 = *(float2*)(ob + rl*36 + dt*8 + lc*2);
                    float2 p1 = *(float2*)(ob + (rl+8)*36 + dt*8 + lc*2);
                    oc[mi][dt][0] += p0.x; oc[mi][dt][1] += p0.y;
                    oc[mi][dt][2] += p1.x; oc[mi][dt][3] += p1.y;
                }
            }
        }
        if (wn == 2) {
            #pragma unroll
            for (int mi = 0; mi < 2; mi++) {
                int rl = wm*32 + mi*16 + lr;
                #pragma unroll
                for (int dt = 0; dt < 4; dt++) {
                    *(float2*)(obuf1 + rl*36 + dt*8 + lc*2)     = make_float2(oc[mi][dt][0], oc[mi][dt][1]);
                    *(float2*)(obuf1 + (rl+8)*36 + dt*8 + lc*2) = make_float2(oc[mi][dt][2], oc[mi][dt][3]);
                }
            }
        }
        __syncthreads();
        if (wn == 0) {
            #pragma unroll
            for (int mi = 0; mi < 2; mi++) {
                int rl = wm*32 + mi*16 + lr;
                size_t ro0 = ((size_t)r*LDIM + i0 + rl) * CDIM + h*HDIM;
                size_t ro1 = ro0 + 8*CDIM;
                #pragma unroll
                for (int dt = 0; dt < 4; dt++) {
                    float2 p0 = *(float2*)(obuf1 + rl*36 + dt*8 + lc*2);
                    float2 p1 = *(float2*)(obuf1 + (rl+8)*36 + dt*8 + lc*2);
                    *(float2*)(g_attn + ro0 + dt*8 + lc*2) =
                        make_float2(oc[mi][dt][0] + p0.x, oc[mi][dt][1] + p0.y);
                    *(float2*)(g_attn + ro1 + dt*8 + lc*2) =
                        make_float2(oc[mi][dt][2] + p1.x, oc[mi][dt][3] + p1.y);
                }
            }
        }
    }
}

// ============ kernel 3: (gate * attn) @ w_out + b_out (validated, unchanged) ============
#define GEMM_OUT_SMEM_FLOATS (64*APAD + 128*BPAD)
__global__ __launch_bounds__(256, 2) void gemm_out_kernel(
    const float* __restrict__ bout, float* __restrict__ out)
{
    extern __shared__ float sm[];
    float* As = sm;
    float* Bs = sm + 64*APAD;
    int tid = threadIdx.x;
    int m0 = blockIdx.x * 64;

    #pragma unroll
    for (int it = 0; it < 16; it++) {
        int lin = tid + it*256;
        int k = lin >> 5, c4 = lin & 31;
        cp_async16(Bs + k*BPAD + c4*4, g_wouttf + k*128 + c4*4);
    }
    cp_commit();

    #pragma unroll
    for (int it = 0; it < 8; it++) {
        int lin = tid + it*256;
        int r = lin >> 5, c4 = lin & 31;
        float4 gte = *(const float4*)(g_gate + (size_t)(m0 + r)*CDIM + c4*4);
        float4 att = *(const float4*)(g_attn + (size_t)(m0 + r)*CDIM + c4*4);
        float4 a;
        a.x = f2tff(gte.x * att.x); a.y = f2tff(gte.y * att.y);
        a.z = f2tff(gte.z * att.z); a.w = f2tff(gte.w * att.w);
        *(float4*)(As + r*APAD + c4*4) = a;
    }
    cp_wait<0>();
    __syncthreads();

    int warp = tid >> 5, lane = tid & 31;
    int lr = lane >> 2, lc = lane & 3;
    int wm = warp & 1, wn = warp >> 1;

    float acc[2][4][4];
    #pragma unroll
    for (int mi = 0; mi < 2; mi++)
        #pragma unroll
        for (int ni = 0; ni < 4; ni++)
            acc[mi][ni][0] = acc[mi][ni][1] = acc[mi][ni][2] = acc[mi][ni][3] = 0.f;

    #pragma unroll
    for (int ks = 0; ks < 16; ks++) {
        int k0 = ks * 8;
        unsigned a[2][4], bf[4][2];
        #pragma unroll
        for (int mi = 0; mi < 2; mi++) {
            int r = wm*32 + mi*16 + lr;
            a[mi][0] = fu(As[r*APAD + k0 + lc]);
            a[mi][1] = fu(As[(r+8)*APAD + k0 + lc]);
            a[mi][2] = fu(As[r*APAD + k0 + 4 + lc]);
            a[mi][3] = fu(As[(r+8)*APAD + k0 + 4 + lc]);
        }
        #pragma unroll
        for (int ni = 0; ni < 4; ni++) {
            int n = wn*32 + ni*8 + lr;
            bf[ni][0] = fu(Bs[(k0 + lc)*BPAD + n]);
            bf[ni][1] = fu(Bs[(k0 + 4 + lc)*BPAD + n]);
        }
        #pragma unroll
        for (int mi = 0; mi < 2; mi++)
            #pragma unroll
            for (int ni = 0; ni < 4; ni++)
                mma_tf32(acc[mi][ni], a[mi], bf[ni]);
    }

    #pragma unroll
    for (int mi = 0; mi < 2; mi++) {
        #pragma unroll
        for (int ni = 0; ni < 4; ni++) {
            int gr = m0 + wm*32 + mi*16 + lr;
            int cn = wn*32 + ni*8 + lc*2;
            float b0 = bout[cn], b1 = bout[cn+1];
            *(float2*)(out + (size_t)gr * CDIM + cn) =
                make_float2(acc[mi][ni][0] + b0, acc[mi][ni][1] + b1);
            *(float2*)(out + (size_t)(gr+8) * CDIM + cn) =
                make_float2(acc[mi][ni][2] + b0, acc[mi][ni][3] + b1);
        }
    }
}

// ---------------- launch ----------------
extern "C" void kernel_launch(void* const* d_in, const int* in_sizes, int n_in,
                              void* d_out, int out_size)
{
    (void)in_sizes; (void)n_in; (void)out_size;
    const float* z        = (const float*)d_in[0];
    const int*   src_mask = (const int*)  d_in[1];
    const float* ln_g     = (const float*)d_in[2];
    const float* ln_b     = (const float*)d_in[3];
    const float* w_qkv    = (const float*)d_in[4];
    const float* w_pair   = (const float*)d_in[5];
    const float* w_gate   = (const float*)d_in[6];
    const float* b_gate   = (const float*)d_in[7];
    const float* w_out    = (const float*)d_in[8];
    const float* b_out    = (const float*)d_in[9];
    float* out = (float*)d_out;

    const int qkv_smem  = GEMM_QKV_SMEM_FLOATS * 4;
    const int out_smem  = GEMM_OUT_SMEM_FLOATS * 4;
    const int attn_smem = ATTN_SMEM_FLOATS * 4;    // ~112.6 KB
    cudaFuncSetAttribute(gemm_qkv_gate,   cudaFuncAttributeMaxDynamicSharedMemorySize, qkv_smem);
    cudaFuncSetAttribute(attn_kernel,     cudaFuncAttributeMaxDynamicSharedMemorySize, attn_smem);
    cudaFuncSetAttribute(gemm_out_kernel, cudaFuncAttributeMaxDynamicSharedMemorySize, out_smem);

    prep_weights<<<80, 256>>>(w_qkv, w_gate, w_out);
    gemm_qkv_gate<<<NROWS/64, 256, qkv_smem>>>(z, ln_g, ln_b, b_gate, w_pair);
    attn_kernel<<<dim3(NH, LDIM), 256, attn_smem>>>(src_mask);
    gemm_out_kernel<<<NROWS/64, 256, out_smem>>>(b_out, out);
}

// round 17
// speedup vs baseline: 1.1804x; 1.0059x over previous
#include <cuda_runtime.h>
#include <cstdint>

#define LDIM 256
#define CDIM 128
#define NH 4
#define HDIM 32
#define NROWS (LDIM*LDIM)        // 65536
#define QKVN 384
#define SQRT32 5.656854249492380f
#define APAD 140
#define BPAD 136

// ---------------- scratch ----------------
__device__ float g_qkv  [(size_t)NROWS * QKVN];
__device__ float g_gate [(size_t)NROWS * CDIM];
__device__ float g_biasT[(size_t)NH * NROWS];
__device__ float g_attn [(size_t)NROWS * CDIM];
__device__ float g_wtf  [4 * 128 * 128];
__device__ float g_wouttf[128 * 128];

// ---------------- helpers ----------------
__device__ __forceinline__ unsigned f2tf(float f) {
    unsigned r;
    asm("cvt.rna.tf32.f32 %0, %1;" : "=r"(r) : "f"(f));
    return r;
}
__device__ __forceinline__ float f2tff(float f) { return __uint_as_float(f2tf(f)); }
__device__ __forceinline__ unsigned fu(float f) { return __float_as_uint(f); }

__device__ __forceinline__ void mma_tf32(float c[4], const unsigned a[4], const unsigned b[2]) {
    asm volatile(
        "mma.sync.aligned.m16n8k8.row.col.f32.tf32.tf32.f32 "
        "{%0,%1,%2,%3},{%4,%5,%6,%7},{%8,%9},{%0,%1,%2,%3};"
        : "+f"(c[0]), "+f"(c[1]), "+f"(c[2]), "+f"(c[3])
        : "r"(a[0]), "r"(a[1]), "r"(a[2]), "r"(a[3]), "r"(b[0]), "r"(b[1]));
}

__device__ __forceinline__ void cp_async16(float* smem_dst, const float* gsrc) {
    unsigned s = (unsigned)__cvta_generic_to_shared(smem_dst);
    asm volatile("cp.async.cg.shared.global [%0], [%1], 16;" :: "r"(s), "l"(gsrc));
}
__device__ __forceinline__ void cp_commit() { asm volatile("cp.async.commit_group;"); }
template<int N> __device__ __forceinline__ void cp_wait() {
    asm volatile("cp.async.wait_group %0;" :: "n"(N));
}

// ============ kernel 0: one-time weight conversion (validated) ============
__global__ __launch_bounds__(256) void prep_weights(
    const float* __restrict__ wqkv, const float* __restrict__ wgate,
    const float* __restrict__ wout)
{
    int idx4 = (blockIdx.x * 256 + threadIdx.x) * 4;
    if (idx4 < 4*128*128) {
        int nt = idx4 >> 14, wi = idx4 & 16383, k = wi >> 7, n = wi & 127;
        float4 w;
        if (nt < 3) w = *(const float4*)(wqkv + (size_t)k*QKVN + nt*128 + n);
        else        w = *(const float4*)(wgate + (size_t)k*CDIM + n);
        if (nt == 0) { w.x *= SQRT32; w.y *= SQRT32; w.z *= SQRT32; w.w *= SQRT32; }
        w.x = f2tff(w.x); w.y = f2tff(w.y); w.z = f2tff(w.z); w.w = f2tff(w.w);
        *(float4*)(g_wtf + idx4) = w;
    } else {
        int j = idx4 - 4*128*128;
        float4 w = *(const float4*)(wout + j);
        w.x = f2tff(w.x); w.y = f2tff(w.y); w.z = f2tff(w.z); w.w = f2tff(w.w);
        *(float4*)(g_wouttf + j) = w;
    }
}

// ============ kernel 1: fused LN + GEMM (validated, unchanged) ============
#define GEMM_QKV_SMEM_FLOATS (64*APAD + 128*BPAD + 128 + 128 + 512)
__global__ __launch_bounds__(256, 2) void gemm_qkv_gate(
    const float* __restrict__ z, const float* __restrict__ lng, const float* __restrict__ lnb,
    const float* __restrict__ bgate, const float* __restrict__ wpair)
{
    extern __shared__ float sm[];
    float* As  = sm;
    float* Bs  = sm + 64*APAD;
    float* gS  = Bs + 128*BPAD;
    float* bS  = gS + 128;
    float* wpS = bS + 128;

    int tid = threadIdx.x;
    int m0 = blockIdx.x * 64;

    #pragma unroll
    for (int it = 0; it < 8; it++) {
        int lin = tid + it*256;
        int r = lin >> 5, c4 = lin & 31;
        cp_async16(As + r*APAD + c4*4, z + (size_t)(m0 + r)*CDIM + c4*4);
    }
    #pragma unroll
    for (int it = 0; it < 16; it++) {
        int lin = tid + it*256;
        int k = lin >> 5, c4 = lin & 31;
        cp_async16(Bs + k*BPAD + c4*4, g_wtf + k*128 + c4*4);
    }
    cp_commit();
    if (tid < 128) { gS[tid] = lng[tid]; bS[tid] = lnb[tid]; }
    wpS[tid] = wpair[tid];
    wpS[tid + 256] = wpair[tid + 256];
    cp_wait<0>();
    __syncthreads();

    {
        int row = tid >> 2, quad = tid & 3;
        float* Ar = As + row*APAD + quad*4;
        float v[32];
        float s = 0.f, ss = 0.f;
        #pragma unroll
        for (int k = 0; k < 8; k++) {
            float4 t = *(float4*)(Ar + k*16);
            v[k*4] = t.x; v[k*4+1] = t.y; v[k*4+2] = t.z; v[k*4+3] = t.w;
            s  += t.x + t.y + t.z + t.w;
            ss += t.x*t.x + t.y*t.y + t.z*t.z + t.w*t.w;
        }
        s  += __shfl_xor_sync(0xffffffffu, s, 1);  s  += __shfl_xor_sync(0xffffffffu, s, 2);
        ss += __shfl_xor_sync(0xffffffffu, ss, 1); ss += __shfl_xor_sync(0xffffffffu, ss, 2);
        float mu  = s * (1.0f / CDIM);
        float var = ss * (1.0f / CDIM) - mu * mu;
        float rstd = rsqrtf(var + 1e-5f);

        float bh0 = 0.f, bh1 = 0.f, bh2 = 0.f, bh3 = 0.f;
        #pragma unroll
        for (int k = 0; k < 8; k++) {
            float4 o;
            float* ov = &o.x;
            #pragma unroll
            for (int j = 0; j < 4; j++) {
                int c = quad*4 + k*16 + j;
                float zn = (v[k*4+j] - mu) * rstd * gS[c] + bS[c];
                bh0 += zn * wpS[c*4];   bh1 += zn * wpS[c*4+1];
                bh2 += zn * wpS[c*4+2]; bh3 += zn * wpS[c*4+3];
                ov[j] = f2tff(zn);
            }
            *(float4*)(Ar + k*16) = o;
        }
        bh0 += __shfl_xor_sync(0xffffffffu, bh0, 1); bh0 += __shfl_xor_sync(0xffffffffu, bh0, 2);
        bh1 += __shfl_xor_sync(0xffffffffu, bh1, 1); bh1 += __shfl_xor_sync(0xffffffffu, bh1, 2);
        bh2 += __shfl_xor_sync(0xffffffffu, bh2, 1); bh2 += __shfl_xor_sync(0xffffffffu, bh2, 2);
        bh3 += __shfl_xor_sync(0xffffffffu, bh3, 1); bh3 += __shfl_xor_sync(0xffffffffu, bh3, 2);
        if (quad == 0) {
            g_biasT[(size_t)0*NROWS + m0 + row] = bh0;
            g_biasT[(size_t)1*NROWS + m0 + row] = bh1;
            g_biasT[(size_t)2*NROWS + m0 + row] = bh2;
            g_biasT[(size_t)3*NROWS + m0 + row] = bh3;
        }
    }
    __syncthreads();

    int warp = tid >> 5, lane = tid & 31;
    int lr = lane >> 2, lc = lane & 3;
    int wm = warp & 1, wn = warp >> 1;

    #pragma unroll
    for (int nt = 0; nt < 4; nt++) {
        float acc[2][4][4];
        #pragma unroll
        for (int mi = 0; mi < 2; mi++)
            #pragma unroll
            for (int ni = 0; ni < 4; ni++)
                acc[mi][ni][0] = acc[mi][ni][1] = acc[mi][ni][2] = acc[mi][ni][3] = 0.f;

        #pragma unroll
        for (int ks = 0; ks < 16; ks++) {
            int k0 = ks * 8;
            unsigned a[2][4], bf[4][2];
            #pragma unroll
            for (int mi = 0; mi < 2; mi++) {
                int r = wm*32 + mi*16 + lr;
                a[mi][0] = fu(As[r*APAD + k0 + lc]);
                a[mi][1] = fu(As[(r+8)*APAD + k0 + lc]);
                a[mi][2] = fu(As[r*APAD + k0 + 4 + lc]);
                a[mi][3] = fu(As[(r+8)*APAD + k0 + 4 + lc]);
            }
            #pragma unroll
            for (int ni = 0; ni < 4; ni++) {
                int n = wn*32 + ni*8 + lr;
                bf[ni][0] = fu(Bs[(k0 + lc)*BPAD + n]);
                bf[ni][1] = fu(Bs[(k0 + 4 + lc)*BPAD + n]);
            }
            #pragma unroll
            for (int mi = 0; mi < 2; mi++)
                #pragma unroll
                for (int ni = 0; ni < 4; ni++)
                    mma_tf32(acc[mi][ni], a[mi], bf[ni]);
        }

        #pragma unroll
        for (int mi = 0; mi < 2; mi++) {
            #pragma unroll
            for (int ni = 0; ni < 4; ni++) {
                int gr = m0 + wm*32 + mi*16 + lr;
                int cn = wn*32 + ni*8 + lc*2;
                if (nt < 3) {
                    int gc = nt*128 + cn;
                    *(float2*)(g_qkv + (size_t)gr * QKVN + gc) =
                        make_float2(f2tff(acc[mi][ni][0]), f2tff(acc[mi][ni][1]));
                    *(float2*)(g_qkv + (size_t)(gr+8) * QKVN + gc) =
                        make_float2(f2tff(acc[mi][ni][2]), f2tff(acc[mi][ni][3]));
                } else {
                    float b0 = bgate[cn], b1 = bgate[cn+1];
                    *(float2*)(g_gate + (size_t)gr * CDIM + cn) =
                        make_float2(1.f/(1.f + __expf(-(acc[mi][ni][0] + b0))),
                                    1.f/(1.f + __expf(-(acc[mi][ni][1] + b1))));
                    *(float2*)(g_gate + (size_t)(gr+8) * CDIM + cn) =
                        make_float2(1.f/(1.f + __expf(-(acc[mi][ni][2] + b0))),
                                    1.f/(1.f + __expf(-(acc[mi][ni][3] + b1))));
                }
            }
        }

        if (nt < 3) {
            __syncthreads();
            #pragma unroll
            for (int it = 0; it < 16; it++) {
                int lin = tid + it*256;
                int k = lin >> 5, c4 = lin & 31;
                cp_async16(Bs + k*BPAD + c4*4, g_wtf + (nt+1)*16384 + k*128 + c4*4);
            }
            cp_commit();
            cp_wait<0>();
            __syncthreads();
        }
    }
}

// ============ kernel 2: attention — deferred softmax division, 2 syncs/chunk ============
// 8 warps: wm = warp&1 (32-row strip), wn = warp>>1 (j quarter of 64).
#define ATTN_SMEM_FLOATS (256*36*2 + 2*64*36 + 256 + 2*64*36 + 256)
__global__ __launch_bounds__(256, 2) void attn_kernel(const int* __restrict__ src_mask)
{
    extern __shared__ float sm[];
    float* Ks     = sm;                 // [256][36]
    float* Vs     = Ks + 256*36;        // [256][36]
    float* Qs0    = Vs + 256*36;        // [64][36]
    float* Qs1    = Qs0 + 64*36;        // [64][36]
    float* redsum = Qs1 + 64*36;        // [4][64]
    float* obuf0  = redsum + 256;       // [64][36]
    float* obuf1  = obuf0 + 64*36;      // [64][36]
    float* msk    = obuf1 + 64*36;      // [256]

    int h = blockIdx.x, r = blockIdx.y;
    int tid = threadIdx.x;
    const float* base = g_qkv + (size_t)r * LDIM * QKVN;

    #pragma unroll
    for (int p = 0; p < 8; p++) {
        int lin = tid + p*256;
        int j = lin >> 3, d4 = lin & 7;
        cp_async16(Ks + j*36 + d4*4, base + (size_t)j*QKVN + 128 + h*HDIM + d4*4);
        cp_async16(Vs + j*36 + d4*4, base + (size_t)j*QKVN + 256 + h*HDIM + d4*4);
    }
    #pragma unroll
    for (int p = 0; p < 2; p++) {
        int lin = tid + p*256;
        int row = lin >> 3, d4 = lin & 7;
        cp_async16(Qs0 + row*36 + d4*4, base + (size_t)row*QKVN + h*HDIM + d4*4);
    }
    cp_commit();
    msk[tid] = (src_mask[tid] == 0) ? -1.f : 1.f;

    int warp = tid >> 5, lane = tid & 31;
    int lr = lane >> 2, lc = lane & 3;
    int wm = warp & 1, wn = warp >> 1;
    const float* biasH = g_biasT + (size_t)h * NROWS;

    int s0l = (lane & ~3) | (lc >> 1);
    int s1l = s0l + 2;
    int sel = lc & 1;

    for (int ic = 0; ic < 4; ic++) {
        int i0 = ic * 64;
        float* Qs = (ic & 1) ? Qs1 : Qs0;
        if (ic < 3) {
            float* Qn = (ic & 1) ? Qs0 : Qs1;
            #pragma unroll
            for (int p = 0; p < 2; p++) {
                int lin = tid + p*256;
                int row = lin >> 3, d4 = lin & 7;
                cp_async16(Qn + row*36 + d4*4,
                           base + (size_t)(i0 + 64 + row)*QKVN + h*HDIM + d4*4);
            }
            cp_commit();
            cp_wait<1>();
        } else {
            cp_wait<0>();
        }
        __syncthreads();

        // ---- QK^T ----
        float acc[2][8][4];
        #pragma unroll
        for (int mi = 0; mi < 2; mi++)
            #pragma unroll
            for (int ni = 0; ni < 8; ni++)
                acc[mi][ni][0] = acc[mi][ni][1] = acc[mi][ni][2] = acc[mi][ni][3] = 0.f;

        #pragma unroll
        for (int ks = 0; ks < 4; ks++) {
            int k0 = ks * 8;
            unsigned a[2][4];
            #pragma unroll
            for (int mi = 0; mi < 2; mi++) {
                int rrow = wm*32 + mi*16 + lr;
                a[mi][0] = fu(Qs[rrow*36 + k0 + lc]);
                a[mi][1] = fu(Qs[(rrow+8)*36 + k0 + lc]);
                a[mi][2] = fu(Qs[rrow*36 + k0 + 4 + lc]);
                a[mi][3] = fu(Qs[(rrow+8)*36 + k0 + 4 + lc]);
            }
            #pragma unroll
            for (int ni = 0; ni < 8; ni++) {
                int j = wn*64 + ni*8 + lr;
                unsigned b[2] = { fu(Ks[j*36 + k0 + lc]), fu(Ks[j*36 + k0 + 4 + lc]) };
                mma_tf32(acc[0][ni], a[0], b);
                mma_tf32(acc[1][ni], a[1], b);
            }
        }

        // ---- bias + mask + exp (CVT fused) + local sums ----
        float smv[2][2] = {{0.f,0.f},{0.f,0.f}};
        #pragma unroll
        for (int mi = 0; mi < 2; mi++) {
            int rl = wm*32 + mi*16 + lr;
            float mi0 = msk[i0 + rl], mi1 = msk[i0 + rl + 8];
            const float* bp0 = biasH + (size_t)(i0 + rl) * LDIM;
            const float* bp1 = bp0 + 8 * LDIM;
            #pragma unroll
            for (int ni = 0; ni < 8; ni++) {
                int j = wn*64 + ni*8 + lc*2;
                float2 b0 = *(const float2*)(bp0 + j);
                float2 b1 = *(const float2*)(bp1 + j);
                float mj0 = msk[j], mj1 = msk[j+1];
                float v0 = acc[mi][ni][0] + b0.x;
                float v1 = acc[mi][ni][1] + b0.y;
                float v2 = acc[mi][ni][2] + b1.x;
                float v3 = acc[mi][ni][3] + b1.y;
                if (mi0*mj0 < 0.f) v0 = -1e-9f;
                if (mi0*mj1 < 0.f) v1 = -1e-9f;
                if (mi1*mj0 < 0.f) v2 = -1e-9f;
                if (mi1*mj1 < 0.f) v3 = -1e-9f;
                float e0 = __expf(v0), e1 = __expf(v1);
                float e2 = __expf(v2), e3 = __expf(v3);
                acc[mi][ni][0] = f2tff(e0); acc[mi][ni][1] = f2tff(e1);
                acc[mi][ni][2] = f2tff(e2); acc[mi][ni][3] = f2tff(e3);
                smv[mi][0] += e0 + e1; smv[mi][1] += e2 + e3;
            }
        }
        #pragma unroll
        for (int mi = 0; mi < 2; mi++) {
            smv[mi][0] += __shfl_xor_sync(0xffffffffu, smv[mi][0], 1);
            smv[mi][0] += __shfl_xor_sync(0xffffffffu, smv[mi][0], 2);
            smv[mi][1] += __shfl_xor_sync(0xffffffffu, smv[mi][1], 1);
            smv[mi][1] += __shfl_xor_sync(0xffffffffu, smv[mi][1], 2);
        }
        if (lc == 0) {
            #pragma unroll
            for (int mi = 0; mi < 2; mi++) {
                int rl = wm*32 + mi*16 + lr;
                redsum[wn*64 + rl]     = smv[mi][0];
                redsum[wn*64 + rl + 8] = smv[mi][1];
            }
        }
        // no sync here: redsum consumed by wn0 only after the combine sync below

        // ---- P @ V with UNSCALED exp values ----
        float oc[2][4][4];
        #pragma unroll
        for (int mi = 0; mi < 2; mi++)
            #pragma unroll
            for (int dt = 0; dt < 4; dt++)
                oc[mi][dt][0] = oc[mi][dt][1] = oc[mi][dt][2] = oc[mi][dt][3] = 0.f;

        #pragma unroll
        for (int ni = 0; ni < 8; ni++) {
            unsigned aP[2][4];
            #pragma unroll
            for (int mi = 0; mi < 2; mi++) {
                float t00 = __shfl_sync(0xffffffffu, acc[mi][ni][0], s0l);
                float t01 = __shfl_sync(0xffffffffu, acc[mi][ni][1], s0l);
                float t10 = __shfl_sync(0xffffffffu, acc[mi][ni][2], s0l);
                float t11 = __shfl_sync(0xffffffffu, acc[mi][ni][3], s0l);
                float u00 = __shfl_sync(0xffffffffu, acc[mi][ni][0], s1l);
                float u01 = __shfl_sync(0xffffffffu, acc[mi][ni][1], s1l);
                float u10 = __shfl_sync(0xffffffffu, acc[mi][ni][2], s1l);
                float u11 = __shfl_sync(0xffffffffu, acc[mi][ni][3], s1l);
                aP[mi][0] = fu(sel ? t01 : t00);
                aP[mi][1] = fu(sel ? t11 : t10);
                aP[mi][2] = fu(sel ? u01 : u00);
                aP[mi][3] = fu(sel ? u11 : u10);
            }
            int jb = wn*64 + ni*8;
            #pragma unroll
            for (int dt = 0; dt < 4; dt++) {
                unsigned b[2] = { fu(Vs[(jb + lc)*36 + dt*8 + lr]),
                                  fu(Vs[(jb + 4 + lc)*36 + dt*8 + lr]) };
                mma_tf32(oc[0][dt], aP[0], b);
                mma_tf32(oc[1][dt], aP[1], b);
            }
        }

        // ---- combine (2 stages) ----
        if (wn == 1 || wn == 3) {
            float* ob = (wn == 1) ? obuf0 : obuf1;
            #pragma unroll
            for (int mi = 0; mi < 2; mi++) {
                int rl = wm*32 + mi*16 + lr;
                #pragma unroll
                for (int dt = 0; dt < 4; dt++) {
                    *(float2*)(ob + rl*36 + dt*8 + lc*2)     = make_float2(oc[mi][dt][0], oc[mi][dt][1]);
                    *(float2*)(ob + (rl+8)*36 + dt*8 + lc*2) = make_float2(oc[mi][dt][2], oc[mi][dt][3]);
                }
            }
        }
        __syncthreads();   // covers obuf writes AND redsum writes
        if (wn == 0 || wn == 2) {
            float* ob = (wn == 0) ? obuf0 : obuf1;
            #pragma unroll
            for (int mi = 0; mi < 2; mi++) {
                int rl = wm*32 + mi*16 + lr;
                #pragma unroll
                for (int dt = 0; dt < 4; dt++) {
                    float2 p0 = *(float2*)(ob + rl*36 + dt*8 + lc*2);
                    float2 p1 = *(float2*)(ob + (rl+8)*36 + dt*8 + lc*2);
                    oc[mi][dt][0] += p0.x; oc[mi][dt][1] += p0.y;
                    oc[mi][dt][2] += p1.x; oc[mi][dt][3] += p1.y;
                }
            }
        }
        if (wn == 2) {
            #pragma unroll
            for (int mi = 0; mi < 2; mi++) {
                int rl = wm*32 + mi*16 + lr;
                #pragma unroll
                for (int dt = 0; dt < 4; dt++) {
                    *(float2*)(obuf1 + rl*36 + dt*8 + lc*2)     = make_float2(oc[mi][dt][0], oc[mi][dt][1]);
                    *(float2*)(obuf1 + (rl+8)*36 + dt*8 + lc*2) = make_float2(oc[mi][dt][2], oc[mi][dt][3]);
                }
            }
        }
        __syncthreads();
        if (wn == 0) {
            #pragma unroll
            for (int mi = 0; mi < 2; mi++) {
                int rl = wm*32 + mi*16 + lr;
                float inv0 = 1.f / (redsum[rl] + redsum[64 + rl] + redsum[128 + rl] + redsum[192 + rl]);
                float inv1 = 1.f / (redsum[rl+8] + redsum[64 + rl+8] + redsum[128 + rl+8] + redsum[192 + rl+8]);
                size_t ro0 = ((size_t)r*LDIM + i0 + rl) * CDIM + h*HDIM;
                size_t ro1 = ro0 + 8*CDIM;
                #pragma unroll
                for (int dt = 0; dt < 4; dt++) {
                    float2 p0 = *(float2*)(obuf1 + rl*36 + dt*8 + lc*2);
                    float2 p1 = *(float2*)(obuf1 + (rl+8)*36 + dt*8 + lc*2);
                    *(float2*)(g_attn + ro0 + dt*8 + lc*2) =
                        make_float2((oc[mi][dt][0] + p0.x) * inv0, (oc[mi][dt][1] + p0.y) * inv0);
                    *(float2*)(g_attn + ro1 + dt*8 + lc*2) =
                        make_float2((oc[mi][dt][2] + p1.x) * inv1, (oc[mi][dt][3] + p1.y) * inv1);
                }
            }
        }
    }
}

// ============ kernel 3: (gate * attn) @ w_out + b_out (validated, unchanged) ============
#define GEMM_OUT_SMEM_FLOATS (64*APAD + 128*BPAD)
__global__ __launch_bounds__(256, 2) void gemm_out_kernel(
    const float* __restrict__ bout, float* __restrict__ out)
{
    extern __shared__ float sm[];
    float* As = sm;
    float* Bs = sm + 64*APAD;
    int tid = threadIdx.x;
    int m0 = blockIdx.x * 64;

    #pragma unroll
    for (int it = 0; it < 16; it++) {
        int lin = tid + it*256;
        int k = lin >> 5, c4 = lin & 31;
        cp_async16(Bs + k*BPAD + c4*4, g_wouttf + k*128 + c4*4);
    }
    cp_commit();

    #pragma unroll
    for (int it = 0; it < 8; it++) {
        int lin = tid + it*256;
        int r = lin >> 5, c4 = lin & 31;
        float4 gte = *(const float4*)(g_gate + (size_t)(m0 + r)*CDIM + c4*4);
        float4 att = *(const float4*)(g_attn + (size_t)(m0 + r)*CDIM + c4*4);
        float4 a;
        a.x = f2tff(gte.x * att.x); a.y = f2tff(gte.y * att.y);
        a.z = f2tff(gte.z * att.z); a.w = f2tff(gte.w * att.w);
        *(float4*)(As + r*APAD + c4*4) = a;
    }
    cp_wait<0>();
    __syncthreads();

    int warp = tid >> 5, lane = tid & 31;
    int lr = lane >> 2, lc = lane & 3;
    int wm = warp & 1, wn = warp >> 1;

    float acc[2][4][4];
    #pragma unroll
    for (int mi = 0; mi < 2; mi++)
        #pragma unroll
        for (int ni = 0; ni < 4; ni++)
            acc[mi][ni][0] = acc[mi][ni][1] = acc[mi][ni][2] = acc[mi][ni][3] = 0.f;

    #pragma unroll
    for (int ks = 0; ks < 16; ks++) {
        int k0 = ks * 8;
        unsigned a[2][4], bf[4][2];
        #pragma unroll
        for (int mi = 0; mi < 2; mi++) {
            int r = wm*32 + mi*16 + lr;
            a[mi][0] = fu(As[r*APAD + k0 + lc]);
            a[mi][1] = fu(As[(r+8)*APAD + k0 + lc]);
            a[mi][2] = fu(As[r*APAD + k0 + 4 + lc]);
            a[mi][3] = fu(As[(r+8)*APAD + k0 + 4 + lc]);
        }
        #pragma unroll
        for (int ni = 0; ni < 4; ni++) {
            int n = wn*32 + ni*8 + lr;
            bf[ni][0] = fu(Bs[(k0 + lc)*BPAD + n]);
            bf[ni][1] = fu(Bs[(k0 + 4 + lc)*BPAD + n]);
        }
        #pragma unroll
        for (int mi = 0; mi < 2; mi++)
            #pragma unroll
            for (int ni = 0; ni < 4; ni++)
                mma_tf32(acc[mi][ni], a[mi], bf[ni]);
    }

    #pragma unroll
    for (int mi = 0; mi < 2; mi++) {
        #pragma unroll
        for (int ni = 0; ni < 4; ni++) {
            int gr = m0 + wm*32 + mi*16 + lr;
            int cn = wn*32 + ni*8 + lc*2;
            float b0 = bout[cn], b1 = bout[cn+1];
            *(float2*)(out + (size_t)gr * CDIM + cn) =
                make_float2(acc[mi][ni][0] + b0, acc[mi][ni][1] + b1);
            *(float2*)(out + (size_t)(gr+8) * CDIM + cn) =
                make_float2(acc[mi][ni][2] + b0, acc[mi][ni][3] + b1);
        }
    }
}

// ---------------- launch ----------------
extern "C" void kernel_launch(void* const* d_in, const int* in_sizes, int n_in,
                              void* d_out, int out_size)
{
    (void)in_sizes; (void)n_in; (void)out_size;
    const float* z        = (const float*)d_in[0];
    const int*   src_mask = (const int*)  d_in[1];
    const float* ln_g     = (const float*)d_in[2];
    const float* ln_b     = (const float*)d_in[3];
    const float* w_qkv    = (const float*)d_in[4];
    const float* w_pair   = (const float*)d_in[5];
    const float* w_gate   = (const float*)d_in[6];
    const float* b_gate   = (const float*)d_in[7];
    const float* w_out    = (const float*)d_in[8];
    const float* b_out    = (const float*)d_in[9];
    float* out = (float*)d_out;

    const int qkv_smem  = GEMM_QKV_SMEM_FLOATS * 4;
    const int out_smem  = GEMM_OUT_SMEM_FLOATS * 4;
    const int attn_smem = ATTN_SMEM_FLOATS * 4;
    cudaFuncSetAttribute(gemm_qkv_gate,   cudaFuncAttributeMaxDynamicSharedMemorySize, qkv_smem);
    cudaFuncSetAttribute(attn_kernel,     cudaFuncAttributeMaxDynamicSharedMemorySize, attn_smem);
    cudaFuncSetAttribute(gemm_out_kernel, cudaFuncAttributeMaxDynamicSharedMemorySize, out_smem);

    prep_weights<<<80, 256>>>(w_qkv, w_gate, w_out);
    gemm_qkv_gate<<<NROWS/64, 256, qkv_smem>>>(z, ln_g, ln_b, b_gate, w_pair);
    attn_kernel<<<dim3(NH, LDIM), 256, attn_smem>>>(src_mask);
    gemm_out_kernel<<<NROWS/64, 256, out_smem>>>(b_out, out);
}